// round 1
// baseline (speedup 1.0000x reference)
#include <cuda_runtime.h>
#include <cstdint>
#include <cstddef>

#define SEQ 1024
#define BATCH 8
#define TOK (BATCH*SEQ)
#define DMODEL 256
#define DI 512
#define NH 4
#define DHH 128
#define NL 4

// ---------------- scratch (device globals; no allocation allowed) ----------------
__device__ float g_h[TOK*DMODEL];
__device__ float g_hn[TOK*DMODEL];
__device__ float g_up[TOK*1024];
__device__ float g_xc[TOK*DI];
__device__ float g_q[TOK*DI];
__device__ float g_k[TOK*DI];
__device__ float g_v[TOK*DI];
__device__ float g_gates[TOK*8];
__device__ float g_Fc[BATCH*NH*SEQ];
__device__ float g_a[BATCH*NH*SEQ];
__device__ float g_m[BATCH*NH*SEQ];
__device__ float g_att[TOK*DI];
__device__ float g_att2[TOK*DI];

__device__ __forceinline__ float warp_sum(float v){
    #pragma unroll
    for (int o=16;o;o>>=1) v += __shfl_xor_sync(0xffffffffu, v, o);
    return v;
}

// ---------------- embed: h = [x, tf] @ Wp + bp ----------------
__global__ void embed_kernel(const float* __restrict__ x, const float* __restrict__ tf,
                             const float* __restrict__ Wp, const float* __restrict__ bp,
                             float* __restrict__ h){
    int idx = blockIdx.x*blockDim.x + threadIdx.x;       // TOK*256
    int j = idx & 255; int tok = idx >> 8;
    float acc = bp[j] + x[tok]*Wp[j];
    #pragma unroll
    for (int f=0; f<4; f++) acc += tf[tok*4+f]*Wp[(1+f)*256+j];
    h[idx] = acc;
}

// ---------------- layernorm over D=256, warp per row ----------------
__global__ void ln_kernel(const float* __restrict__ x, const float* __restrict__ g,
                          const float* __restrict__ b, float* __restrict__ y){
    int row = blockIdx.x*8 + (threadIdx.x>>5);
    int lane = threadIdx.x & 31;
    const float* xr = x + (size_t)row*256;
    float4 v0 = *(const float4*)(xr + lane*4);
    float4 v1 = *(const float4*)(xr + 128 + lane*4);
    float s = v0.x+v0.y+v0.z+v0.w + v1.x+v1.y+v1.z+v1.w;
    s = warp_sum(s);
    float mu = s * (1.f/256.f);
    float d0x=v0.x-mu, d0y=v0.y-mu, d0z=v0.z-mu, d0w=v0.w-mu;
    float d1x=v1.x-mu, d1y=v1.y-mu, d1z=v1.z-mu, d1w=v1.w-mu;
    float sq = d0x*d0x+d0y*d0y+d0z*d0z+d0w*d0w + d1x*d1x+d1y*d1y+d1z*d1z+d1w*d1w;
    sq = warp_sum(sq);
    float is = rsqrtf(sq*(1.f/256.f) + 1e-5f);
    float4 g0 = *(const float4*)(g + lane*4);
    float4 g1 = *(const float4*)(g + 128 + lane*4);
    float4 b0 = *(const float4*)(b + lane*4);
    float4 b1 = *(const float4*)(b + 128 + lane*4);
    float* yr = y + (size_t)row*256;
    float4 o0, o1;
    o0.x = d0x*is*g0.x + b0.x; o0.y = d0y*is*g0.y + b0.y;
    o0.z = d0z*is*g0.z + b0.z; o0.w = d0w*is*g0.w + b0.w;
    o1.x = d1x*is*g1.x + b1.x; o1.y = d1y*is*g1.y + b1.y;
    o1.z = d1z*is*g1.z + b1.z; o1.w = d1w*is*g1.w + b1.w;
    *(float4*)(yr + lane*4) = o0;
    *(float4*)(yr + 128 + lane*4) = o1;
}

// ---------------- SGEMM 64x64 tile, 4x4/thread, fp32 ----------------
// C[M,N] = A[M,K](lda) @ B[K,N](ldb) + bias + resid ; M,N mult of 64, K mult of 16
__global__ __launch_bounds__(256) void sgemm64(
    const float* __restrict__ A, int lda,
    const float* __restrict__ B, int ldb,
    float* __restrict__ C, int ldc,
    const float* __restrict__ bias,
    const float* __restrict__ resid,
    int K)
{
    __shared__ float As[16*64];
    __shared__ float Bs[16*64];
    int tid = threadIdx.x;
    int tx = tid & 15, ty = tid >> 4;
    int m0 = blockIdx.y*64, n0 = blockIdx.x*64;
    float acc[4][4] = {};

    const float* Ab = A + (size_t)(m0 + (tid>>2))*lda + ((tid&3)<<2);
    const float* Bb = B + (size_t)(tid>>4)*ldb + n0 + ((tid&15)<<2);
    int arow = tid>>2, ak = (tid&3)<<2;
    int bk = tid>>4, bn = (tid&15)<<2;

    for (int k0=0; k0<K; k0+=16){
        float4 av = *(const float4*)(Ab + k0);
        As[(ak+0)*64 + arow] = av.x;
        As[(ak+1)*64 + arow] = av.y;
        As[(ak+2)*64 + arow] = av.z;
        As[(ak+3)*64 + arow] = av.w;
        *(float4*)&Bs[bk*64 + bn] = *(const float4*)(Bb + (size_t)k0*ldb);
        __syncthreads();
        #pragma unroll
        for (int k=0; k<16; k++){
            float4 a = *(float4*)&As[k*64 + (ty<<2)];
            float4 b = *(float4*)&Bs[k*64 + (tx<<2)];
            acc[0][0]+=a.x*b.x; acc[0][1]+=a.x*b.y; acc[0][2]+=a.x*b.z; acc[0][3]+=a.x*b.w;
            acc[1][0]+=a.y*b.x; acc[1][1]+=a.y*b.y; acc[1][2]+=a.y*b.z; acc[1][3]+=a.y*b.w;
            acc[2][0]+=a.z*b.x; acc[2][1]+=a.z*b.y; acc[2][2]+=a.z*b.z; acc[2][3]+=a.z*b.w;
            acc[3][0]+=a.w*b.x; acc[3][1]+=a.w*b.y; acc[3][2]+=a.w*b.z; acc[3][3]+=a.w*b.w;
        }
        __syncthreads();
    }
    float4 bs = bias ? *(const float4*)&bias[n0 + (tx<<2)] : make_float4(0.f,0.f,0.f,0.f);
    #pragma unroll
    for (int i=0;i<4;i++){
        int mrow = m0 + (ty<<2) + i;
        float4 r = make_float4(0.f,0.f,0.f,0.f);
        if (resid) r = *(const float4*)&resid[(size_t)mrow*ldc + n0 + (tx<<2)];
        float4 o;
        o.x = acc[i][0] + bs.x + r.x;
        o.y = acc[i][1] + bs.y + r.y;
        o.z = acc[i][2] + bs.z + r.z;
        o.w = acc[i][3] + bs.w + r.w;
        *(float4*)&C[(size_t)mrow*ldc + n0 + (tx<<2)] = o;
    }
}

// ---------------- causal depthwise conv (K=4) + silu ----------------
__global__ void conv_silu_kernel(const float* __restrict__ up, const float* __restrict__ w,
                                 const float* __restrict__ cb, float* __restrict__ xc){
    int idx = blockIdx.x*blockDim.x + threadIdx.x;    // TOK*512
    int c = idx & 511; int tok = idx >> 9; int t = tok & 1023;
    float acc = cb[c];
    #pragma unroll
    for (int j=0;j<4;j++){
        int ts = t - 3 + j;
        if (ts >= 0) acc += w[j*512+c] * up[(size_t)(tok-3+j)*1024 + c];
    }
    float sv = acc / (1.f + expf(-acc));
    xc[(size_t)tok*512 + c] = sv;
}

// ---------------- gates = [q,k,v] @ Wif + bif (N=8) ----------------
__global__ void gates_kernel(const float* __restrict__ q, const float* __restrict__ k,
                             const float* __restrict__ v, const float* __restrict__ Wif,
                             const float* __restrict__ bif, float* __restrict__ gates){
    __shared__ float gi[1536];
    int tok = blockIdx.x, tid = threadIdx.x;
    for (int i=tid;i<512;i+=256){
        gi[i]      = q[(size_t)tok*512+i];
        gi[512+i]  = k[(size_t)tok*512+i];
        gi[1024+i] = v[(size_t)tok*512+i];
    }
    __syncthreads();
    int w = tid>>5, lane = tid&31;
    float acc = 0.f;
    for (int i=lane;i<1536;i+=32) acc += gi[i]*Wif[i*8+w];
    acc = warp_sum(acc);
    if (!lane) gates[tok*8+w] = acc + bif[w];
}

// ---------------- gate scan: Fc, a, m per (b,h) ----------------
__global__ void scan_kernel(const float* __restrict__ gates, float* __restrict__ Fc,
                            float* __restrict__ a, float* __restrict__ m){
    int bh = threadIdx.x;
    if (bh >= 32) return;
    int b = bh>>2, h = bh&3;
    float fc = 0.f, amax = -1e30f;
    for (int s=0;s<SEQ;s++){
        const float* g = gates + ((size_t)(b*SEQ + s))*8;
        float ip = g[h], fp = g[4+h];
        float lf = fminf(fp, 0.f) - log1pf(expf(-fabsf(fp)));
        fc += lf;
        float av = ip - fc;
        amax = fmaxf(amax, av);
        int o = bh*SEQ + s;
        Fc[o] = fc; a[o] = av; m[o] = fc + amax;
    }
}

// ---------------- mLSTM attention, 32x32 tiles, DH=128, no online rescale ----------------
__global__ __launch_bounds__(256) void attn_kernel(
    const float* __restrict__ q, const float* __restrict__ k, const float* __restrict__ v,
    const float* __restrict__ Fcv, const float* __restrict__ av, const float* __restrict__ mv,
    float* __restrict__ out)
{
    extern __shared__ float smem[];
    float* qs  = smem;               // 32*128
    float* ks  = qs  + 32*128;       // 32*132 (padded)
    float* vs  = ks  + 32*132;       // 32*128
    float* Ps  = vs  + 32*128;       // 32*33
    float* fct = Ps  + 32*33;        // 32
    float* mt  = fct + 32;           // 32
    float* as_ = mt  + 32;           // 32
    float* dns = as_ + 32;           // 32

    int bh = blockIdx.x; int b = bh>>2; int hh = bh&3;
    int it = blockIdx.y; int t0 = it<<5;
    int tid = threadIdx.x;
    const float scale = 0.08838834764831845f; // 1/sqrt(128)

    const float* qg = q + ((size_t)(b*SEQ + t0))*512 + hh*128;
    #pragma unroll
    for (int r=0;r<4;r++){
        int idx = tid + (r<<8); int row = idx>>5; int c4 = (idx&31)<<2;
        *(float4*)&qs[row*128+c4] = *(const float4*)(qg + (size_t)row*512 + c4);
    }
    if (tid < 32){ int tg = bh*SEQ + t0 + tid; fct[tid]=Fcv[tg]; mt[tid]=mv[tg]; }

    int sq = tid & 31; int tb = (tid>>5)<<2;     // qk role
    int tp = tid >> 3; int dg = tid & 7;         // pv role
    float4 acc0=make_float4(0,0,0,0), acc1=acc0, acc2=acc0, acc3=acc0;
    float den = 0.f;

    for (int js=0; js<=it; js++){
        int s0 = js<<5;
        __syncthreads();
        const float* kg = k + ((size_t)(b*SEQ + s0))*512 + hh*128;
        const float* vg = v + ((size_t)(b*SEQ + s0))*512 + hh*128;
        #pragma unroll
        for (int r=0;r<4;r++){
            int idx = tid + (r<<8); int row = idx>>5; int c4 = (idx&31)<<2;
            *(float4*)&ks[row*132+c4] = *(const float4*)(kg + (size_t)row*512 + c4);
            *(float4*)&vs[row*128+c4] = *(const float4*)(vg + (size_t)row*512 + c4);
        }
        if (tid < 32) as_[tid] = av[bh*SEQ + s0 + tid];
        __syncthreads();

        // qk: thread -> (t = tb..tb+3, s = sq)
        float a0=0,a1=0,a2=0,a3=0;
        const float* kr = &ks[sq*132];
        #pragma unroll
        for (int d4=0; d4<128; d4+=4){
            float4 kv = *(const float4*)(kr+d4);
            float4 q0 = *(const float4*)&qs[(tb+0)*128+d4];
            float4 q1 = *(const float4*)&qs[(tb+1)*128+d4];
            float4 q2 = *(const float4*)&qs[(tb+2)*128+d4];
            float4 q3 = *(const float4*)&qs[(tb+3)*128+d4];
            a0 += q0.x*kv.x + q0.y*kv.y + q0.z*kv.z + q0.w*kv.w;
            a1 += q1.x*kv.x + q1.y*kv.y + q1.z*kv.z + q1.w*kv.w;
            a2 += q2.x*kv.x + q2.y*kv.y + q2.z*kv.z + q2.w*kv.w;
            a3 += q3.x*kv.x + q3.y*kv.y + q3.z*kv.z + q3.w*kv.w;
        }
        int sg = s0 + sq;
        {
            float aa[4] = {a0,a1,a2,a3};
            #pragma unroll
            for (int j=0;j<4;j++){
                int t = tb+j; int tg = t0 + t;
                float val = (sg <= tg) ? aa[j]*scale*__expf(fct[t] + as_[sq] - mt[t]) : 0.f;
                Ps[t*33+sq] = val;
            }
        }
        __syncthreads();

        // pv: thread -> (t = tp, d = dg*4 + 32j)
        #pragma unroll 4
        for (int s=0;s<32;s++){
            float p = Ps[tp*33+s];
            if (dg==0) den += p;
            const float* vr = &vs[s*128];
            float4 v0 = *(const float4*)(vr + (dg<<2));
            float4 v1 = *(const float4*)(vr + (dg<<2) + 32);
            float4 v2 = *(const float4*)(vr + (dg<<2) + 64);
            float4 v3 = *(const float4*)(vr + (dg<<2) + 96);
            acc0.x+=p*v0.x; acc0.y+=p*v0.y; acc0.z+=p*v0.z; acc0.w+=p*v0.w;
            acc1.x+=p*v1.x; acc1.y+=p*v1.y; acc1.z+=p*v1.z; acc1.w+=p*v1.w;
            acc2.x+=p*v2.x; acc2.y+=p*v2.y; acc2.z+=p*v2.z; acc2.w+=p*v2.w;
            acc3.x+=p*v3.x; acc3.y+=p*v3.y; acc3.z+=p*v3.z; acc3.w+=p*v3.w;
        }
    }
    __syncthreads();
    if (dg==0) dns[tp] = den;
    __syncthreads();
    float dd = dns[tp];
    float nrm = fmaxf(fabsf(dd), __expf(-mt[tp])) + 1e-6f;
    float inv = 1.f / nrm;
    float* og = out + ((size_t)(b*SEQ + t0 + tp))*512 + hh*128 + (dg<<2);
    float4 o0 = make_float4(acc0.x*inv, acc0.y*inv, acc0.z*inv, acc0.w*inv);
    float4 o1 = make_float4(acc1.x*inv, acc1.y*inv, acc1.z*inv, acc1.w*inv);
    float4 o2 = make_float4(acc2.x*inv, acc2.y*inv, acc2.z*inv, acc2.w*inv);
    float4 o3 = make_float4(acc3.x*inv, acc3.y*inv, acc3.z*inv, acc3.w*inv);
    *(float4*)(og)      = o0;
    *(float4*)(og + 32) = o1;
    *(float4*)(og + 64) = o2;
    *(float4*)(og + 96) = o3;
}

// ---------------- groupnorm per (b,s,h) + skip*xc + silu(z) gating ----------------
__global__ void gn_fuse_kernel(const float* __restrict__ att, const float* __restrict__ up,
                               const float* __restrict__ xc, const float* __restrict__ gng,
                               const float* __restrict__ gnb, const float* __restrict__ skip,
                               float* __restrict__ out){
    __shared__ float sh[4];
    __shared__ float s_mu, s_var;
    int tid = threadIdx.x;                 // 128
    int bsh = blockIdx.x; int hh = bsh & 3; int tok = bsh >> 2;
    int c = hh*128 + tid;
    float vv = att[(size_t)tok*512 + c];
    float s = warp_sum(vv);
    if ((tid&31)==0) sh[tid>>5] = s;
    __syncthreads();
    if (tid==0) s_mu = (sh[0]+sh[1]+sh[2]+sh[3])*(1.f/128.f);
    __syncthreads();
    float mu = s_mu;
    float d = vv - mu;
    float s2 = warp_sum(d*d);
    if ((tid&31)==0) sh[tid>>5] = s2;
    __syncthreads();
    if (tid==0) s_var = (sh[0]+sh[1]+sh[2]+sh[3])*(1.f/128.f);
    __syncthreads();
    float yn = d*rsqrtf(s_var + 1e-5f)*gng[c] + gnb[c];
    float val = yn + skip[c]*xc[(size_t)tok*512 + c];
    float z = up[(size_t)tok*1024 + 512 + c];
    val *= z / (1.f + expf(-z));
    out[(size_t)tok*512 + c] = val;
}

// ---------------- final: LN(last token) @ Wf + bf ----------------
__global__ void final_kernel(const float* __restrict__ h, const float* __restrict__ g,
                             const float* __restrict__ b, const float* __restrict__ Wf,
                             const float* __restrict__ bf, float* __restrict__ out){
    __shared__ float sh[8];
    __shared__ float sv;
    int bb = blockIdx.x, tid = threadIdx.x;   // 256 threads
    float vv = h[((size_t)(bb*SEQ + SEQ-1))*256 + tid];
    float s = warp_sum(vv);
    if (!(tid&31)) sh[tid>>5] = s;
    __syncthreads();
    if (tid==0){ float t=0; for(int i=0;i<8;i++) t+=sh[i]; sv = t*(1.f/256.f); }
    __syncthreads();
    float mu = sv;
    float d = vv - mu;
    float s2 = warp_sum(d*d);
    if (!(tid&31)) sh[tid>>5] = s2;
    __syncthreads();
    if (tid==0){ float t=0; for(int i=0;i<8;i++) t+=sh[i]; sv = t*(1.f/256.f); }
    __syncthreads();
    float yn = d*rsqrtf(sv + 1e-5f)*g[tid] + b[tid];
    float p = yn * Wf[tid];
    float s3 = warp_sum(p);
    __syncthreads();
    if (!(tid&31)) sh[tid>>5] = s3;
    __syncthreads();
    if (tid==0){ float t=0; for(int i=0;i<8;i++) t+=sh[i]; out[bb] = t + bf[0]; }
}

// ---------------- launch ----------------
extern "C" void kernel_launch(void* const* d_in, const int* in_sizes, int n_in,
                              void* d_out, int out_size){
    const float* x    = (const float*)d_in[0];
    const float* tf   = (const float*)d_in[1];
    const float* Wp   = (const float*)d_in[2];
    const float* bp   = (const float*)d_in[3];
    const float* ln_g = (const float*)d_in[4];
    const float* ln_b = (const float*)d_in[5];
    const float* Wup  = (const float*)d_in[6];
    const float* bup  = (const float*)d_in[7];
    const float* cw   = (const float*)d_in[8];
    const float* cb   = (const float*)d_in[9];
    const float* Wq   = (const float*)d_in[10];
    const float* Wk   = (const float*)d_in[11];
    const float* Wv   = (const float*)d_in[12];
    const float* Wif  = (const float*)d_in[13];
    const float* bif  = (const float*)d_in[14];
    const float* gng  = (const float*)d_in[15];
    const float* gnb  = (const float*)d_in[16];
    const float* skip = (const float*)d_in[17];
    const float* Wdn  = (const float*)d_in[18];
    const float* bdn  = (const float*)d_in[19];
    const float* lnfg = (const float*)d_in[20];
    const float* lnfb = (const float*)d_in[21];
    const float* Wf   = (const float*)d_in[22];
    const float* bf   = (const float*)d_in[23];

    float *h,*hn,*up,*xc,*q,*k,*v,*gates,*Fc,*a,*m,*att,*att2;
    cudaGetSymbolAddress((void**)&h,    g_h);
    cudaGetSymbolAddress((void**)&hn,   g_hn);
    cudaGetSymbolAddress((void**)&up,   g_up);
    cudaGetSymbolAddress((void**)&xc,   g_xc);
    cudaGetSymbolAddress((void**)&q,    g_q);
    cudaGetSymbolAddress((void**)&k,    g_k);
    cudaGetSymbolAddress((void**)&v,    g_v);
    cudaGetSymbolAddress((void**)&gates,g_gates);
    cudaGetSymbolAddress((void**)&Fc,   g_Fc);
    cudaGetSymbolAddress((void**)&a,    g_a);
    cudaGetSymbolAddress((void**)&m,    g_m);
    cudaGetSymbolAddress((void**)&att,  g_att);
    cudaGetSymbolAddress((void**)&att2, g_att2);

    int attn_smem = (32*128 + 32*132 + 32*128 + 32*33 + 128) * sizeof(float);
    cudaFuncSetAttribute(attn_kernel, cudaFuncAttributeMaxDynamicSharedMemorySize, attn_smem);

    embed_kernel<<<TOK*256/256, 256>>>(x, tf, Wp, bp, h);

    for (int l=0; l<NL; l++){
        ln_kernel<<<TOK/8, 256>>>(h, ln_g + l*256, ln_b + l*256, hn);
        sgemm64<<<dim3(1024/64, TOK/64), 256>>>(hn, 256, Wup + (size_t)l*256*1024, 1024,
                                                up, 1024, bup + l*1024, nullptr, 256);
        conv_silu_kernel<<<TOK*512/256, 256>>>(up, cw + l*4*512, cb + l*512, xc);
        sgemm64<<<dim3(512/64, TOK/64), 256>>>(xc, 512, Wq + (size_t)l*512*512, 512,
                                               q, 512, nullptr, nullptr, 512);
        sgemm64<<<dim3(512/64, TOK/64), 256>>>(xc, 512, Wk + (size_t)l*512*512, 512,
                                               k, 512, nullptr, nullptr, 512);
        sgemm64<<<dim3(512/64, TOK/64), 256>>>(up, 1024, Wv + (size_t)l*512*512, 512,
                                               v, 512, nullptr, nullptr, 512);
        gates_kernel<<<TOK, 256>>>(q, k, v, Wif + (size_t)l*1536*8, bif + l*8, gates);
        scan_kernel<<<1, 32>>>(gates, Fc, a, m);
        attn_kernel<<<dim3(BATCH*NH, SEQ/32), 256, attn_smem>>>(q, k, v, Fc, a, m, att);
        gn_fuse_kernel<<<TOK*NH, 128>>>(att, up, xc, gng + l*512, gnb + l*512, skip + l*512, att2);
        sgemm64<<<dim3(256/64, TOK/64), 256>>>(att2, 512, Wdn + (size_t)l*512*256, 256,
                                               h, 256, bdn + l*256, h, 512);
    }
    final_kernel<<<BATCH, 256>>>(h, lnfg, lnfb, Wf, bf, (float*)d_out);
}

// round 3
// speedup vs baseline: 1.2997x; 1.2997x over previous
#include <cuda_runtime.h>
#include <cstdint>
#include <cstddef>

#define SEQ 1024
#define BATCH 8
#define TOK (BATCH*SEQ)
#define DMODEL 256
#define DI 512
#define NH 4
#define DHH 128
#define NL 4

// ---------------- scratch (device globals; no allocation allowed) ----------------
__device__ float g_h[TOK*DMODEL];
__device__ float g_hn[TOK*DMODEL];
__device__ float g_up[TOK*1024];
__device__ float g_xc[TOK*DI];
__device__ float g_q[TOK*DI];
__device__ float g_k[TOK*DI];
__device__ float g_v[TOK*DI];
__device__ float g_gates[TOK*8];
__device__ float g_Fc[BATCH*NH*SEQ];
__device__ float g_a[BATCH*NH*SEQ];
__device__ float g_m[BATCH*NH*SEQ];
__device__ float g_att[TOK*DI];
__device__ float g_att2[TOK*DI];

__device__ __forceinline__ float warp_sum(float v){
    #pragma unroll
    for (int o=16;o;o>>=1) v += __shfl_xor_sync(0xffffffffu, v, o);
    return v;
}

__device__ __forceinline__ uint32_t f2tf(float x){
    uint32_t r; asm("cvt.rna.tf32.f32 %0, %1;" : "=r"(r) : "f"(x)); return r;
}

// ---------------- embed: h = [x, tf] @ Wp + bp ----------------
__global__ void embed_kernel(const float* __restrict__ x, const float* __restrict__ tf,
                             const float* __restrict__ Wp, const float* __restrict__ bp,
                             float* __restrict__ h){
    int idx = blockIdx.x*blockDim.x + threadIdx.x;       // TOK*256
    int j = idx & 255; int tok = idx >> 8;
    float acc = bp[j] + x[tok]*Wp[j];
    #pragma unroll
    for (int f=0; f<4; f++) acc += tf[tok*4+f]*Wp[(1+f)*256+j];
    h[idx] = acc;
}

// ---------------- layernorm over D=256, warp per row ----------------
__global__ void ln_kernel(const float* __restrict__ x, const float* __restrict__ g,
                          const float* __restrict__ b, float* __restrict__ y){
    int row = blockIdx.x*8 + (threadIdx.x>>5);
    int lane = threadIdx.x & 31;
    const float* xr = x + (size_t)row*256;
    float4 v0 = *(const float4*)(xr + lane*4);
    float4 v1 = *(const float4*)(xr + 128 + lane*4);
    float s = v0.x+v0.y+v0.z+v0.w + v1.x+v1.y+v1.z+v1.w;
    s = warp_sum(s);
    float mu = s * (1.f/256.f);
    float d0x=v0.x-mu, d0y=v0.y-mu, d0z=v0.z-mu, d0w=v0.w-mu;
    float d1x=v1.x-mu, d1y=v1.y-mu, d1z=v1.z-mu, d1w=v1.w-mu;
    float sq = d0x*d0x+d0y*d0y+d0z*d0z+d0w*d0w + d1x*d1x+d1y*d1y+d1z*d1z+d1w*d1w;
    sq = warp_sum(sq);
    float is = rsqrtf(sq*(1.f/256.f) + 1e-5f);
    float4 g0 = *(const float4*)(g + lane*4);
    float4 g1 = *(const float4*)(g + 128 + lane*4);
    float4 b0 = *(const float4*)(b + lane*4);
    float4 b1 = *(const float4*)(b + 128 + lane*4);
    float* yr = y + (size_t)row*256;
    float4 o0, o1;
    o0.x = d0x*is*g0.x + b0.x; o0.y = d0y*is*g0.y + b0.y;
    o0.z = d0z*is*g0.z + b0.z; o0.w = d0w*is*g0.w + b0.w;
    o1.x = d1x*is*g1.x + b1.x; o1.y = d1y*is*g1.y + b1.y;
    o1.z = d1z*is*g1.z + b1.z; o1.w = d1w*is*g1.w + b1.w;
    *(float4*)(yr + lane*4) = o0;
    *(float4*)(yr + 128 + lane*4) = o1;
}

// ---------------- tf32 tensor-core GEMM ----------------
// C[M,N] = A[M,K](lda) @ B[K,N](ldb) + bias + resid
// CTA tile 128x64x32; 8 warps in 4x2; warp tile 32x32 (2x4 mma m16n8k8).
// A smem: [128][32] words, XOR swizzle on 16B chunks -> conflict-free loads+stores.
// B smem: [32][72] words (stride 72 -> 8k+col bank pattern, conflict-free).
__global__ __launch_bounds__(256) void mma_gemm(
    const float* __restrict__ A, int lda,
    const float* __restrict__ B, int ldb,
    float* __restrict__ C, int ldc,
    const float* __restrict__ bias,
    const float* __restrict__ resid,
    int K)
{
    __shared__ uint32_t As[128*32];
    __shared__ uint32_t Bs[32*72];
    int tid = threadIdx.x;
    int lane = tid & 31, wid = tid >> 5;
    int wm = wid >> 1, wn = wid & 1;
    int m0 = blockIdx.y*128, n0 = blockIdx.x*64;

    float c[2][4][4] = {};

    int arow = tid >> 3;            // 0..31 (+32r)
    int ak4  = (tid & 7) << 2;      // 0,4,...,28
    int bn4  = (tid & 15) << 2;
    int bk   = tid >> 4;            // 0..15 (+16)

    for (int k0 = 0; k0 < K; k0 += 32){
        #pragma unroll
        for (int r = 0; r < 4; r++){
            int row = arow + (r<<5);
            float4 v = *(const float4*)(A + (size_t)(m0+row)*lda + k0 + ak4);
            int chunk = (ak4>>2) ^ (row&7);
            *(uint4*)&As[row*32 + (chunk<<2)] =
                make_uint4(f2tf(v.x), f2tf(v.y), f2tf(v.z), f2tf(v.w));
        }
        #pragma unroll
        for (int r = 0; r < 2; r++){
            int kk = bk + (r<<4);
            float4 v = *(const float4*)(B + (size_t)(k0+kk)*ldb + n0 + bn4);
            *(uint4*)&Bs[kk*72 + bn4] =
                make_uint4(f2tf(v.x), f2tf(v.y), f2tf(v.z), f2tf(v.w));
        }
        __syncthreads();
        #pragma unroll
        for (int ks = 0; ks < 4; ks++){
            uint32_t a[2][4], b[4][2];
            #pragma unroll
            for (int mt=0; mt<2; mt++){
                int r0 = wm*32 + mt*16 + (lane>>2);
                int r1 = r0 + 8;
                int j0 = ks*2, j1 = ks*2 + 1;
                a[mt][0] = As[r0*32 + (((j0^(r0&7))<<2)) + (lane&3)];
                a[mt][1] = As[r1*32 + (((j0^(r1&7))<<2)) + (lane&3)];
                a[mt][2] = As[r0*32 + (((j1^(r0&7))<<2)) + (lane&3)];
                a[mt][3] = As[r1*32 + (((j1^(r1&7))<<2)) + (lane&3)];
            }
            int krow = ks*8 + (lane&3);
            #pragma unroll
            for (int nt=0; nt<4; nt++){
                int col = wn*32 + nt*8 + (lane>>2);
                b[nt][0] = Bs[krow*72 + col];
                b[nt][1] = Bs[(krow+4)*72 + col];
            }
            #pragma unroll
            for (int mt=0; mt<2; mt++)
              #pragma unroll
              for (int nt=0; nt<4; nt++)
                asm volatile(
                  "mma.sync.aligned.m16n8k8.row.col.f32.tf32.tf32.f32 "
                  "{%0,%1,%2,%3}, {%4,%5,%6,%7}, {%8,%9}, {%0,%1,%2,%3};\n"
                  : "+f"(c[mt][nt][0]), "+f"(c[mt][nt][1]),
                    "+f"(c[mt][nt][2]), "+f"(c[mt][nt][3])
                  : "r"(a[mt][0]), "r"(a[mt][1]), "r"(a[mt][2]), "r"(a[mt][3]),
                    "r"(b[nt][0]), "r"(b[nt][1]));
        }
        __syncthreads();
    }

    #pragma unroll
    for (int mt=0;mt<2;mt++){
        #pragma unroll
        for (int nt=0;nt<4;nt++){
            int row0 = m0 + wm*32 + mt*16 + (lane>>2);
            int col  = n0 + wn*32 + nt*8 + ((lane&3)<<1);
            float bx=0.f, by=0.f;
            if (bias){ bx = bias[col]; by = bias[col+1]; }
            float2 r0v = make_float2(0.f,0.f), r1v = make_float2(0.f,0.f);
            if (resid){
                r0v = *(const float2*)&resid[(size_t)row0*ldc + col];
                r1v = *(const float2*)&resid[(size_t)(row0+8)*ldc + col];
            }
            *(float2*)&C[(size_t)row0*ldc + col] =
                make_float2(c[mt][nt][0]+bx+r0v.x, c[mt][nt][1]+by+r0v.y);
            *(float2*)&C[(size_t)(row0+8)*ldc + col] =
                make_float2(c[mt][nt][2]+bx+r1v.x, c[mt][nt][3]+by+r1v.y);
        }
    }
}

// ---------------- causal depthwise conv (K=4) + silu ----------------
__global__ void conv_silu_kernel(const float* __restrict__ up, const float* __restrict__ w,
                                 const float* __restrict__ cb, float* __restrict__ xc){
    int idx = blockIdx.x*blockDim.x + threadIdx.x;    // TOK*512
    int c = idx & 511; int tok = idx >> 9; int t = tok & 1023;
    float acc = cb[c];
    #pragma unroll
    for (int j=0;j<4;j++){
        int ts = t - 3 + j;
        if (ts >= 0) acc += w[j*512+c] * up[(size_t)(tok-3+j)*1024 + c];
    }
    float sv = acc / (1.f + expf(-acc));
    xc[(size_t)tok*512 + c] = sv;
}

// ---------------- gates = [q,k,v] @ Wif + bif (N=8) ----------------
__global__ void gates_kernel(const float* __restrict__ q, const float* __restrict__ k,
                             const float* __restrict__ v, const float* __restrict__ Wif,
                             const float* __restrict__ bif, float* __restrict__ gates){
    __shared__ float gi[1536];
    int tok = blockIdx.x, tid = threadIdx.x;
    for (int i=tid;i<512;i+=256){
        gi[i]      = q[(size_t)tok*512+i];
        gi[512+i]  = k[(size_t)tok*512+i];
        gi[1024+i] = v[(size_t)tok*512+i];
    }
    __syncthreads();
    int w = tid>>5, lane = tid&31;
    float acc = 0.f;
    for (int i=lane;i<1536;i+=32) acc += gi[i]*Wif[i*8+w];
    acc = warp_sum(acc);
    if (!lane) gates[tok*8+w] = acc + bif[w];
}

// ---------------- gate scan: Fc, a, m per (b,h) ----------------
__global__ void scan_kernel(const float* __restrict__ gates, float* __restrict__ Fc,
                            float* __restrict__ a, float* __restrict__ m){
    int bh = threadIdx.x;
    if (bh >= 32) return;
    int b = bh>>2, h = bh&3;
    float fc = 0.f, amax = -1e30f;
    for (int s=0;s<SEQ;s++){
        const float* g = gates + ((size_t)(b*SEQ + s))*8;
        float ip = g[h], fp = g[4+h];
        float lf = fminf(fp, 0.f) - log1pf(expf(-fabsf(fp)));
        fc += lf;
        float av = ip - fc;
        amax = fmaxf(amax, av);
        int o = bh*SEQ + s;
        Fc[o] = fc; a[o] = av; m[o] = fc + amax;
    }
}

// ---------------- mLSTM attention, 32x32 tiles, DH=128, no online rescale ----------------
__global__ __launch_bounds__(256) void attn_kernel(
    const float* __restrict__ q, const float* __restrict__ k, const float* __restrict__ v,
    const float* __restrict__ Fcv, const float* __restrict__ av, const float* __restrict__ mv,
    float* __restrict__ out)
{
    extern __shared__ float smem[];
    float* qs  = smem;               // 32*128
    float* ks  = qs  + 32*128;       // 32*132 (padded)
    float* vs  = ks  + 32*132;       // 32*128
    float* Ps  = vs  + 32*128;       // 32*33
    float* fct = Ps  + 32*33;        // 32
    float* mt  = fct + 32;           // 32
    float* as_ = mt  + 32;           // 32
    float* dns = as_ + 32;           // 32

    int bh = blockIdx.x; int b = bh>>2; int hh = bh&3;
    int it = blockIdx.y; int t0 = it<<5;
    int tid = threadIdx.x;
    const float scale = 0.08838834764831845f; // 1/sqrt(128)

    const float* qg = q + ((size_t)(b*SEQ + t0))*512 + hh*128;
    #pragma unroll
    for (int r=0;r<4;r++){
        int idx = tid + (r<<8); int row = idx>>5; int c4 = (idx&31)<<2;
        *(float4*)&qs[row*128+c4] = *(const float4*)(qg + (size_t)row*512 + c4);
    }
    if (tid < 32){ int tg = bh*SEQ + t0 + tid; fct[tid]=Fcv[tg]; mt[tid]=mv[tg]; }

    int sq = tid & 31; int tb = (tid>>5)<<2;     // qk role
    int tp = tid >> 3; int dg = tid & 7;         // pv role
    float4 acc0=make_float4(0,0,0,0), acc1=acc0, acc2=acc0, acc3=acc0;
    float den = 0.f;

    for (int js=0; js<=it; js++){
        int s0 = js<<5;
        __syncthreads();
        const float* kg = k + ((size_t)(b*SEQ + s0))*512 + hh*128;
        const float* vg = v + ((size_t)(b*SEQ + s0))*512 + hh*128;
        #pragma unroll
        for (int r=0;r<4;r++){
            int idx = tid + (r<<8); int row = idx>>5; int c4 = (idx&31)<<2;
            *(float4*)&ks[row*132+c4] = *(const float4*)(kg + (size_t)row*512 + c4);
            *(float4*)&vs[row*128+c4] = *(const float4*)(vg + (size_t)row*512 + c4);
        }
        if (tid < 32) as_[tid] = av[bh*SEQ + s0 + tid];
        __syncthreads();

        // qk: thread -> (t = tb..tb+3, s = sq)
        float a0=0,a1=0,a2=0,a3=0;
        const float* kr = &ks[sq*132];
        #pragma unroll
        for (int d4=0; d4<128; d4+=4){
            float4 kv = *(const float4*)(kr+d4);
            float4 q0 = *(const float4*)&qs[(tb+0)*128+d4];
            float4 q1 = *(const float4*)&qs[(tb+1)*128+d4];
            float4 q2 = *(const float4*)&qs[(tb+2)*128+d4];
            float4 q3 = *(const float4*)&qs[(tb+3)*128+d4];
            a0 += q0.x*kv.x + q0.y*kv.y + q0.z*kv.z + q0.w*kv.w;
            a1 += q1.x*kv.x + q1.y*kv.y + q1.z*kv.z + q1.w*kv.w;
            a2 += q2.x*kv.x + q2.y*kv.y + q2.z*kv.z + q2.w*kv.w;
            a3 += q3.x*kv.x + q3.y*kv.y + q3.z*kv.z + q3.w*kv.w;
        }
        int sg = s0 + sq;
        {
            float aa[4] = {a0,a1,a2,a3};
            #pragma unroll
            for (int j=0;j<4;j++){
                int t = tb+j; int tg = t0 + t;
                float val = (sg <= tg) ? aa[j]*scale*__expf(fct[t] + as_[sq] - mt[t]) : 0.f;
                Ps[t*33+sq] = val;
            }
        }
        __syncthreads();

        // pv: thread -> (t = tp, d = dg*4 + 32j)
        #pragma unroll 4
        for (int s=0;s<32;s++){
            float p = Ps[tp*33+s];
            if (dg==0) den += p;
            const float* vr = &vs[s*128];
            float4 v0 = *(const float4*)(vr + (dg<<2));
            float4 v1 = *(const float4*)(vr + (dg<<2) + 32);
            float4 v2 = *(const float4*)(vr + (dg<<2) + 64);
            float4 v3 = *(const float4*)(vr + (dg<<2) + 96);
            acc0.x+=p*v0.x; acc0.y+=p*v0.y; acc0.z+=p*v0.z; acc0.w+=p*v0.w;
            acc1.x+=p*v1.x; acc1.y+=p*v1.y; acc1.z+=p*v1.z; acc1.w+=p*v1.w;
            acc2.x+=p*v2.x; acc2.y+=p*v2.y; acc2.z+=p*v2.z; acc2.w+=p*v2.w;
            acc3.x+=p*v3.x; acc3.y+=p*v3.y; acc3.z+=p*v3.z; acc3.w+=p*v3.w;
        }
    }
    __syncthreads();
    if (dg==0) dns[tp] = den;
    __syncthreads();
    float dd = dns[tp];
    float nrm = fmaxf(fabsf(dd), __expf(-mt[tp])) + 1e-6f;
    float inv = 1.f / nrm;
    float* og = out + ((size_t)(b*SEQ + t0 + tp))*512 + hh*128 + (dg<<2);
    float4 o0 = make_float4(acc0.x*inv, acc0.y*inv, acc0.z*inv, acc0.w*inv);
    float4 o1 = make_float4(acc1.x*inv, acc1.y*inv, acc1.z*inv, acc1.w*inv);
    float4 o2 = make_float4(acc2.x*inv, acc2.y*inv, acc2.z*inv, acc2.w*inv);
    float4 o3 = make_float4(acc3.x*inv, acc3.y*inv, acc3.z*inv, acc3.w*inv);
    *(float4*)(og)      = o0;
    *(float4*)(og + 32) = o1;
    *(float4*)(og + 64) = o2;
    *(float4*)(og + 96) = o3;
}

// ---------------- groupnorm per (b,s,h) + skip*xc + silu(z) gating ----------------
__global__ void gn_fuse_kernel(const float* __restrict__ att, const float* __restrict__ up,
                               const float* __restrict__ xc, const float* __restrict__ gng,
                               const float* __restrict__ gnb, const float* __restrict__ skip,
                               float* __restrict__ out){
    __shared__ float sh[4];
    __shared__ float s_mu, s_var;
    int tid = threadIdx.x;                 // 128
    int bsh = blockIdx.x; int hh = bsh & 3; int tok = bsh >> 2;
    int c = hh*128 + tid;
    float vv = att[(size_t)tok*512 + c];
    float s = warp_sum(vv);
    if ((tid&31)==0) sh[tid>>5] = s;
    __syncthreads();
    if (tid==0) s_mu = (sh[0]+sh[1]+sh[2]+sh[3])*(1.f/128.f);
    __syncthreads();
    float mu = s_mu;
    float d = vv - mu;
    float s2 = warp_sum(d*d);
    if ((tid&31)==0) sh[tid>>5] = s2;
    __syncthreads();
    if (tid==0) s_var = (sh[0]+sh[1]+sh[2]+sh[3])*(1.f/128.f);
    __syncthreads();
    float yn = d*rsqrtf(s_var + 1e-5f)*gng[c] + gnb[c];
    float val = yn + skip[c]*xc[(size_t)tok*512 + c];
    float z = up[(size_t)tok*1024 + 512 + c];
    val *= z / (1.f + expf(-z));
    out[(size_t)tok*512 + c] = val;
}

// ---------------- final: LN(last token) @ Wf + bf ----------------
__global__ void final_kernel(const float* __restrict__ h, const float* __restrict__ g,
                             const float* __restrict__ b, const float* __restrict__ Wf,
                             const float* __restrict__ bf, float* __restrict__ out){
    __shared__ float sh[8];
    __shared__ float sv;
    int bb = blockIdx.x, tid = threadIdx.x;   // 256 threads
    float vv = h[((size_t)(bb*SEQ + SEQ-1))*256 + tid];
    float s = warp_sum(vv);
    if (!(tid&31)) sh[tid>>5] = s;
    __syncthreads();
    if (tid==0){ float t=0; for(int i=0;i<8;i++) t+=sh[i]; sv = t*(1.f/256.f); }
    __syncthreads();
    float mu = sv;
    float d = vv - mu;
    float s2 = warp_sum(d*d);
    if (!(tid&31)) sh[tid>>5] = s2;
    __syncthreads();
    if (tid==0){ float t=0; for(int i=0;i<8;i++) t+=sh[i]; sv = t*(1.f/256.f); }
    __syncthreads();
    float yn = d*rsqrtf(sv + 1e-5f)*g[tid] + b[tid];
    float p = yn * Wf[tid];
    float s3 = warp_sum(p);
    __syncthreads();
    if (!(tid&31)) sh[tid>>5] = s3;
    __syncthreads();
    if (tid==0){ float t=0; for(int i=0;i<8;i++) t+=sh[i]; out[bb] = t + bf[0]; }
}

// ---------------- launch ----------------
extern "C" void kernel_launch(void* const* d_in, const int* in_sizes, int n_in,
                              void* d_out, int out_size){
    const float* x    = (const float*)d_in[0];
    const float* tf   = (const float*)d_in[1];
    const float* Wp   = (const float*)d_in[2];
    const float* bp   = (const float*)d_in[3];
    const float* ln_g = (const float*)d_in[4];
    const float* ln_b = (const float*)d_in[5];
    const float* Wup  = (const float*)d_in[6];
    const float* bup  = (const float*)d_in[7];
    const float* cw   = (const float*)d_in[8];
    const float* cb   = (const float*)d_in[9];
    const float* Wq   = (const float*)d_in[10];
    const float* Wk   = (const float*)d_in[11];
    const float* Wv   = (const float*)d_in[12];
    const float* Wif  = (const float*)d_in[13];
    const float* bif  = (const float*)d_in[14];
    const float* gng  = (const float*)d_in[15];
    const float* gnb  = (const float*)d_in[16];
    const float* skip = (const float*)d_in[17];
    const float* Wdn  = (const float*)d_in[18];
    const float* bdn  = (const float*)d_in[19];
    const float* lnfg = (const float*)d_in[20];
    const float* lnfb = (const float*)d_in[21];
    const float* Wf   = (const float*)d_in[22];
    const float* bf   = (const float*)d_in[23];

    float *h,*hn,*up,*xc,*q,*k,*v,*gates,*Fc,*a,*m,*att,*att2;
    cudaGetSymbolAddress((void**)&h,    g_h);
    cudaGetSymbolAddress((void**)&hn,   g_hn);
    cudaGetSymbolAddress((void**)&up,   g_up);
    cudaGetSymbolAddress((void**)&xc,   g_xc);
    cudaGetSymbolAddress((void**)&q,    g_q);
    cudaGetSymbolAddress((void**)&k,    g_k);
    cudaGetSymbolAddress((void**)&v,    g_v);
    cudaGetSymbolAddress((void**)&gates,g_gates);
    cudaGetSymbolAddress((void**)&Fc,   g_Fc);
    cudaGetSymbolAddress((void**)&a,    g_a);
    cudaGetSymbolAddress((void**)&m,    g_m);
    cudaGetSymbolAddress((void**)&att,  g_att);
    cudaGetSymbolAddress((void**)&att2, g_att2);

    int attn_smem = (32*128 + 32*132 + 32*128 + 32*33 + 128) * sizeof(float);
    cudaFuncSetAttribute(attn_kernel, cudaFuncAttributeMaxDynamicSharedMemorySize, attn_smem);

    embed_kernel<<<TOK*256/256, 256>>>(x, tf, Wp, bp, h);

    for (int l=0; l<NL; l++){
        ln_kernel<<<TOK/8, 256>>>(h, ln_g + l*256, ln_b + l*256, hn);
        mma_gemm<<<dim3(1024/64, TOK/128), 256>>>(hn, 256, Wup + (size_t)l*256*1024, 1024,
                                                  up, 1024, bup + l*1024, nullptr, 256);
        conv_silu_kernel<<<TOK*512/256, 256>>>(up, cw + l*4*512, cb + l*512, xc);
        mma_gemm<<<dim3(512/64, TOK/128), 256>>>(xc, 512, Wq + (size_t)l*512*512, 512,
                                                 q, 512, nullptr, nullptr, 512);
        mma_gemm<<<dim3(512/64, TOK/128), 256>>>(xc, 512, Wk + (size_t)l*512*512, 512,
                                                 k, 512, nullptr, nullptr, 512);
        mma_gemm<<<dim3(512/64, TOK/128), 256>>>(up, 1024, Wv + (size_t)l*512*512, 512,
                                                 v, 512, nullptr, nullptr, 512);
        gates_kernel<<<TOK, 256>>>(q, k, v, Wif + (size_t)l*1536*8, bif + l*8, gates);
        scan_kernel<<<1, 32>>>(gates, Fc, a, m);
        attn_kernel<<<dim3(BATCH*NH, SEQ/32), 256, attn_smem>>>(q, k, v, Fc, a, m, att);
        gn_fuse_kernel<<<TOK*NH, 128>>>(att, up, xc, gng + l*512, gnb + l*512, skip + l*512, att2);
        mma_gemm<<<dim3(256/64, TOK/128), 256>>>(att2, 512, Wdn + (size_t)l*512*256, 256,
                                                 h, 256, bdn + l*256, h, 512);
    }
    final_kernel<<<BATCH, 256>>>(h, lnfg, lnfb, Wf, bf, (float*)d_out);
}

// round 4
// speedup vs baseline: 2.0253x; 1.5583x over previous
#include <cuda_runtime.h>
#include <cstdint>
#include <cstddef>

#define SEQ 1024
#define BATCH 8
#define TOK (BATCH*SEQ)
#define DMODEL 256
#define DI 512
#define NH 4
#define DHH 128
#define NL 4

// ---------------- scratch (device globals; no allocation allowed) ----------------
__device__ float g_h[TOK*DMODEL];
__device__ float g_hn[TOK*DMODEL];
__device__ float g_up[TOK*1024];
__device__ float g_xc[TOK*DI];
__device__ float g_q[TOK*DI];
__device__ float g_k[TOK*DI];
__device__ float g_v[TOK*DI];
__device__ float g_gates[TOK*8];
__device__ float g_Fc[BATCH*NH*SEQ];
__device__ float g_a[BATCH*NH*SEQ];
__device__ float g_m[BATCH*NH*SEQ];
__device__ float g_att[TOK*DI];
__device__ float g_att2[TOK*DI];

__device__ __forceinline__ float warp_sum(float v){
    #pragma unroll
    for (int o=16;o;o>>=1) v += __shfl_xor_sync(0xffffffffu, v, o);
    return v;
}

__device__ __forceinline__ uint32_t f2tf(float x){
    uint32_t r; asm("cvt.rna.tf32.f32 %0, %1;" : "=r"(r) : "f"(x)); return r;
}

__device__ __forceinline__ void mma_tf32(float* c, const uint32_t* a, uint32_t b0, uint32_t b1){
    asm volatile(
      "mma.sync.aligned.m16n8k8.row.col.f32.tf32.tf32.f32 "
      "{%0,%1,%2,%3}, {%4,%5,%6,%7}, {%8,%9}, {%0,%1,%2,%3};\n"
      : "+f"(c[0]), "+f"(c[1]), "+f"(c[2]), "+f"(c[3])
      : "r"(a[0]), "r"(a[1]), "r"(a[2]), "r"(a[3]), "r"(b0), "r"(b1));
}

// ---------------- embed: h = [x, tf] @ Wp + bp ----------------
__global__ void embed_kernel(const float* __restrict__ x, const float* __restrict__ tf,
                             const float* __restrict__ Wp, const float* __restrict__ bp,
                             float* __restrict__ h){
    int idx = blockIdx.x*blockDim.x + threadIdx.x;       // TOK*256
    int j = idx & 255; int tok = idx >> 8;
    float acc = bp[j] + x[tok]*Wp[j];
    #pragma unroll
    for (int f=0; f<4; f++) acc += tf[tok*4+f]*Wp[(1+f)*256+j];
    h[idx] = acc;
}

// ---------------- layernorm over D=256, warp per row ----------------
__global__ void ln_kernel(const float* __restrict__ x, const float* __restrict__ g,
                          const float* __restrict__ b, float* __restrict__ y){
    int row = blockIdx.x*8 + (threadIdx.x>>5);
    int lane = threadIdx.x & 31;
    const float* xr = x + (size_t)row*256;
    float4 v0 = *(const float4*)(xr + lane*4);
    float4 v1 = *(const float4*)(xr + 128 + lane*4);
    float s = v0.x+v0.y+v0.z+v0.w + v1.x+v1.y+v1.z+v1.w;
    s = warp_sum(s);
    float mu = s * (1.f/256.f);
    float d0x=v0.x-mu, d0y=v0.y-mu, d0z=v0.z-mu, d0w=v0.w-mu;
    float d1x=v1.x-mu, d1y=v1.y-mu, d1z=v1.z-mu, d1w=v1.w-mu;
    float sq = d0x*d0x+d0y*d0y+d0z*d0z+d0w*d0w + d1x*d1x+d1y*d1y+d1z*d1z+d1w*d1w;
    sq = warp_sum(sq);
    float is = rsqrtf(sq*(1.f/256.f) + 1e-5f);
    float4 g0 = *(const float4*)(g + lane*4);
    float4 g1 = *(const float4*)(g + 128 + lane*4);
    float4 b0 = *(const float4*)(b + lane*4);
    float4 b1 = *(const float4*)(b + 128 + lane*4);
    float* yr = y + (size_t)row*256;
    float4 o0, o1;
    o0.x = d0x*is*g0.x + b0.x; o0.y = d0y*is*g0.y + b0.y;
    o0.z = d0z*is*g0.z + b0.z; o0.w = d0w*is*g0.w + b0.w;
    o1.x = d1x*is*g1.x + b1.x; o1.y = d1y*is*g1.y + b1.y;
    o1.z = d1z*is*g1.z + b1.z; o1.w = d1w*is*g1.w + b1.w;
    *(float4*)(yr + lane*4) = o0;
    *(float4*)(yr + 128 + lane*4) = o1;
}

// ---------------- tf32 tensor-core GEMM ----------------
__global__ __launch_bounds__(256) void mma_gemm(
    const float* __restrict__ A, int lda,
    const float* __restrict__ B, int ldb,
    float* __restrict__ C, int ldc,
    const float* __restrict__ bias,
    const float* __restrict__ resid,
    int K)
{
    __shared__ uint32_t As[128*32];
    __shared__ uint32_t Bs[32*72];
    int tid = threadIdx.x;
    int lane = tid & 31, wid = tid >> 5;
    int wm = wid >> 1, wn = wid & 1;
    int m0 = blockIdx.y*128, n0 = blockIdx.x*64;

    float c[2][4][4] = {};

    int arow = tid >> 3;
    int ak4  = (tid & 7) << 2;
    int bn4  = (tid & 15) << 2;
    int bk   = tid >> 4;

    for (int k0 = 0; k0 < K; k0 += 32){
        #pragma unroll
        for (int r = 0; r < 4; r++){
            int row = arow + (r<<5);
            float4 v = *(const float4*)(A + (size_t)(m0+row)*lda + k0 + ak4);
            int chunk = (ak4>>2) ^ (row&7);
            *(uint4*)&As[row*32 + (chunk<<2)] =
                make_uint4(f2tf(v.x), f2tf(v.y), f2tf(v.z), f2tf(v.w));
        }
        #pragma unroll
        for (int r = 0; r < 2; r++){
            int kk = bk + (r<<4);
            float4 v = *(const float4*)(B + (size_t)(k0+kk)*ldb + n0 + bn4);
            *(uint4*)&Bs[kk*72 + bn4] =
                make_uint4(f2tf(v.x), f2tf(v.y), f2tf(v.z), f2tf(v.w));
        }
        __syncthreads();
        #pragma unroll
        for (int ks = 0; ks < 4; ks++){
            uint32_t a[2][4], b[4][2];
            #pragma unroll
            for (int mt=0; mt<2; mt++){
                int r0 = wm*32 + mt*16 + (lane>>2);
                int r1 = r0 + 8;
                int j0 = ks*2, j1 = ks*2 + 1;
                a[mt][0] = As[r0*32 + (((j0^(r0&7))<<2)) + (lane&3)];
                a[mt][1] = As[r1*32 + (((j0^(r1&7))<<2)) + (lane&3)];
                a[mt][2] = As[r0*32 + (((j1^(r0&7))<<2)) + (lane&3)];
                a[mt][3] = As[r1*32 + (((j1^(r1&7))<<2)) + (lane&3)];
            }
            int krow = ks*8 + (lane&3);
            #pragma unroll
            for (int nt=0; nt<4; nt++){
                int col = wn*32 + nt*8 + (lane>>2);
                b[nt][0] = Bs[krow*72 + col];
                b[nt][1] = Bs[(krow+4)*72 + col];
            }
            #pragma unroll
            for (int mt=0; mt<2; mt++)
              #pragma unroll
              for (int nt=0; nt<4; nt++)
                mma_tf32(c[mt][nt], a[mt], b[nt][0], b[nt][1]);
        }
        __syncthreads();
    }

    #pragma unroll
    for (int mt=0;mt<2;mt++){
        #pragma unroll
        for (int nt=0;nt<4;nt++){
            int row0 = m0 + wm*32 + mt*16 + (lane>>2);
            int col  = n0 + wn*32 + nt*8 + ((lane&3)<<1);
            float bx=0.f, by=0.f;
            if (bias){ bx = bias[col]; by = bias[col+1]; }
            float2 r0v = make_float2(0.f,0.f), r1v = make_float2(0.f,0.f);
            if (resid){
                r0v = *(const float2*)&resid[(size_t)row0*ldc + col];
                r1v = *(const float2*)&resid[(size_t)(row0+8)*ldc + col];
            }
            *(float2*)&C[(size_t)row0*ldc + col] =
                make_float2(c[mt][nt][0]+bx+r0v.x, c[mt][nt][1]+by+r0v.y);
            *(float2*)&C[(size_t)(row0+8)*ldc + col] =
                make_float2(c[mt][nt][2]+bx+r1v.x, c[mt][nt][3]+by+r1v.y);
        }
    }
}

// ---------------- causal depthwise conv (K=4) + silu ----------------
__global__ void conv_silu_kernel(const float* __restrict__ up, const float* __restrict__ w,
                                 const float* __restrict__ cb, float* __restrict__ xc){
    int idx = blockIdx.x*blockDim.x + threadIdx.x;    // TOK*512
    int c = idx & 511; int tok = idx >> 9; int t = tok & 1023;
    float acc = cb[c];
    #pragma unroll
    for (int j=0;j<4;j++){
        int ts = t - 3 + j;
        if (ts >= 0) acc += w[j*512+c] * up[(size_t)(tok-3+j)*1024 + c];
    }
    float sv = acc / (1.f + expf(-acc));
    xc[(size_t)tok*512 + c] = sv;
}

// ---------------- gates = [q,k,v] @ Wif + bif (N=8) ----------------
__global__ void gates_kernel(const float* __restrict__ q, const float* __restrict__ k,
                             const float* __restrict__ v, const float* __restrict__ Wif,
                             const float* __restrict__ bif, float* __restrict__ gates){
    __shared__ float gi[1536];
    int tok = blockIdx.x, tid = threadIdx.x;
    for (int i=tid;i<512;i+=256){
        gi[i]      = q[(size_t)tok*512+i];
        gi[512+i]  = k[(size_t)tok*512+i];
        gi[1024+i] = v[(size_t)tok*512+i];
    }
    __syncthreads();
    int w = tid>>5, lane = tid&31;
    float acc = 0.f;
    for (int i=lane;i<1536;i+=32) acc += gi[i]*Wif[i*8+w];
    acc = warp_sum(acc);
    if (!lane) gates[tok*8+w] = acc + bif[w];
}

// ---------------- parallel gate scan: warp per (b,h), chunked warp-scan ----------------
__global__ void scan_kernel2(const float* __restrict__ gates, float* __restrict__ Fc,
                             float* __restrict__ a, float* __restrict__ m){
    int warp = threadIdx.x >> 5;      // 0..31, one block of 1024 threads
    int lane = threadIdx.x & 31;
    int b = warp>>2, h = warp&3;
    float cfc = 0.f, cmax = -1e30f;
    for (int c=0;c<32;c++){
        int s = c*32 + lane;
        const float* g = gates + ((size_t)(b*SEQ + s))*8;
        float ip = g[h], fp = g[4+h];
        float lf = fminf(fp, 0.f) - log1pf(expf(-fabsf(fp)));
        float x = lf;
        #pragma unroll
        for (int o=1;o<32;o<<=1){ float y = __shfl_up_sync(0xffffffffu, x, o); if (lane>=o) x += y; }
        float fc = cfc + x;
        float av = ip - fc;
        float mx = av;
        #pragma unroll
        for (int o=1;o<32;o<<=1){ float y = __shfl_up_sync(0xffffffffu, mx, o); if (lane>=o) mx = fmaxf(mx, y); }
        float cm = fmaxf(cmax, mx);
        int off = warp*SEQ + s;
        Fc[off] = fc; a[off] = av; m[off] = fc + cm;
        cfc += __shfl_sync(0xffffffffu, x, 31);
        cmax = fmaxf(cmax, __shfl_sync(0xffffffffu, mx, 31));
    }
}

// ---------------- mLSTM attention on tensor cores ----------------
// CTA: one (b,h), 64 q-rows. 8 warps in 4x2. QK^T and P@V via m16n8k8 tf32.
// smem strides chosen for conflict-free fragment access:
//   Q/K: 132 (bank = 4*row + k), V: 136 (bank = 8*k + d), P: 68 (bank = 4*row + k)
#define ATS 132
#define VTS 136
#define PTS 68
__global__ __launch_bounds__(256) void attn_mma(
    const float* __restrict__ q, const float* __restrict__ k, const float* __restrict__ v,
    const float* __restrict__ Fcv, const float* __restrict__ av, const float* __restrict__ mv,
    float* __restrict__ out)
{
    extern __shared__ uint32_t smu[];
    uint32_t* Qs = smu;                 // 64*132, reused as Ps (64*68)
    uint32_t* Ks = Qs + 64*ATS;
    uint32_t* Vs = Ks + 64*ATS;
    float* fct  = (float*)(Vs + 64*VTS); // 64
    float* mt   = fct + 64;              // 64
    float* as_  = mt + 64;               // 64
    float* den2 = as_ + 64;              // 128

    int bh = blockIdx.x; int b = bh>>2, hh = bh&3;
    int it = (int)(gridDim.y - 1) - (int)blockIdx.y;   // longest work first
    int t0 = it<<6;
    int tid = threadIdx.x, lane = tid&31, wid = tid>>5;
    int wm = wid>>1, wn = wid&1;
    int ls = lane>>2, lk = lane&3;
    const float scale = 0.08838834764831845f; // 1/sqrt(128)

    // stage Q tile (64x128) as tf32
    const float* qg = q + ((size_t)(b*SEQ + t0))*512 + hh*128;
    #pragma unroll
    for (int r=0;r<8;r++){
        int idx = tid + (r<<8);
        int row = idx>>5, c4 = (idx&31)<<2;
        float4 vq = *(const float4*)(qg + (size_t)row*512 + c4);
        *(uint4*)&Qs[row*ATS + c4] = make_uint4(f2tf(vq.x), f2tf(vq.y), f2tf(vq.z), f2tf(vq.w));
    }
    if (tid < 64){ int tg = bh*SEQ + t0 + tid; fct[tid] = Fcv[tg]; mt[tid] = mv[tg]; }
    __syncthreads();

    // hoist Q A-fragments into registers (16 k-steps x 4 regs)
    uint32_t qf[16][4];
    int r0 = wm*16 + ls, r1 = r0 + 8;
    #pragma unroll
    for (int ks=0; ks<16; ks++){
        int kc = ks*8 + lk;
        qf[ks][0] = Qs[r0*ATS + kc];
        qf[ks][1] = Qs[r1*ATS + kc];
        qf[ks][2] = Qs[r0*ATS + kc + 4];
        qf[ks][3] = Qs[r1*ATS + kc + 4];
    }

    float oacc[8][4];
    #pragma unroll
    for (int i=0;i<8;i++){ oacc[i][0]=0.f; oacc[i][1]=0.f; oacc[i][2]=0.f; oacc[i][3]=0.f; }
    float den0 = 0.f, den1 = 0.f;

    for (int js=0; js<=it; js++){
        int s0 = js<<6;
        __syncthreads();   // protect Ks/Vs/as_/Ps from previous iteration readers
        const float* kg = k + ((size_t)(b*SEQ + s0))*512 + hh*128;
        const float* vg = v + ((size_t)(b*SEQ + s0))*512 + hh*128;
        #pragma unroll
        for (int r=0;r<8;r++){
            int idx = tid + (r<<8);
            int row = idx>>5, c4 = (idx&31)<<2;
            float4 kv = *(const float4*)(kg + (size_t)row*512 + c4);
            float4 vv = *(const float4*)(vg + (size_t)row*512 + c4);
            *(uint4*)&Ks[row*ATS + c4] = make_uint4(f2tf(kv.x), f2tf(kv.y), f2tf(kv.z), f2tf(kv.w));
            *(uint4*)&Vs[row*VTS + c4] = make_uint4(f2tf(vv.x), f2tf(vv.y), f2tf(vv.z), f2tf(vv.w));
        }
        if (tid < 64) as_[tid] = av[bh*SEQ + s0 + tid];
        __syncthreads();

        // ---- S = Q @ K^T (64x64) ----
        float sacc[4][4] = {};
        #pragma unroll
        for (int ks=0; ks<16; ks++){
            #pragma unroll
            for (int nt=0; nt<4; nt++){
                int sc = wn*32 + nt*8 + ls;
                uint32_t b0 = Ks[sc*ATS + ks*8 + lk];
                uint32_t b1 = Ks[sc*ATS + ks*8 + lk + 4];
                mma_tf32(sacc[nt], qf[ks], b0, b1);
            }
        }

        // ---- weight, mask, accumulate denominator, write P (tf32) ----
        float f0 = fct[r0], mm0 = mt[r0], f1 = fct[r1], mm1 = mt[r1];
        bool diag = (js == it);
        #pragma unroll
        for (int nt=0; nt<4; nt++){
            int c0 = wn*32 + nt*8 + (lk<<1);
            int c1 = c0 + 1;
            float a0v = as_[c0], a1v = as_[c1];
            float v00 = sacc[nt][0]*scale*__expf(f0 + a0v - mm0);
            float v01 = sacc[nt][1]*scale*__expf(f0 + a1v - mm0);
            float v10 = sacc[nt][2]*scale*__expf(f1 + a0v - mm1);
            float v11 = sacc[nt][3]*scale*__expf(f1 + a1v - mm1);
            if (diag){
                if (c0 > r0) v00 = 0.f;
                if (c1 > r0) v01 = 0.f;
                if (c0 > r1) v10 = 0.f;
                if (c1 > r1) v11 = 0.f;
            }
            den0 += v00 + v01;
            den1 += v10 + v11;
            *(uint2*)&Qs[r0*PTS + c0] = make_uint2(f2tf(v00), f2tf(v01));
            *(uint2*)&Qs[r1*PTS + c0] = make_uint2(f2tf(v10), f2tf(v11));
        }
        __syncthreads();   // P visible to all warps

        // ---- out += P @ V (64x128, K=64) ----
        #pragma unroll
        for (int ks=0; ks<8; ks++){
            uint32_t af[4];
            af[0] = Qs[r0*PTS + ks*8 + lk];
            af[1] = Qs[r1*PTS + ks*8 + lk];
            af[2] = Qs[r0*PTS + ks*8 + lk + 4];
            af[3] = Qs[r1*PTS + ks*8 + lk + 4];
            #pragma unroll
            for (int nt=0; nt<8; nt++){
                int dc = wn*64 + nt*8 + ls;
                uint32_t b0 = Vs[(ks*8 + lk)*VTS + dc];
                uint32_t b1 = Vs[(ks*8 + lk + 4)*VTS + dc];
                mma_tf32(oacc[nt], af, b0, b1);
            }
        }
    }

    // ---- denominator: quad reduce + combine across warp columns ----
    den0 += __shfl_xor_sync(0xffffffffu, den0, 1);
    den0 += __shfl_xor_sync(0xffffffffu, den0, 2);
    den1 += __shfl_xor_sync(0xffffffffu, den1, 1);
    den1 += __shfl_xor_sync(0xffffffffu, den1, 2);
    if (lk == 0){ den2[wn*64 + r0] = den0; den2[wn*64 + r1] = den1; }
    __syncthreads();
    float dt0 = den2[r0] + den2[64 + r0];
    float dt1 = den2[r1] + den2[64 + r1];
    float inv0 = 1.f / (fmaxf(fabsf(dt0), __expf(-mt[r0])) + 1e-6f);
    float inv1 = 1.f / (fmaxf(fabsf(dt1), __expf(-mt[r1])) + 1e-6f);

    float* og = out + ((size_t)(b*SEQ + t0))*512 + hh*128;
    #pragma unroll
    for (int nt=0; nt<8; nt++){
        int dc = wn*64 + nt*8 + (lk<<1);
        *(float2*)(og + (size_t)r0*512 + dc) = make_float2(oacc[nt][0]*inv0, oacc[nt][1]*inv0);
        *(float2*)(og + (size_t)r1*512 + dc) = make_float2(oacc[nt][2]*inv1, oacc[nt][3]*inv1);
    }
}

// ---------------- groupnorm per (b,s,h) + skip*xc + silu(z) gating ----------------
__global__ void gn_fuse_kernel(const float* __restrict__ att, const float* __restrict__ up,
                               const float* __restrict__ xc, const float* __restrict__ gng,
                               const float* __restrict__ gnb, const float* __restrict__ skip,
                               float* __restrict__ out){
    __shared__ float sh[4];
    __shared__ float s_mu, s_var;
    int tid = threadIdx.x;                 // 128
    int bsh = blockIdx.x; int hh = bsh & 3; int tok = bsh >> 2;
    int c = hh*128 + tid;
    float vv = att[(size_t)tok*512 + c];
    float s = warp_sum(vv);
    if ((tid&31)==0) sh[tid>>5] = s;
    __syncthreads();
    if (tid==0) s_mu = (sh[0]+sh[1]+sh[2]+sh[3])*(1.f/128.f);
    __syncthreads();
    float mu = s_mu;
    float d = vv - mu;
    float s2 = warp_sum(d*d);
    if ((tid&31)==0) sh[tid>>5] = s2;
    __syncthreads();
    if (tid==0) s_var = (sh[0]+sh[1]+sh[2]+sh[3])*(1.f/128.f);
    __syncthreads();
    float yn = d*rsqrtf(s_var + 1e-5f)*gng[c] + gnb[c];
    float val = yn + skip[c]*xc[(size_t)tok*512 + c];
    float z = up[(size_t)tok*1024 + 512 + c];
    val *= z / (1.f + expf(-z));
    out[(size_t)tok*512 + c] = val;
}

// ---------------- final: LN(last token) @ Wf + bf ----------------
__global__ void final_kernel(const float* __restrict__ h, const float* __restrict__ g,
                             const float* __restrict__ b, const float* __restrict__ Wf,
                             const float* __restrict__ bf, float* __restrict__ out){
    __shared__ float sh[8];
    __shared__ float sv;
    int bb = blockIdx.x, tid = threadIdx.x;   // 256 threads
    float vv = h[((size_t)(bb*SEQ + SEQ-1))*256 + tid];
    float s = warp_sum(vv);
    if (!(tid&31)) sh[tid>>5] = s;
    __syncthreads();
    if (tid==0){ float t=0; for(int i=0;i<8;i++) t+=sh[i]; sv = t*(1.f/256.f); }
    __syncthreads();
    float mu = sv;
    float d = vv - mu;
    float s2 = warp_sum(d*d);
    if (!(tid&31)) sh[tid>>5] = s2;
    __syncthreads();
    if (tid==0){ float t=0; for(int i=0;i<8;i++) t+=sh[i]; sv = t*(1.f/256.f); }
    __syncthreads();
    float yn = d*rsqrtf(sv + 1e-5f)*g[tid] + b[tid];
    float p = yn * Wf[tid];
    float s3 = warp_sum(p);
    __syncthreads();
    if (!(tid&31)) sh[tid>>5] = s3;
    __syncthreads();
    if (tid==0){ float t=0; for(int i=0;i<8;i++) t+=sh[i]; out[bb] = t + bf[0]; }
}

// ---------------- launch ----------------
extern "C" void kernel_launch(void* const* d_in, const int* in_sizes, int n_in,
                              void* d_out, int out_size){
    const float* x    = (const float*)d_in[0];
    const float* tf   = (const float*)d_in[1];
    const float* Wp   = (const float*)d_in[2];
    const float* bp   = (const float*)d_in[3];
    const float* ln_g = (const float*)d_in[4];
    const float* ln_b = (const float*)d_in[5];
    const float* Wup  = (const float*)d_in[6];
    const float* bup  = (const float*)d_in[7];
    const float* cw   = (const float*)d_in[8];
    const float* cb   = (const float*)d_in[9];
    const float* Wq   = (const float*)d_in[10];
    const float* Wk   = (const float*)d_in[11];
    const float* Wv   = (const float*)d_in[12];
    const float* Wif  = (const float*)d_in[13];
    const float* bif  = (const float*)d_in[14];
    const float* gng  = (const float*)d_in[15];
    const float* gnb  = (const float*)d_in[16];
    const float* skip = (const float*)d_in[17];
    const float* Wdn  = (const float*)d_in[18];
    const float* bdn  = (const float*)d_in[19];
    const float* lnfg = (const float*)d_in[20];
    const float* lnfb = (const float*)d_in[21];
    const float* Wf   = (const float*)d_in[22];
    const float* bf   = (const float*)d_in[23];

    float *h,*hn,*up,*xc,*q,*k,*v,*gates,*Fc,*a,*m,*att,*att2;
    cudaGetSymbolAddress((void**)&h,    g_h);
    cudaGetSymbolAddress((void**)&hn,   g_hn);
    cudaGetSymbolAddress((void**)&up,   g_up);
    cudaGetSymbolAddress((void**)&xc,   g_xc);
    cudaGetSymbolAddress((void**)&q,    g_q);
    cudaGetSymbolAddress((void**)&k,    g_k);
    cudaGetSymbolAddress((void**)&v,    g_v);
    cudaGetSymbolAddress((void**)&gates,g_gates);
    cudaGetSymbolAddress((void**)&Fc,   g_Fc);
    cudaGetSymbolAddress((void**)&a,    g_a);
    cudaGetSymbolAddress((void**)&m,    g_m);
    cudaGetSymbolAddress((void**)&att,  g_att);
    cudaGetSymbolAddress((void**)&att2, g_att2);

    int attn_smem = (64*ATS + 64*ATS + 64*VTS + 64 + 64 + 64 + 128) * 4;
    static int attr_set = 0;
    if (!attr_set){
        cudaFuncSetAttribute(attn_mma, cudaFuncAttributeMaxDynamicSharedMemorySize, attn_smem);
        attr_set = 1;
    }

    embed_kernel<<<TOK*256/256, 256>>>(x, tf, Wp, bp, h);

    for (int l=0; l<NL; l++){
        ln_kernel<<<TOK/8, 256>>>(h, ln_g + l*256, ln_b + l*256, hn);
        mma_gemm<<<dim3(1024/64, TOK/128), 256>>>(hn, 256, Wup + (size_t)l*256*1024, 1024,
                                                  up, 1024, bup + l*1024, nullptr, 256);
        conv_silu_kernel<<<TOK*512/256, 256>>>(up, cw + l*4*512, cb + l*512, xc);
        mma_gemm<<<dim3(512/64, TOK/128), 256>>>(xc, 512, Wq + (size_t)l*512*512, 512,
                                                 q, 512, nullptr, nullptr, 512);
        mma_gemm<<<dim3(512/64, TOK/128), 256>>>(xc, 512, Wk + (size_t)l*512*512, 512,
                                                 k, 512, nullptr, nullptr, 512);
        mma_gemm<<<dim3(512/64, TOK/128), 256>>>(up, 1024, Wv + (size_t)l*512*512, 512,
                                                 v, 512, nullptr, nullptr, 512);
        gates_kernel<<<TOK, 256>>>(q, k, v, Wif + (size_t)l*1536*8, bif + l*8, gates);
        scan_kernel2<<<1, 1024>>>(gates, Fc, a, m);
        attn_mma<<<dim3(BATCH*NH, SEQ/64), 256, attn_smem>>>(q, k, v, Fc, a, m, att);
        gn_fuse_kernel<<<TOK*NH, 128>>>(att, up, xc, gng + l*512, gnb + l*512, skip + l*512, att2);
        mma_gemm<<<dim3(256/64, TOK/128), 256>>>(att2, 512, Wdn + (size_t)l*512*256, 256,
                                                 h, 256, bdn + l*256, h, 512);
    }
    final_kernel<<<BATCH, 256>>>(h, lnfg, lnfb, Wf, bf, (float*)d_out);
}

// round 5
// speedup vs baseline: 4.0643x; 2.0067x over previous
#include <cuda_runtime.h>
#include <cuda_bf16.h>
#include <cstdint>
#include <cstddef>

#define SEQ 1024
#define BATCH 8
#define TOK (BATCH*SEQ)
#define DMODEL 256
#define DI 512
#define NH 4
#define DHH 128
#define NL 4

// ---------------- scratch (device globals; no allocation allowed) ----------------
__device__ float g_h[TOK*DMODEL];
__device__ float g_up[TOK*1024];
__device__ float g_xc[TOK*DI];
__device__ float g_q[TOK*DI];
__device__ float g_k[TOK*DI];
__device__ float g_v[TOK*DI];
__device__ float g_giT[BATCH*NH*SEQ];
__device__ float g_gfT[BATCH*NH*SEQ];
__device__ float g_Fc[BATCH*NH*SEQ];
__device__ float g_a[BATCH*NH*SEQ];
__device__ float g_m[BATCH*NH*SEQ];
__device__ float g_att[TOK*DI];

__device__ __nv_bfloat16 g_hn_bf[TOK*DMODEL];
__device__ __nv_bfloat16 g_xc_bf[TOK*DI];
__device__ __nv_bfloat16 g_up_bf[TOK*DI];
__device__ __nv_bfloat16 g_att2_bf[TOK*DI];
__device__ __nv_bfloat16 g_wup_bf[NL*DMODEL*1024];
__device__ __nv_bfloat16 g_wq_bf[NL*DI*DI];
__device__ __nv_bfloat16 g_wk_bf[NL*DI*DI];
__device__ __nv_bfloat16 g_wv_bf[NL*DI*DI];
__device__ __nv_bfloat16 g_wdn_bf[NL*DI*DMODEL];

__device__ __forceinline__ float warp_sum(float v){
    #pragma unroll
    for (int o=16;o;o>>=1) v += __shfl_xor_sync(0xffffffffu, v, o);
    return v;
}

__device__ __forceinline__ uint32_t f2tf(float x){
    uint32_t r; asm("cvt.rna.tf32.f32 %0, %1;" : "=r"(r) : "f"(x)); return r;
}

__device__ __forceinline__ void mma_tf32(float* c, const uint32_t* a, uint32_t b0, uint32_t b1){
    asm volatile(
      "mma.sync.aligned.m16n8k8.row.col.f32.tf32.tf32.f32 "
      "{%0,%1,%2,%3}, {%4,%5,%6,%7}, {%8,%9}, {%0,%1,%2,%3};\n"
      : "+f"(c[0]), "+f"(c[1]), "+f"(c[2]), "+f"(c[3])
      : "r"(a[0]), "r"(a[1]), "r"(a[2]), "r"(a[3]), "r"(b0), "r"(b1));
}

__device__ __forceinline__ uint32_t smaddr(const void* p){
    return (uint32_t)__cvta_generic_to_shared(p);
}
#define CPA16(dst,src) asm volatile("cp.async.cg.shared.global [%0], [%1], 16;\n"::"r"(dst),"l"(src))
#define CPCOMMIT() asm volatile("cp.async.commit_group;\n")
#define CPWAIT(n) asm volatile("cp.async.wait_group %0;\n"::"n"(n))

// ---------------- f32 -> bf16 convert ----------------
__global__ void f2bf_kernel(const float* __restrict__ in, __nv_bfloat16* __restrict__ out, int n){
    int i = (blockIdx.x*blockDim.x + threadIdx.x)*2;
    if (i < n){
        float2 v = *(const float2*)(in+i);
        *(__nv_bfloat162*)(out+i) = __floats2bfloat162_rn(v.x, v.y);
    }
}

// ---------------- embed: h = [x, tf] @ Wp + bp ----------------
__global__ void embed_kernel(const float* __restrict__ x, const float* __restrict__ tf,
                             const float* __restrict__ Wp, const float* __restrict__ bp,
                             float* __restrict__ h){
    int idx = blockIdx.x*blockDim.x + threadIdx.x;
    int j = idx & 255; int tok = idx >> 8;
    float acc = bp[j] + x[tok]*Wp[j];
    #pragma unroll
    for (int f=0; f<4; f++) acc += tf[tok*4+f]*Wp[(1+f)*256+j];
    h[idx] = acc;
}

// ---------------- layernorm over D=256, warp per row, bf16 out ----------------
__global__ void ln_kernel(const float* __restrict__ x, const float* __restrict__ g,
                          const float* __restrict__ b, __nv_bfloat16* __restrict__ y){
    int row = blockIdx.x*8 + (threadIdx.x>>5);
    int lane = threadIdx.x & 31;
    const float* xr = x + (size_t)row*256;
    float4 v0 = *(const float4*)(xr + lane*4);
    float4 v1 = *(const float4*)(xr + 128 + lane*4);
    float s = v0.x+v0.y+v0.z+v0.w + v1.x+v1.y+v1.z+v1.w;
    s = warp_sum(s);
    float mu = s * (1.f/256.f);
    float d0x=v0.x-mu, d0y=v0.y-mu, d0z=v0.z-mu, d0w=v0.w-mu;
    float d1x=v1.x-mu, d1y=v1.y-mu, d1z=v1.z-mu, d1w=v1.w-mu;
    float sq = d0x*d0x+d0y*d0y+d0z*d0z+d0w*d0w + d1x*d1x+d1y*d1y+d1z*d1z+d1w*d1w;
    sq = warp_sum(sq);
    float is = rsqrtf(sq*(1.f/256.f) + 1e-5f);
    float4 g0 = *(const float4*)(g + lane*4);
    float4 g1 = *(const float4*)(g + 128 + lane*4);
    float4 b0 = *(const float4*)(b + lane*4);
    float4 b1 = *(const float4*)(b + 128 + lane*4);
    __nv_bfloat16* yr = y + (size_t)row*256;
    float o0x = d0x*is*g0.x + b0.x, o0y = d0y*is*g0.y + b0.y;
    float o0z = d0z*is*g0.z + b0.z, o0w = d0w*is*g0.w + b0.w;
    float o1x = d1x*is*g1.x + b1.x, o1y = d1y*is*g1.y + b1.y;
    float o1z = d1z*is*g1.z + b1.z, o1w = d1w*is*g1.w + b1.w;
    *(__nv_bfloat162*)&yr[lane*4]     = __floats2bfloat162_rn(o0x, o0y);
    *(__nv_bfloat162*)&yr[lane*4+2]   = __floats2bfloat162_rn(o0z, o0w);
    *(__nv_bfloat162*)&yr[128+lane*4]   = __floats2bfloat162_rn(o1x, o1y);
    *(__nv_bfloat162*)&yr[128+lane*4+2] = __floats2bfloat162_rn(o1z, o1w);
}

// ---------------- bf16 tensor-core GEMM, cp.async double-buffered ----------------
// C[M,N] = A[M,K] @ B[K,N] + bias + resid.  CTA 128x64, K-chunk 64, 8 warps 4x2.
// smem: XOR swizzle on 16B chunks (chunk ^ (row&7)); ldmatrix conflict-free.
__global__ __launch_bounds__(256) void gemm_bf16(
    const __nv_bfloat16* __restrict__ A, int lda,
    const __nv_bfloat16* __restrict__ B, int ldb,
    float* __restrict__ C, int ldc,
    const float* __restrict__ bias,
    const float* __restrict__ resid,
    int K,
    __nv_bfloat16* __restrict__ Cbf, int bfcap)
{
    __shared__ __nv_bfloat16 As[2][128*64];
    __shared__ __nv_bfloat16 Bs[2][64*64];
    int tid = threadIdx.x, lane = tid&31, wid = tid>>5;
    int wm = wid>>1, wn = wid&1;
    int m0 = blockIdx.y*128, n0 = blockIdx.x*64;

    int ar = tid >> 1;                  // 0..127
    int ac0 = (tid & 1) << 2;           // chunk base (4 chunks each)
    int br = tid >> 2;                  // 0..63
    int bc0 = (tid & 3) << 1;           // chunk base (2 chunks each)
    const __nv_bfloat16* Ag = A + (size_t)(m0+ar)*lda;
    const __nv_bfloat16* Bg = B + (size_t)br*ldb + n0;

    int KC = K >> 6;
    {
        #pragma unroll
        for (int c=0;c<4;c++){
            int ch = ac0+c;
            CPA16(smaddr(&As[0][ar*64 + ((ch ^ (ar&7))<<3)]), Ag + (ch<<3));
        }
        #pragma unroll
        for (int c=0;c<2;c++){
            int ch = bc0+c;
            CPA16(smaddr(&Bs[0][br*64 + ((ch ^ (br&7))<<3)]), Bg + (ch<<3));
        }
        CPCOMMIT();
    }

    float acc[2][4][4] = {};
    int g = lane>>3, lr = lane&7;

    for (int kc=0; kc<KC; kc++){
        int cur = kc & 1;
        if (kc+1 < KC){
            int nb = (kc+1)&1, k0 = (kc+1)<<6;
            #pragma unroll
            for (int c=0;c<4;c++){
                int ch = ac0+c;
                CPA16(smaddr(&As[nb][ar*64 + ((ch ^ (ar&7))<<3)]), Ag + k0 + (ch<<3));
            }
            #pragma unroll
            for (int c=0;c<2;c++){
                int ch = bc0+c;
                CPA16(smaddr(&Bs[nb][br*64 + ((ch ^ (br&7))<<3)]), Bg + (size_t)k0*ldb + (ch<<3));
            }
            CPCOMMIT();
            CPWAIT(1);
        } else {
            CPWAIT(0);
        }
        __syncthreads();

        #pragma unroll
        for (int ks=0; ks<4; ks++){
            uint32_t af[2][4];
            #pragma unroll
            for (int mt=0; mt<2; mt++){
                int arow = wm*32 + mt*16 + lr + ((g&1)<<3);
                int ch = (ks<<1) + (g>>1);
                uint32_t addr = smaddr(&As[cur][arow*64 + ((ch ^ (arow&7))<<3)]);
                asm volatile("ldmatrix.sync.aligned.m8n8.x4.shared.b16 {%0,%1,%2,%3}, [%4];\n"
                    : "=r"(af[mt][0]),"=r"(af[mt][1]),"=r"(af[mt][2]),"=r"(af[mt][3]) : "r"(addr));
            }
            uint32_t bf[4][2];
            int krow = (ks<<4) + lr + ((g&1)<<3);   // lanes 0..15 meaningful for x2
            #pragma unroll
            for (int nt=0; nt<4; nt++){
                int ch = wn*4 + nt;
                uint32_t addr = smaddr(&Bs[cur][krow*64 + ((ch ^ (krow&7))<<3)]);
                asm volatile("ldmatrix.sync.aligned.m8n8.x2.trans.shared.b16 {%0,%1}, [%2];\n"
                    : "=r"(bf[nt][0]),"=r"(bf[nt][1]) : "r"(addr));
            }
            #pragma unroll
            for (int mt=0;mt<2;mt++)
              #pragma unroll
              for (int nt=0;nt<4;nt++)
                asm volatile("mma.sync.aligned.m16n8k16.row.col.f32.bf16.bf16.f32 "
                  "{%0,%1,%2,%3},{%4,%5,%6,%7},{%8,%9},{%0,%1,%2,%3};\n"
                  : "+f"(acc[mt][nt][0]),"+f"(acc[mt][nt][1]),
                    "+f"(acc[mt][nt][2]),"+f"(acc[mt][nt][3])
                  : "r"(af[mt][0]),"r"(af[mt][1]),"r"(af[mt][2]),"r"(af[mt][3]),
                    "r"(bf[nt][0]),"r"(bf[nt][1]));
        }
        __syncthreads();
    }

    #pragma unroll
    for (int mt=0;mt<2;mt++){
        #pragma unroll
        for (int nt=0;nt<4;nt++){
            int row0 = m0 + wm*32 + mt*16 + (lane>>2);
            int col  = n0 + wn*32 + nt*8 + ((lane&3)<<1);
            float bx=0.f, by=0.f;
            if (bias){ bx = bias[col]; by = bias[col+1]; }
            float2 r0v = make_float2(0.f,0.f), r1v = make_float2(0.f,0.f);
            if (resid){
                r0v = *(const float2*)&resid[(size_t)row0*ldc + col];
                r1v = *(const float2*)&resid[(size_t)(row0+8)*ldc + col];
            }
            float v00 = acc[mt][nt][0]+bx+r0v.x, v01 = acc[mt][nt][1]+by+r0v.y;
            float v10 = acc[mt][nt][2]+bx+r1v.x, v11 = acc[mt][nt][3]+by+r1v.y;
            *(float2*)&C[(size_t)row0*ldc + col]     = make_float2(v00, v01);
            *(float2*)&C[(size_t)(row0+8)*ldc + col] = make_float2(v10, v11);
            if (Cbf && col < bfcap){
                *(__nv_bfloat162*)&Cbf[(size_t)row0*bfcap + col]     = __floats2bfloat162_rn(v00, v01);
                *(__nv_bfloat162*)&Cbf[(size_t)(row0+8)*bfcap + col] = __floats2bfloat162_rn(v10, v11);
            }
        }
    }
}

// ---------------- causal depthwise conv (K=4) + silu; fp32 + bf16 out ----------------
__global__ void conv_silu_kernel(const float* __restrict__ up, const float* __restrict__ w,
                                 const float* __restrict__ cb, float* __restrict__ xc,
                                 __nv_bfloat16* __restrict__ xcbf){
    int idx = blockIdx.x*blockDim.x + threadIdx.x;    // TOK*512
    int c = idx & 511; int tok = idx >> 9; int t = tok & 1023;
    float acc = cb[c];
    #pragma unroll
    for (int j=0;j<4;j++){
        int ts = t - 3 + j;
        if (ts >= 0) acc += w[j*512+c] * up[(size_t)(tok-3+j)*1024 + c];
    }
    float sv = acc / (1.f + expf(-acc));
    xc[(size_t)tok*512 + c] = sv;
    xcbf[(size_t)tok*512 + c] = __float2bfloat16(sv);
}

// ---------------- gates = [q,k,v] @ Wif + bif, transposed output ----------------
__global__ void gates_kernel(const float* __restrict__ q, const float* __restrict__ k,
                             const float* __restrict__ v, const float* __restrict__ Wif,
                             const float* __restrict__ bif,
                             float* __restrict__ giT, float* __restrict__ gfT){
    __shared__ float gi[1536];
    int tok = blockIdx.x, tid = threadIdx.x;
    for (int i=tid;i<512;i+=256){
        gi[i]      = q[(size_t)tok*512+i];
        gi[512+i]  = k[(size_t)tok*512+i];
        gi[1024+i] = v[(size_t)tok*512+i];
    }
    __syncthreads();
    int w = tid>>5, lane = tid&31;
    float acc = 0.f;
    for (int i=lane;i<1536;i+=32) acc += gi[i]*Wif[i*8+w];
    acc = warp_sum(acc);
    if (!lane){
        float r = acc + bif[w];
        int b = tok >> 10, s = tok & 1023;
        if (w < 4) giT[(size_t)(b*4+w)*1024 + s] = r;
        else       gfT[(size_t)(b*4+w-4)*1024 + s] = r;
    }
}

// ---------------- gate scan: one block (warp) per (b,h), coalesced ----------------
__global__ void scan_kernel3(const float* __restrict__ giT, const float* __restrict__ gfT,
                             float* __restrict__ Fc, float* __restrict__ a, float* __restrict__ m){
    int bh = blockIdx.x, lane = threadIdx.x;
    const float* gih = giT + (size_t)bh*1024;
    const float* gfh = gfT + (size_t)bh*1024;
    float cfc = 0.f, cmax = -1e30f;
    float ipc = gih[lane], fpc = gfh[lane];
    for (int c=0;c<32;c++){
        float ip = ipc, fp = fpc;
        if (c+1 < 32){ ipc = gih[(c+1)*32+lane]; fpc = gfh[(c+1)*32+lane]; }
        float lf = fminf(fp, 0.f) - log1pf(expf(-fabsf(fp)));
        float x = lf;
        #pragma unroll
        for (int o=1;o<32;o<<=1){ float y = __shfl_up_sync(0xffffffffu, x, o); if (lane>=o) x += y; }
        float fc = cfc + x;
        float av = ip - fc;
        float mx = av;
        #pragma unroll
        for (int o=1;o<32;o<<=1){ float y = __shfl_up_sync(0xffffffffu, mx, o); if (lane>=o) mx = fmaxf(mx, y); }
        float cm = fmaxf(cmax, mx);
        int off = bh*SEQ + c*32 + lane;
        Fc[off] = fc; a[off] = av; m[off] = fc + cm;
        cfc += __shfl_sync(0xffffffffu, x, 31);
        cmax = fmaxf(cmax, __shfl_sync(0xffffffffu, mx, 31));
    }
}

// ---------------- mLSTM attention on tensor cores (tf32) ----------------
#define ATS 132
#define VTS 136
#define PTS 68
__global__ __launch_bounds__(256) void attn_mma(
    const float* __restrict__ q, const float* __restrict__ k, const float* __restrict__ v,
    const float* __restrict__ Fcv, const float* __restrict__ av, const float* __restrict__ mv,
    float* __restrict__ out)
{
    extern __shared__ uint32_t smu[];
    uint32_t* Qs = smu;
    uint32_t* Ks = Qs + 64*ATS;
    uint32_t* Vs = Ks + 64*ATS;
    float* fct  = (float*)(Vs + 64*VTS);
    float* mt   = fct + 64;
    float* as_  = mt + 64;
    float* den2 = as_ + 64;

    int bh = blockIdx.x; int b = bh>>2, hh = bh&3;
    int it = (int)(gridDim.y - 1) - (int)blockIdx.y;
    int t0 = it<<6;
    int tid = threadIdx.x, lane = tid&31, wid = tid>>5;
    int wm = wid>>1, wn = wid&1;
    int ls = lane>>2, lk = lane&3;
    const float scale = 0.08838834764831845f;

    const float* qg = q + ((size_t)(b*SEQ + t0))*512 + hh*128;
    #pragma unroll
    for (int r=0;r<8;r++){
        int idx = tid + (r<<8);
        int row = idx>>5, c4 = (idx&31)<<2;
        float4 vq = *(const float4*)(qg + (size_t)row*512 + c4);
        *(uint4*)&Qs[row*ATS + c4] = make_uint4(f2tf(vq.x), f2tf(vq.y), f2tf(vq.z), f2tf(vq.w));
    }
    if (tid < 64){ int tg = bh*SEQ + t0 + tid; fct[tid] = Fcv[tg]; mt[tid] = mv[tg]; }
    __syncthreads();

    uint32_t qf[16][4];
    int r0 = wm*16 + ls, r1 = r0 + 8;
    #pragma unroll
    for (int ks=0; ks<16; ks++){
        int kc = ks*8 + lk;
        qf[ks][0] = Qs[r0*ATS + kc];
        qf[ks][1] = Qs[r1*ATS + kc];
        qf[ks][2] = Qs[r0*ATS + kc + 4];
        qf[ks][3] = Qs[r1*ATS + kc + 4];
    }

    float oacc[8][4];
    #pragma unroll
    for (int i=0;i<8;i++){ oacc[i][0]=0.f; oacc[i][1]=0.f; oacc[i][2]=0.f; oacc[i][3]=0.f; }
    float den0 = 0.f, den1 = 0.f;

    for (int js=0; js<=it; js++){
        int s0 = js<<6;
        __syncthreads();
        const float* kg = k + ((size_t)(b*SEQ + s0))*512 + hh*128;
        const float* vg = v + ((size_t)(b*SEQ + s0))*512 + hh*128;
        #pragma unroll
        for (int r=0;r<8;r++){
            int idx = tid + (r<<8);
            int row = idx>>5, c4 = (idx&31)<<2;
            float4 kv = *(const float4*)(kg + (size_t)row*512 + c4);
            float4 vv = *(const float4*)(vg + (size_t)row*512 + c4);
            *(uint4*)&Ks[row*ATS + c4] = make_uint4(f2tf(kv.x), f2tf(kv.y), f2tf(kv.z), f2tf(kv.w));
            *(uint4*)&Vs[row*VTS + c4] = make_uint4(f2tf(vv.x), f2tf(vv.y), f2tf(vv.z), f2tf(vv.w));
        }
        if (tid < 64) as_[tid] = av[bh*SEQ + s0 + tid];
        __syncthreads();

        float sacc[4][4] = {};
        #pragma unroll
        for (int ks=0; ks<16; ks++){
            #pragma unroll
            for (int nt=0; nt<4; nt++){
                int sc = wn*32 + nt*8 + ls;
                uint32_t b0 = Ks[sc*ATS + ks*8 + lk];
                uint32_t b1 = Ks[sc*ATS + ks*8 + lk + 4];
                mma_tf32(sacc[nt], qf[ks], b0, b1);
            }
        }

        float f0 = fct[r0], mm0 = mt[r0], f1 = fct[r1], mm1 = mt[r1];
        bool diag = (js == it);
        #pragma unroll
        for (int nt=0; nt<4; nt++){
            int c0 = wn*32 + nt*8 + (lk<<1);
            int c1 = c0 + 1;
            float a0v = as_[c0], a1v = as_[c1];
            float v00 = sacc[nt][0]*scale*__expf(f0 + a0v - mm0);
            float v01 = sacc[nt][1]*scale*__expf(f0 + a1v - mm0);
            float v10 = sacc[nt][2]*scale*__expf(f1 + a0v - mm1);
            float v11 = sacc[nt][3]*scale*__expf(f1 + a1v - mm1);
            if (diag){
                if (c0 > r0) v00 = 0.f;
                if (c1 > r0) v01 = 0.f;
                if (c0 > r1) v10 = 0.f;
                if (c1 > r1) v11 = 0.f;
            }
            den0 += v00 + v01;
            den1 += v10 + v11;
            *(uint2*)&Qs[r0*PTS + c0] = make_uint2(f2tf(v00), f2tf(v01));
            *(uint2*)&Qs[r1*PTS + c0] = make_uint2(f2tf(v10), f2tf(v11));
        }
        __syncthreads();

        #pragma unroll
        for (int ks=0; ks<8; ks++){
            uint32_t af[4];
            af[0] = Qs[r0*PTS + ks*8 + lk];
            af[1] = Qs[r1*PTS + ks*8 + lk];
            af[2] = Qs[r0*PTS + ks*8 + lk + 4];
            af[3] = Qs[r1*PTS + ks*8 + lk + 4];
            #pragma unroll
            for (int nt=0; nt<8; nt++){
                int dc = wn*64 + nt*8 + ls;
                uint32_t b0 = Vs[(ks*8 + lk)*VTS + dc];
                uint32_t b1 = Vs[(ks*8 + lk + 4)*VTS + dc];
                mma_tf32(oacc[nt], af, b0, b1);
            }
        }
    }

    den0 += __shfl_xor_sync(0xffffffffu, den0, 1);
    den0 += __shfl_xor_sync(0xffffffffu, den0, 2);
    den1 += __shfl_xor_sync(0xffffffffu, den1, 1);
    den1 += __shfl_xor_sync(0xffffffffu, den1, 2);
    if (lk == 0){ den2[wn*64 + r0] = den0; den2[wn*64 + r1] = den1; }
    __syncthreads();
    float dt0 = den2[r0] + den2[64 + r0];
    float dt1 = den2[r1] + den2[64 + r1];
    float inv0 = 1.f / (fmaxf(fabsf(dt0), __expf(-mt[r0])) + 1e-6f);
    float inv1 = 1.f / (fmaxf(fabsf(dt1), __expf(-mt[r1])) + 1e-6f);

    float* og = out + ((size_t)(b*SEQ + t0))*512 + hh*128;
    #pragma unroll
    for (int nt=0; nt<8; nt++){
        int dc = wn*64 + nt*8 + (lk<<1);
        *(float2*)(og + (size_t)r0*512 + dc) = make_float2(oacc[nt][0]*inv0, oacc[nt][1]*inv0);
        *(float2*)(og + (size_t)r1*512 + dc) = make_float2(oacc[nt][2]*inv1, oacc[nt][3]*inv1);
    }
}

// ---------------- groupnorm + skip*xc + silu(z) gating; bf16 out ----------------
__global__ void gn_fuse_kernel(const float* __restrict__ att, const float* __restrict__ up,
                               const float* __restrict__ xc, const float* __restrict__ gng,
                               const float* __restrict__ gnb, const float* __restrict__ skip,
                               __nv_bfloat16* __restrict__ out){
    __shared__ float sh[4];
    __shared__ float s_mu, s_var;
    int tid = threadIdx.x;                 // 128
    int bsh = blockIdx.x; int hh = bsh & 3; int tok = bsh >> 2;
    int c = hh*128 + tid;
    float vv = att[(size_t)tok*512 + c];
    float s = warp_sum(vv);
    if ((tid&31)==0) sh[tid>>5] = s;
    __syncthreads();
    if (tid==0) s_mu = (sh[0]+sh[1]+sh[2]+sh[3])*(1.f/128.f);
    __syncthreads();
    float mu = s_mu;
    float d = vv - mu;
    float s2 = warp_sum(d*d);
    if ((tid&31)==0) sh[tid>>5] = s2;
    __syncthreads();
    if (tid==0) s_var = (sh[0]+sh[1]+sh[2]+sh[3])*(1.f/128.f);
    __syncthreads();
    float yn = d*rsqrtf(s_var + 1e-5f)*gng[c] + gnb[c];
    float val = yn + skip[c]*xc[(size_t)tok*512 + c];
    float z = up[(size_t)tok*1024 + 512 + c];
    val *= z / (1.f + expf(-z));
    out[(size_t)tok*512 + c] = __float2bfloat16(val);
}

// ---------------- final: LN(last token) @ Wf + bf ----------------
__global__ void final_kernel(const float* __restrict__ h, const float* __restrict__ g,
                             const float* __restrict__ b, const float* __restrict__ Wf,
                             const float* __restrict__ bf, float* __restrict__ out){
    __shared__ float sh[8];
    __shared__ float sv;
    int bb = blockIdx.x, tid = threadIdx.x;
    float vv = h[((size_t)(bb*SEQ + SEQ-1))*256 + tid];
    float s = warp_sum(vv);
    if (!(tid&31)) sh[tid>>5] = s;
    __syncthreads();
    if (tid==0){ float t=0; for(int i=0;i<8;i++) t+=sh[i]; sv = t*(1.f/256.f); }
    __syncthreads();
    float mu = sv;
    float d = vv - mu;
    float s2 = warp_sum(d*d);
    if (!(tid&31)) sh[tid>>5] = s2;
    __syncthreads();
    if (tid==0){ float t=0; for(int i=0;i<8;i++) t+=sh[i]; sv = t*(1.f/256.f); }
    __syncthreads();
    float yn = d*rsqrtf(sv + 1e-5f)*g[tid] + b[tid];
    float p = yn * Wf[tid];
    float s3 = warp_sum(p);
    __syncthreads();
    if (!(tid&31)) sh[tid>>5] = s3;
    __syncthreads();
    if (tid==0){ float t=0; for(int i=0;i<8;i++) t+=sh[i]; out[bb] = t + bf[0]; }
}

// ---------------- launch ----------------
extern "C" void kernel_launch(void* const* d_in, const int* in_sizes, int n_in,
                              void* d_out, int out_size){
    const float* x    = (const float*)d_in[0];
    const float* tf   = (const float*)d_in[1];
    const float* Wp   = (const float*)d_in[2];
    const float* bp   = (const float*)d_in[3];
    const float* ln_g = (const float*)d_in[4];
    const float* ln_b = (const float*)d_in[5];
    const float* Wup  = (const float*)d_in[6];
    const float* bup  = (const float*)d_in[7];
    const float* cw   = (const float*)d_in[8];
    const float* cb   = (const float*)d_in[9];
    const float* Wq   = (const float*)d_in[10];
    const float* Wk   = (const float*)d_in[11];
    const float* Wv   = (const float*)d_in[12];
    const float* Wif  = (const float*)d_in[13];
    const float* bif  = (const float*)d_in[14];
    const float* gng  = (const float*)d_in[15];
    const float* gnb  = (const float*)d_in[16];
    const float* skip = (const float*)d_in[17];
    const float* Wdn  = (const float*)d_in[18];
    const float* bdn  = (const float*)d_in[19];
    const float* lnfg = (const float*)d_in[20];
    const float* lnfb = (const float*)d_in[21];
    const float* Wf   = (const float*)d_in[22];
    const float* bf   = (const float*)d_in[23];

    float *h,*up,*xc,*q,*k,*v,*giT,*gfT,*Fc,*a,*m,*att;
    __nv_bfloat16 *hnbf,*xcbf,*upbf,*att2bf,*wupbf,*wqbf,*wkbf,*wvbf,*wdnbf;
    cudaGetSymbolAddress((void**)&h,    g_h);
    cudaGetSymbolAddress((void**)&up,   g_up);
    cudaGetSymbolAddress((void**)&xc,   g_xc);
    cudaGetSymbolAddress((void**)&q,    g_q);
    cudaGetSymbolAddress((void**)&k,    g_k);
    cudaGetSymbolAddress((void**)&v,    g_v);
    cudaGetSymbolAddress((void**)&giT,  g_giT);
    cudaGetSymbolAddress((void**)&gfT,  g_gfT);
    cudaGetSymbolAddress((void**)&Fc,   g_Fc);
    cudaGetSymbolAddress((void**)&a,    g_a);
    cudaGetSymbolAddress((void**)&m,    g_m);
    cudaGetSymbolAddress((void**)&att,  g_att);
    cudaGetSymbolAddress((void**)&hnbf, g_hn_bf);
    cudaGetSymbolAddress((void**)&xcbf, g_xc_bf);
    cudaGetSymbolAddress((void**)&upbf, g_up_bf);
    cudaGetSymbolAddress((void**)&att2bf, g_att2_bf);
    cudaGetSymbolAddress((void**)&wupbf, g_wup_bf);
    cudaGetSymbolAddress((void**)&wqbf,  g_wq_bf);
    cudaGetSymbolAddress((void**)&wkbf,  g_wk_bf);
    cudaGetSymbolAddress((void**)&wvbf,  g_wv_bf);
    cudaGetSymbolAddress((void**)&wdnbf, g_wdn_bf);

    int attn_smem = (64*ATS + 64*ATS + 64*VTS + 64 + 64 + 64 + 128) * 4;
    static int attr_set = 0;
    if (!attr_set){
        cudaFuncSetAttribute(attn_mma, cudaFuncAttributeMaxDynamicSharedMemorySize, attn_smem);
        attr_set = 1;
    }

    // weight conversion (once per call; graph-captured)
    f2bf_kernel<<<(NL*DMODEL*1024/2+255)/256, 256>>>(Wup, wupbf, NL*DMODEL*1024);
    f2bf_kernel<<<(NL*DI*DI/2+255)/256, 256>>>(Wq, wqbf, NL*DI*DI);
    f2bf_kernel<<<(NL*DI*DI/2+255)/256, 256>>>(Wk, wkbf, NL*DI*DI);
    f2bf_kernel<<<(NL*DI*DI/2+255)/256, 256>>>(Wv, wvbf, NL*DI*DI);
    f2bf_kernel<<<(NL*DI*DMODEL/2+255)/256, 256>>>(Wdn, wdnbf, NL*DI*DMODEL);

    embed_kernel<<<TOK*256/256, 256>>>(x, tf, Wp, bp, h);

    for (int l=0; l<NL; l++){
        ln_kernel<<<TOK/8, 256>>>(h, ln_g + l*256, ln_b + l*256, hnbf);
        gemm_bf16<<<dim3(1024/64, TOK/128), 256>>>(hnbf, 256, wupbf + (size_t)l*256*1024, 1024,
                                                   up, 1024, bup + l*1024, nullptr, 256,
                                                   upbf, 512);
        conv_silu_kernel<<<TOK*512/256, 256>>>(up, cw + l*4*512, cb + l*512, xc, xcbf);
        gemm_bf16<<<dim3(512/64, TOK/128), 256>>>(xcbf, 512, wqbf + (size_t)l*512*512, 512,
                                                  q, 512, nullptr, nullptr, 512, nullptr, 0);
        gemm_bf16<<<dim3(512/64, TOK/128), 256>>>(xcbf, 512, wkbf + (size_t)l*512*512, 512,
                                                  k, 512, nullptr, nullptr, 512, nullptr, 0);
        gemm_bf16<<<dim3(512/64, TOK/128), 256>>>(upbf, 512, wvbf + (size_t)l*512*512, 512,
                                                  v, 512, nullptr, nullptr, 512, nullptr, 0);
        gates_kernel<<<TOK, 256>>>(q, k, v, Wif + (size_t)l*1536*8, bif + l*8, giT, gfT);
        scan_kernel3<<<32, 32>>>(giT, gfT, Fc, a, m);
        attn_mma<<<dim3(BATCH*NH, SEQ/64), 256, attn_smem>>>(q, k, v, Fc, a, m, att);
        gn_fuse_kernel<<<TOK*NH, 128>>>(att, up, xc, gng + l*512, gnb + l*512, skip + l*512, att2bf);
        gemm_bf16<<<dim3(256/64, TOK/128), 256>>>(att2bf, 512, wdnbf + (size_t)l*512*256, 256,
                                                  h, 256, bdn + l*256, h, 512, nullptr, 0);
    }
    final_kernel<<<BATCH, 256>>>(h, lnfg, lnfb, Wf, bf, (float*)d_out);
}

// round 7
// speedup vs baseline: 4.6312x; 1.1395x over previous
#include <cuda_runtime.h>
#include <cuda_bf16.h>
#include <cstdint>
#include <cstddef>

#define SEQ 1024
#define BATCH 8
#define TOK (BATCH*SEQ)
#define DMODEL 256
#define DI 512
#define NH 4
#define DHH 128
#define NL 4

// ---------------- scratch (device globals; no allocation allowed) ----------------
__device__ float g_h[TOK*DMODEL];
__device__ float g_up[TOK*1024];
__device__ float g_xc[TOK*DI];
__device__ float g_q[TOK*DI];
__device__ float g_k[TOK*DI];
__device__ float g_v[TOK*DI];
__device__ float g_giT[BATCH*NH*SEQ];
__device__ float g_gfT[BATCH*NH*SEQ];
__device__ float g_Fc[BATCH*NH*SEQ];
__device__ float g_a[BATCH*NH*SEQ];
__device__ float g_m[BATCH*NH*SEQ];
__device__ float g_att[TOK*DI];

__device__ __nv_bfloat16 g_hn_bf[TOK*DMODEL];
__device__ __nv_bfloat16 g_xc_bf[TOK*DI];
__device__ __nv_bfloat16 g_up_bf[TOK*DI];
__device__ __nv_bfloat16 g_q_bf[TOK*DI];
__device__ __nv_bfloat16 g_k_bf[TOK*DI];
__device__ __nv_bfloat16 g_v_bf[TOK*DI];
__device__ __nv_bfloat16 g_att2_bf[TOK*DI];
__device__ __nv_bfloat16 g_wup_bf[NL*DMODEL*1024];
__device__ __nv_bfloat16 g_wq_bf[NL*DI*DI];
__device__ __nv_bfloat16 g_wk_bf[NL*DI*DI];
__device__ __nv_bfloat16 g_wv_bf[NL*DI*DI];
__device__ __nv_bfloat16 g_wdn_bf[NL*DI*DMODEL];

__device__ __forceinline__ float warp_sum(float v){
    #pragma unroll
    for (int o=16;o;o>>=1) v += __shfl_xor_sync(0xffffffffu, v, o);
    return v;
}

__device__ __forceinline__ uint32_t bf2pack(float x, float y){
    __nv_bfloat162 t = __floats2bfloat162_rn(x, y);
    return *(uint32_t*)&t;
}

__device__ __forceinline__ void mma_bf16(float* c, const uint32_t* a, uint32_t b0, uint32_t b1){
    asm volatile(
      "mma.sync.aligned.m16n8k16.row.col.f32.bf16.bf16.f32 "
      "{%0,%1,%2,%3}, {%4,%5,%6,%7}, {%8,%9}, {%0,%1,%2,%3};\n"
      : "+f"(c[0]), "+f"(c[1]), "+f"(c[2]), "+f"(c[3])
      : "r"(a[0]), "r"(a[1]), "r"(a[2]), "r"(a[3]), "r"(b0), "r"(b1));
}

__device__ __forceinline__ uint32_t smaddr(const void* p){
    return (uint32_t)__cvta_generic_to_shared(p);
}
#define CPA16(dst,src) asm volatile("cp.async.cg.shared.global [%0], [%1], 16;\n"::"r"(dst),"l"(src))
#define CPCOMMIT() asm volatile("cp.async.commit_group;\n")
#define CPWAIT(n) asm volatile("cp.async.wait_group %0;\n"::"n"(n))

// ---------------- f32 -> bf16 convert ----------------
__global__ void f2bf_kernel(const float* __restrict__ in, __nv_bfloat16* __restrict__ out, int n){
    int i = (blockIdx.x*blockDim.x + threadIdx.x)*2;
    if (i < n){
        float2 v = *(const float2*)(in+i);
        *(__nv_bfloat162*)(out+i) = __floats2bfloat162_rn(v.x, v.y);
    }
}

// ---------------- embed ----------------
__global__ void embed_kernel(const float* __restrict__ x, const float* __restrict__ tf,
                             const float* __restrict__ Wp, const float* __restrict__ bp,
                             float* __restrict__ h){
    int idx = blockIdx.x*blockDim.x + threadIdx.x;
    int j = idx & 255; int tok = idx >> 8;
    float acc = bp[j] + x[tok]*Wp[j];
    #pragma unroll
    for (int f=0; f<4; f++) acc += tf[tok*4+f]*Wp[(1+f)*256+j];
    h[idx] = acc;
}

// ---------------- layernorm, bf16 out ----------------
__global__ void ln_kernel(const float* __restrict__ x, const float* __restrict__ g,
                          const float* __restrict__ b, __nv_bfloat16* __restrict__ y){
    int row = blockIdx.x*8 + (threadIdx.x>>5);
    int lane = threadIdx.x & 31;
    const float* xr = x + (size_t)row*256;
    float4 v0 = *(const float4*)(xr + lane*4);
    float4 v1 = *(const float4*)(xr + 128 + lane*4);
    float s = v0.x+v0.y+v0.z+v0.w + v1.x+v1.y+v1.z+v1.w;
    s = warp_sum(s);
    float mu = s * (1.f/256.f);
    float d0x=v0.x-mu, d0y=v0.y-mu, d0z=v0.z-mu, d0w=v0.w-mu;
    float d1x=v1.x-mu, d1y=v1.y-mu, d1z=v1.z-mu, d1w=v1.w-mu;
    float sq = d0x*d0x+d0y*d0y+d0z*d0z+d0w*d0w + d1x*d1x+d1y*d1y+d1z*d1z+d1w*d1w;
    sq = warp_sum(sq);
    float is = rsqrtf(sq*(1.f/256.f) + 1e-5f);
    float4 g0 = *(const float4*)(g + lane*4);
    float4 g1 = *(const float4*)(g + 128 + lane*4);
    float4 b0 = *(const float4*)(b + lane*4);
    float4 b1 = *(const float4*)(b + 128 + lane*4);
    __nv_bfloat16* yr = y + (size_t)row*256;
    *(__nv_bfloat162*)&yr[lane*4]       = __floats2bfloat162_rn(d0x*is*g0.x + b0.x, d0y*is*g0.y + b0.y);
    *(__nv_bfloat162*)&yr[lane*4+2]     = __floats2bfloat162_rn(d0z*is*g0.z + b0.z, d0w*is*g0.w + b0.w);
    *(__nv_bfloat162*)&yr[128+lane*4]   = __floats2bfloat162_rn(d1x*is*g1.x + b1.x, d1y*is*g1.y + b1.y);
    *(__nv_bfloat162*)&yr[128+lane*4+2] = __floats2bfloat162_rn(d1z*is*g1.z + b1.z, d1w*is*g1.w + b1.w);
}

// ---------------- bf16 tensor-core GEMM, cp.async double-buffered ----------------
// blockIdx.z selects (B,C,Cbf) vs (B2,C2,Cbf2) for merged Q/K launches.
__global__ __launch_bounds__(256) void gemm_bf16(
    const __nv_bfloat16* __restrict__ A, int lda,
    const __nv_bfloat16* __restrict__ B, int ldb,
    float* __restrict__ C, int ldc,
    const float* __restrict__ bias,
    const float* __restrict__ resid,
    int K,
    __nv_bfloat16* __restrict__ Cbf, int bfcap,
    const __nv_bfloat16* __restrict__ B2,
    float* __restrict__ C2,
    __nv_bfloat16* __restrict__ Cbf2)
{
    __shared__ __nv_bfloat16 As[2][128*64];
    __shared__ __nv_bfloat16 Bs[2][64*64];
    if (blockIdx.z == 1){ B = B2; C = C2; Cbf = Cbf2; }
    int tid = threadIdx.x, lane = tid&31, wid = tid>>5;
    int wm = wid>>1, wn = wid&1;
    int m0 = blockIdx.y*128, n0 = blockIdx.x*64;

    int ar = tid >> 1;
    int ac0 = (tid & 1) << 2;
    int br = tid >> 2;
    int bc0 = (tid & 3) << 1;
    const __nv_bfloat16* Ag = A + (size_t)(m0+ar)*lda;
    const __nv_bfloat16* Bg = B + (size_t)br*ldb + n0;

    int KC = K >> 6;
    {
        #pragma unroll
        for (int c=0;c<4;c++){
            int ch = ac0+c;
            CPA16(smaddr(&As[0][ar*64 + ((ch ^ (ar&7))<<3)]), Ag + (ch<<3));
        }
        #pragma unroll
        for (int c=0;c<2;c++){
            int ch = bc0+c;
            CPA16(smaddr(&Bs[0][br*64 + ((ch ^ (br&7))<<3)]), Bg + (ch<<3));
        }
        CPCOMMIT();
    }

    float acc[2][4][4] = {};
    int g = lane>>3, lr = lane&7;

    for (int kc=0; kc<KC; kc++){
        int cur = kc & 1;
        if (kc+1 < KC){
            int nb = (kc+1)&1, k0 = (kc+1)<<6;
            #pragma unroll
            for (int c=0;c<4;c++){
                int ch = ac0+c;
                CPA16(smaddr(&As[nb][ar*64 + ((ch ^ (ar&7))<<3)]), Ag + k0 + (ch<<3));
            }
            #pragma unroll
            for (int c=0;c<2;c++){
                int ch = bc0+c;
                CPA16(smaddr(&Bs[nb][br*64 + ((ch ^ (br&7))<<3)]), Bg + (size_t)k0*ldb + (ch<<3));
            }
            CPCOMMIT();
            CPWAIT(1);
        } else {
            CPWAIT(0);
        }
        __syncthreads();

        #pragma unroll
        for (int ks=0; ks<4; ks++){
            uint32_t af[2][4];
            #pragma unroll
            for (int mt=0; mt<2; mt++){
                int arow = wm*32 + mt*16 + lr + ((g&1)<<3);
                int ch = (ks<<1) + (g>>1);
                uint32_t addr = smaddr(&As[cur][arow*64 + ((ch ^ (arow&7))<<3)]);
                asm volatile("ldmatrix.sync.aligned.m8n8.x4.shared.b16 {%0,%1,%2,%3}, [%4];\n"
                    : "=r"(af[mt][0]),"=r"(af[mt][1]),"=r"(af[mt][2]),"=r"(af[mt][3]) : "r"(addr));
            }
            uint32_t bf[4][2];
            int krow = (ks<<4) + lr + ((g&1)<<3);
            #pragma unroll
            for (int nt=0; nt<4; nt++){
                int ch = wn*4 + nt;
                uint32_t addr = smaddr(&Bs[cur][krow*64 + ((ch ^ (krow&7))<<3)]);
                asm volatile("ldmatrix.sync.aligned.m8n8.x2.trans.shared.b16 {%0,%1}, [%2];\n"
                    : "=r"(bf[nt][0]),"=r"(bf[nt][1]) : "r"(addr));
            }
            #pragma unroll
            for (int mt=0;mt<2;mt++)
              #pragma unroll
              for (int nt=0;nt<4;nt++)
                mma_bf16(acc[mt][nt], af[mt], bf[nt][0], bf[nt][1]);
        }
        __syncthreads();
    }

    #pragma unroll
    for (int mt=0;mt<2;mt++){
        #pragma unroll
        for (int nt=0;nt<4;nt++){
            int row0 = m0 + wm*32 + mt*16 + (lane>>2);
            int col  = n0 + wn*32 + nt*8 + ((lane&3)<<1);
            float bx=0.f, by=0.f;
            if (bias){ bx = bias[col]; by = bias[col+1]; }
            float2 r0v = make_float2(0.f,0.f), r1v = make_float2(0.f,0.f);
            if (resid){
                r0v = *(const float2*)&resid[(size_t)row0*ldc + col];
                r1v = *(const float2*)&resid[(size_t)(row0+8)*ldc + col];
            }
            float v00 = acc[mt][nt][0]+bx+r0v.x, v01 = acc[mt][nt][1]+by+r0v.y;
            float v10 = acc[mt][nt][2]+bx+r1v.x, v11 = acc[mt][nt][3]+by+r1v.y;
            *(float2*)&C[(size_t)row0*ldc + col]     = make_float2(v00, v01);
            *(float2*)&C[(size_t)(row0+8)*ldc + col] = make_float2(v10, v11);
            if (Cbf && col < bfcap){
                *(__nv_bfloat162*)&Cbf[(size_t)row0*bfcap + col]     = __floats2bfloat162_rn(v00, v01);
                *(__nv_bfloat162*)&Cbf[(size_t)(row0+8)*bfcap + col] = __floats2bfloat162_rn(v10, v11);
            }
        }
    }
}

// ---------------- causal depthwise conv (K=4) + silu ----------------
__global__ void conv_silu_kernel(const float* __restrict__ up, const float* __restrict__ w,
                                 const float* __restrict__ cb, float* __restrict__ xc,
                                 __nv_bfloat16* __restrict__ xcbf){
    int idx = blockIdx.x*blockDim.x + threadIdx.x;
    int c = idx & 511; int tok = idx >> 9; int t = tok & 1023;
    float acc = cb[c];
    #pragma unroll
    for (int j=0;j<4;j++){
        int ts = t - 3 + j;
        if (ts >= 0) acc += w[j*512+c] * up[(size_t)(tok-3+j)*1024 + c];
    }
    float sv = acc / (1.f + expf(-acc));
    xc[(size_t)tok*512 + c] = sv;
    xcbf[(size_t)tok*512 + c] = __float2bfloat16(sv);
}

// ---------------- gates, transposed output ----------------
__global__ void gates_kernel(const float* __restrict__ q, const float* __restrict__ k,
                             const float* __restrict__ v, const float* __restrict__ Wif,
                             const float* __restrict__ bif,
                             float* __restrict__ giT, float* __restrict__ gfT){
    __shared__ float gi[1536];
    int tok = blockIdx.x, tid = threadIdx.x;
    for (int i=tid;i<512;i+=256){
        gi[i]      = q[(size_t)tok*512+i];
        gi[512+i]  = k[(size_t)tok*512+i];
        gi[1024+i] = v[(size_t)tok*512+i];
    }
    __syncthreads();
    int w = tid>>5, lane = tid&31;
    float acc = 0.f;
    for (int i=lane;i<1536;i+=32) acc += gi[i]*Wif[i*8+w];
    acc = warp_sum(acc);
    if (!lane){
        float r = acc + bif[w];
        int b = tok >> 10, s = tok & 1023;
        if (w < 4) giT[(size_t)(b*4+w)*1024 + s] = r;
        else       gfT[(size_t)(b*4+w-4)*1024 + s] = r;
    }
}

// ---------------- gate scan ----------------
__global__ void scan_kernel3(const float* __restrict__ giT, const float* __restrict__ gfT,
                             float* __restrict__ Fc, float* __restrict__ a, float* __restrict__ m){
    int bh = blockIdx.x, lane = threadIdx.x;
    const float* gih = giT + (size_t)bh*1024;
    const float* gfh = gfT + (size_t)bh*1024;
    float cfc = 0.f, cmax = -1e30f;
    float ipc = gih[lane], fpc = gfh[lane];
    for (int c=0;c<32;c++){
        float ip = ipc, fp = fpc;
        if (c+1 < 32){ ipc = gih[(c+1)*32+lane]; fpc = gfh[(c+1)*32+lane]; }
        float lf = fminf(fp, 0.f) - log1pf(expf(-fabsf(fp)));
        float x = lf;
        #pragma unroll
        for (int o=1;o<32;o<<=1){ float y = __shfl_up_sync(0xffffffffu, x, o); if (lane>=o) x += y; }
        float fc = cfc + x;
        float av = ip - fc;
        float mx = av;
        #pragma unroll
        for (int o=1;o<32;o<<=1){ float y = __shfl_up_sync(0xffffffffu, mx, o); if (lane>=o) mx = fmaxf(mx, y); }
        float cm = fmaxf(cmax, mx);
        int off = bh*SEQ + c*32 + lane;
        Fc[off] = fc; a[off] = av; m[off] = fc + cm;
        cfc += __shfl_sync(0xffffffffu, x, 31);
        cmax = fmaxf(cmax, __shfl_sync(0xffffffffu, mx, 31));
    }
}

// ---------------- mLSTM attention on tensor cores (bf16 m16n8k16) ----------------
// Q/K smem: 68-word rows (packed bf16x2 words); fragment loads bank = 4*ls+lk (conflict-free).
// V smem: 64-word rows, XOR 16B-chunk swizzle, ldmatrix.x2.trans B-frags.
// P: stride-36-word region reusing Q smem; weighting/denominator fp32.
#define QKW 68
#define VW  64
#define PW  36
__global__ __launch_bounds__(256) void attn_bf16(
    const __nv_bfloat16* __restrict__ q, const __nv_bfloat16* __restrict__ k,
    const __nv_bfloat16* __restrict__ v,
    const float* __restrict__ Fcv, const float* __restrict__ av, const float* __restrict__ mv,
    float* __restrict__ out)
{
    extern __shared__ uint32_t smu[];
    uint32_t* Qs = smu;                  // 64*68 words; reused as P (64*36)
    uint32_t* Ks = Qs + 64*QKW;
    uint32_t* Vs = Ks + 64*QKW;          // 64*64 words
    float* fct  = (float*)(Vs + 64*VW);  // 64
    float* mt   = fct + 64;              // 64
    float* as_  = mt + 64;               // 64
    float* den2 = as_ + 64;              // 128

    int bh = blockIdx.x; int b = bh>>2, hh = bh&3;
    int it = (int)(gridDim.y - 1) - (int)blockIdx.y;
    int t0 = it<<6;
    int tid = threadIdx.x, lane = tid&31, wid = tid>>5;
    int wm = wid>>1, wn = wid&1;
    int ls = lane>>2, lk = lane&3;
    int g8 = lane>>3, lr = lane&7;
    const float scale = 0.08838834764831845f;

    // stage Q (64x128 bf16): row = idx>>4, 16B chunk = idx&15
    const __nv_bfloat16* qg = q + ((size_t)(b*SEQ + t0))*512 + hh*128;
    #pragma unroll
    for (int r=0;r<4;r++){
        int idx = tid + (r<<8);
        int row = idx>>4, c16 = idx&15;
        uint4 val = *(const uint4*)(qg + (size_t)row*512 + (c16<<3));
        *(uint4*)&Qs[row*QKW + (c16<<2)] = val;
    }
    if (tid < 64){ int tg = bh*SEQ + t0 + tid; fct[tid] = Fcv[tg]; mt[tid] = mv[tg]; }
    __syncthreads();

    // hoist Q A-fragments: 8 k16-steps x 4 regs
    uint32_t qf[8][4];
    int r0 = wm*16 + ls, r1 = r0 + 8;
    #pragma unroll
    for (int ks=0; ks<8; ks++){
        qf[ks][0] = Qs[r0*QKW + ks*8 + lk];
        qf[ks][1] = Qs[r1*QKW + ks*8 + lk];
        qf[ks][2] = Qs[r0*QKW + ks*8 + lk + 4];
        qf[ks][3] = Qs[r1*QKW + ks*8 + lk + 4];
    }

    float oacc[8][4];
    #pragma unroll
    for (int i=0;i<8;i++){ oacc[i][0]=0.f; oacc[i][1]=0.f; oacc[i][2]=0.f; oacc[i][3]=0.f; }
    float den0 = 0.f, den1 = 0.f;

    for (int js=0; js<=it; js++){
        int s0 = js<<6;
        __syncthreads();
        const __nv_bfloat16* kg = k + ((size_t)(b*SEQ + s0))*512 + hh*128;
        const __nv_bfloat16* vg = v + ((size_t)(b*SEQ + s0))*512 + hh*128;
        #pragma unroll
        for (int r=0;r<4;r++){
            int idx = tid + (r<<8);
            int row = idx>>4, c16 = idx&15;
            uint4 kv = *(const uint4*)(kg + (size_t)row*512 + (c16<<3));
            uint4 vv = *(const uint4*)(vg + (size_t)row*512 + (c16<<3));
            *(uint4*)&Ks[row*QKW + (c16<<2)] = kv;
            *(uint4*)&Vs[row*VW + ((c16 ^ (row&7))<<2)] = vv;
        }
        if (tid < 64) as_[tid] = av[bh*SEQ + s0 + tid];
        __syncthreads();

        // ---- S = Q @ K^T (64x64), 8 k16-steps ----
        float sacc[4][4] = {};
        #pragma unroll
        for (int ks=0; ks<8; ks++){
            #pragma unroll
            for (int nt=0; nt<4; nt++){
                int sc = wn*32 + nt*8 + ls;
                uint32_t b0 = Ks[sc*QKW + ks*8 + lk];
                uint32_t b1 = Ks[sc*QKW + ks*8 + lk + 4];
                mma_bf16(sacc[nt], qf[ks], b0, b1);
            }
        }

        // ---- weight, mask, denominator (fp32); write P packed bf16x2 ----
        float f0 = fct[r0], mm0 = mt[r0], f1 = fct[r1], mm1 = mt[r1];
        bool diag = (js == it);
        #pragma unroll
        for (int nt=0; nt<4; nt++){
            int c0 = wn*32 + nt*8 + (lk<<1);
            int c1 = c0 + 1;
            float a0v = as_[c0], a1v = as_[c1];
            float v00 = sacc[nt][0]*scale*__expf(f0 + a0v - mm0);
            float v01 = sacc[nt][1]*scale*__expf(f0 + a1v - mm0);
            float v10 = sacc[nt][2]*scale*__expf(f1 + a0v - mm1);
            float v11 = sacc[nt][3]*scale*__expf(f1 + a1v - mm1);
            if (diag){
                if (c0 > r0) v00 = 0.f;
                if (c1 > r0) v01 = 0.f;
                if (c0 > r1) v10 = 0.f;
                if (c1 > r1) v11 = 0.f;
            }
            den0 += v00 + v01;
            den1 += v10 + v11;
            int wcol = wn*16 + nt*4 + lk;
            Qs[r0*PW + wcol] = bf2pack(v00, v01);
            Qs[r1*PW + wcol] = bf2pack(v10, v11);
        }
        __syncthreads();

        // ---- out += P @ V (64x128, k=64 in 4 k16-steps) ----
        #pragma unroll
        for (int ks2=0; ks2<4; ks2++){
            uint32_t af[4];
            af[0] = Qs[r0*PW + ks2*8 + lk];
            af[1] = Qs[r1*PW + ks2*8 + lk];
            af[2] = Qs[r0*PW + ks2*8 + lk + 4];
            af[3] = Qs[r1*PW + ks2*8 + lk + 4];
            int krow = (ks2<<4) + lr + ((g8&1)<<3);
            #pragma unroll
            for (int nt=0; nt<8; nt++){
                int cd = wn*8 + nt;
                uint32_t addr = smaddr(&Vs[krow*VW + ((cd ^ (krow&7))<<2)]);
                uint32_t b0, b1;
                asm volatile("ldmatrix.sync.aligned.m8n8.x2.trans.shared.b16 {%0,%1}, [%2];\n"
                    : "=r"(b0),"=r"(b1) : "r"(addr));
                mma_bf16(oacc[nt], af, b0, b1);
            }
        }
    }

    den0 += __shfl_xor_sync(0xffffffffu, den0, 1);
    den0 += __shfl_xor_sync(0xffffffffu, den0, 2);
    den1 += __shfl_xor_sync(0xffffffffu, den1, 1);
    den1 += __shfl_xor_sync(0xffffffffu, den1, 2);
    if (lk == 0){ den2[wn*64 + r0] = den0; den2[wn*64 + r1] = den1; }
    __syncthreads();
    float dt0 = den2[r0] + den2[64 + r0];
    float dt1 = den2[r1] + den2[64 + r1];
    float inv0 = 1.f / (fmaxf(fabsf(dt0), __expf(-mt[r0])) + 1e-6f);
    float inv1 = 1.f / (fmaxf(fabsf(dt1), __expf(-mt[r1])) + 1e-6f);

    float* og = out + ((size_t)(b*SEQ + t0))*512 + hh*128;
    #pragma unroll
    for (int nt=0; nt<8; nt++){
        int dc = wn*64 + nt*8 + (lk<<1);
        *(float2*)(og + (size_t)r0*512 + dc) = make_float2(oacc[nt][0]*inv0, oacc[nt][1]*inv0);
        *(float2*)(og + (size_t)r1*512 + dc) = make_float2(oacc[nt][2]*inv1, oacc[nt][3]*inv1);
    }
}

// ---------------- groupnorm + skip*xc + silu(z); bf16 out ----------------
__global__ void gn_fuse_kernel(const float* __restrict__ att, const float* __restrict__ up,
                               const float* __restrict__ xc, const float* __restrict__ gng,
                               const float* __restrict__ gnb, const float* __restrict__ skip,
                               __nv_bfloat16* __restrict__ out){
    __shared__ float sh[4];
    __shared__ float s_mu, s_var;
    int tid = threadIdx.x;
    int bsh = blockIdx.x; int hh = bsh & 3; int tok = bsh >> 2;
    int c = hh*128 + tid;
    float vv = att[(size_t)tok*512 + c];
    float s = warp_sum(vv);
    if ((tid&31)==0) sh[tid>>5] = s;
    __syncthreads();
    if (tid==0) s_mu = (sh[0]+sh[1]+sh[2]+sh[3])*(1.f/128.f);
    __syncthreads();
    float mu = s_mu;
    float d = vv - mu;
    float s2 = warp_sum(d*d);
    if ((tid&31)==0) sh[tid>>5] = s2;
    __syncthreads();
    if (tid==0) s_var = (sh[0]+sh[1]+sh[2]+sh[3])*(1.f/128.f);
    __syncthreads();
    float yn = d*rsqrtf(s_var + 1e-5f)*gng[c] + gnb[c];
    float val = yn + skip[c]*xc[(size_t)tok*512 + c];
    float z = up[(size_t)tok*1024 + 512 + c];
    val *= z / (1.f + expf(-z));
    out[(size_t)tok*512 + c] = __float2bfloat16(val);
}

// ---------------- final ----------------
__global__ void final_kernel(const float* __restrict__ h, const float* __restrict__ g,
                             const float* __restrict__ b, const float* __restrict__ Wf,
                             const float* __restrict__ bf, float* __restrict__ out){
    __shared__ float sh[8];
    __shared__ float sv;
    int bb = blockIdx.x, tid = threadIdx.x;
    float vv = h[((size_t)(bb*SEQ + SEQ-1))*256 + tid];
    float s = warp_sum(vv);
    if (!(tid&31)) sh[tid>>5] = s;
    __syncthreads();
    if (tid==0){ float t=0; for(int i=0;i<8;i++) t+=sh[i]; sv = t*(1.f/256.f); }
    __syncthreads();
    float mu = sv;
    float d = vv - mu;
    float s2 = warp_sum(d*d);
    if (!(tid&31)) sh[tid>>5] = s2;
    __syncthreads();
    if (tid==0){ float t=0; for(int i=0;i<8;i++) t+=sh[i]; sv = t*(1.f/256.f); }
    __syncthreads();
    float yn = d*rsqrtf(sv + 1e-5f)*g[tid] + b[tid];
    float p = yn * Wf[tid];
    float s3 = warp_sum(p);
    __syncthreads();
    if (!(tid&31)) sh[tid>>5] = s3;
    __syncthreads();
    if (tid==0){ float t=0; for(int i=0;i<8;i++) t+=sh[i]; out[bb] = t + bf[0]; }
}

// ---------------- launch ----------------
extern "C" void kernel_launch(void* const* d_in, const int* in_sizes, int n_in,
                              void* d_out, int out_size){
    const float* x    = (const float*)d_in[0];
    const float* tf   = (const float*)d_in[1];
    const float* Wp   = (const float*)d_in[2];
    const float* bp   = (const float*)d_in[3];
    const float* ln_g = (const float*)d_in[4];
    const float* ln_b = (const float*)d_in[5];
    const float* Wup  = (const float*)d_in[6];
    const float* bup  = (const float*)d_in[7];
    const float* cw   = (const float*)d_in[8];
    const float* cb   = (const float*)d_in[9];
    const float* Wq   = (const float*)d_in[10];
    const float* Wk   = (const float*)d_in[11];
    const float* Wv   = (const float*)d_in[12];
    const float* Wif  = (const float*)d_in[13];
    const float* bif  = (const float*)d_in[14];
    const float* gng  = (const float*)d_in[15];
    const float* gnb  = (const float*)d_in[16];
    const float* skip = (const float*)d_in[17];
    const float* Wdn  = (const float*)d_in[18];
    const float* bdn  = (const float*)d_in[19];
    const float* lnfg = (const float*)d_in[20];
    const float* lnfb = (const float*)d_in[21];
    const float* Wf   = (const float*)d_in[22];
    const float* bf   = (const float*)d_in[23];

    float *h,*up,*xc,*q,*k,*v,*giT,*gfT,*Fc,*a,*m,*att;
    __nv_bfloat16 *hnbf,*xcbf,*upbf,*qbf,*kbf,*vbf,*att2bf,*wupbf,*wqbf,*wkbf,*wvbf,*wdnbf;
    cudaGetSymbolAddress((void**)&h,    g_h);
    cudaGetSymbolAddress((void**)&up,   g_up);
    cudaGetSymbolAddress((void**)&xc,   g_xc);
    cudaGetSymbolAddress((void**)&q,    g_q);
    cudaGetSymbolAddress((void**)&k,    g_k);
    cudaGetSymbolAddress((void**)&v,    g_v);
    cudaGetSymbolAddress((void**)&giT,  g_giT);
    cudaGetSymbolAddress((void**)&gfT,  g_gfT);
    cudaGetSymbolAddress((void**)&Fc,   g_Fc);
    cudaGetSymbolAddress((void**)&a,    g_a);
    cudaGetSymbolAddress((void**)&m,    g_m);
    cudaGetSymbolAddress((void**)&att,  g_att);
    cudaGetSymbolAddress((void**)&hnbf, g_hn_bf);
    cudaGetSymbolAddress((void**)&xcbf, g_xc_bf);
    cudaGetSymbolAddress((void**)&upbf, g_up_bf);
    cudaGetSymbolAddress((void**)&qbf,  g_q_bf);
    cudaGetSymbolAddress((void**)&kbf,  g_k_bf);
    cudaGetSymbolAddress((void**)&vbf,  g_v_bf);
    cudaGetSymbolAddress((void**)&att2bf, g_att2_bf);
    cudaGetSymbolAddress((void**)&wupbf, g_wup_bf);
    cudaGetSymbolAddress((void**)&wqbf,  g_wq_bf);
    cudaGetSymbolAddress((void**)&wkbf,  g_wk_bf);
    cudaGetSymbolAddress((void**)&wvbf,  g_wv_bf);
    cudaGetSymbolAddress((void**)&wdnbf, g_wdn_bf);

    int attn_smem = (64*QKW + 64*QKW + 64*VW + 64 + 64 + 64 + 128) * 4;
    static int attr_set = 0;
    if (!attr_set){
        cudaFuncSetAttribute(attn_bf16, cudaFuncAttributeMaxDynamicSharedMemorySize, attn_smem);
        attr_set = 1;
    }

    f2bf_kernel<<<(NL*DMODEL*1024/2+255)/256, 256>>>(Wup, wupbf, NL*DMODEL*1024);
    f2bf_kernel<<<(NL*DI*DI/2+255)/256, 256>>>(Wq, wqbf, NL*DI*DI);
    f2bf_kernel<<<(NL*DI*DI/2+255)/256, 256>>>(Wk, wkbf, NL*DI*DI);
    f2bf_kernel<<<(NL*DI*DI/2+255)/256, 256>>>(Wv, wvbf, NL*DI*DI);
    f2bf_kernel<<<(NL*DI*DMODEL/2+255)/256, 256>>>(Wdn, wdnbf, NL*DI*DMODEL);

    embed_kernel<<<TOK*256/256, 256>>>(x, tf, Wp, bp, h);

    for (int l=0; l<NL; l++){
        ln_kernel<<<TOK/8, 256>>>(h, ln_g + l*256, ln_b + l*256, hnbf);
        gemm_bf16<<<dim3(1024/64, TOK/128, 1), 256>>>(hnbf, 256, wupbf + (size_t)l*256*1024, 1024,
                                                   up, 1024, bup + l*1024, nullptr, 256,
                                                   upbf, 512, nullptr, nullptr, nullptr);
        conv_silu_kernel<<<TOK*512/256, 256>>>(up, cw + l*4*512, cb + l*512, xc, xcbf);
        // merged Q (z=0) and K (z=1) projections
        gemm_bf16<<<dim3(512/64, TOK/128, 2), 256>>>(xcbf, 512, wqbf + (size_t)l*512*512, 512,
                                                  q, 512, nullptr, nullptr, 512, qbf, 512,
                                                  wkbf + (size_t)l*512*512, k, kbf);
        gemm_bf16<<<dim3(512/64, TOK/128, 1), 256>>>(upbf, 512, wvbf + (size_t)l*512*512, 512,
                                                  v, 512, nullptr, nullptr, 512, vbf, 512,
                                                  nullptr, nullptr, nullptr);
        gates_kernel<<<TOK, 256>>>(q, k, v, Wif + (size_t)l*1536*8, bif + l*8, giT, gfT);
        scan_kernel3<<<32, 32>>>(giT, gfT, Fc, a, m);
        attn_bf16<<<dim3(BATCH*NH, SEQ/64), 256, attn_smem>>>(qbf, kbf, vbf, Fc, a, m, att);
        gn_fuse_kernel<<<TOK*NH, 128>>>(att, up, xc, gng + l*512, gnb + l*512, skip + l*512, att2bf);
        gemm_bf16<<<dim3(256/64, TOK/128, 1), 256>>>(att2bf, 512, wdnbf + (size_t)l*512*256, 256,
                                                  h, 256, bdn + l*256, h, 512,
                                                  nullptr, 0, nullptr, nullptr, nullptr);
    }
    final_kernel<<<BATCH, 256>>>(h, lnfg, lnfb, Wf, bf, (float*)d_out);
}

// round 8
// speedup vs baseline: 5.3559x; 1.1565x over previous
#include <cuda_runtime.h>
#include <cuda_bf16.h>
#include <cstdint>
#include <cstddef>

#define SEQ 1024
#define BATCH 8
#define TOK (BATCH*SEQ)
#define DMODEL 256
#define DI 512
#define NH 4
#define DHH 128
#define NL 4

// ---------------- scratch (device globals; no allocation allowed) ----------------
__device__ float g_h[TOK*DMODEL];
__device__ float g_up[TOK*1024];
__device__ float g_xc[TOK*DI];
__device__ float g_giT[BATCH*NH*SEQ];
__device__ float g_gfT[BATCH*NH*SEQ];
__device__ float g_Fc[BATCH*NH*SEQ];
__device__ float g_a[BATCH*NH*SEQ];
__device__ float g_m[BATCH*NH*SEQ];
__device__ float g_Wg[NL*1024*8];

__device__ __nv_bfloat16 g_hn_bf[TOK*DMODEL];
__device__ __nv_bfloat16 g_xc_bf[TOK*DI];
__device__ __nv_bfloat16 g_up_bf[TOK*DI];
__device__ __nv_bfloat16 g_q_bf[TOK*DI];
__device__ __nv_bfloat16 g_k_bf[TOK*DI];
__device__ __nv_bfloat16 g_v_bf[TOK*DI];
__device__ __nv_bfloat16 g_att2_bf[TOK*DI];
__device__ __nv_bfloat16 g_wup_bf[NL*DMODEL*1024];
__device__ __nv_bfloat16 g_wq_bf[NL*DI*DI];
__device__ __nv_bfloat16 g_wk_bf[NL*DI*DI];
__device__ __nv_bfloat16 g_wv_bf[NL*DI*DI];
__device__ __nv_bfloat16 g_wdn_bf[NL*DI*DMODEL];

__device__ __forceinline__ float warp_sum(float v){
    #pragma unroll
    for (int o=16;o;o>>=1) v += __shfl_xor_sync(0xffffffffu, v, o);
    return v;
}

__device__ __forceinline__ uint32_t bf2pack(float x, float y){
    __nv_bfloat162 t = __floats2bfloat162_rn(x, y);
    return *(uint32_t*)&t;
}

__device__ __forceinline__ void mma_bf16(float* c, const uint32_t* a, uint32_t b0, uint32_t b1){
    asm volatile(
      "mma.sync.aligned.m16n8k16.row.col.f32.bf16.bf16.f32 "
      "{%0,%1,%2,%3}, {%4,%5,%6,%7}, {%8,%9}, {%0,%1,%2,%3};\n"
      : "+f"(c[0]), "+f"(c[1]), "+f"(c[2]), "+f"(c[3])
      : "r"(a[0]), "r"(a[1]), "r"(a[2]), "r"(a[3]), "r"(b0), "r"(b1));
}

__device__ __forceinline__ uint32_t smaddr(const void* p){
    return (uint32_t)__cvta_generic_to_shared(p);
}
#define CPA16(dst,src) asm volatile("cp.async.cg.shared.global [%0], [%1], 16;\n"::"r"(dst),"l"(src))
#define CPCOMMIT() asm volatile("cp.async.commit_group;\n")
#define CPWAIT(n) asm volatile("cp.async.wait_group %0;\n"::"n"(n))

// ---------------- f32 -> bf16 convert ----------------
__global__ void f2bf_kernel(const float* __restrict__ in, __nv_bfloat16* __restrict__ out, int n){
    int i = (blockIdx.x*blockDim.x + threadIdx.x)*2;
    if (i < n){
        float2 v = *(const float2*)(in+i);
        *(__nv_bfloat162*)(out+i) = __floats2bfloat162_rn(v.x, v.y);
    }
}

// ---------------- composite gate weights: Wg = [Wq@Wif_i + Wk@Wif_k ; Wv@Wif_v] ----------------
__global__ void gatew_kernel(const float* __restrict__ Wq, const float* __restrict__ Wk,
                             const float* __restrict__ Wv, const float* __restrict__ Wif,
                             float* __restrict__ Wg){
    int idx = blockIdx.x*blockDim.x + threadIdx.x;   // NL*1024*8
    int l = idx >> 13; int r = idx & 8191;
    int c = r >> 3; int j = r & 7;
    const float* Wifl = Wif + (size_t)l*1536*8;
    float acc = 0.f;
    if (c < 512){
        const float* wq = Wq + ((size_t)l*512 + c)*512;
        const float* wk = Wk + ((size_t)l*512 + c)*512;
        #pragma unroll 4
        for (int i=0;i<512;i++)
            acc += wq[i]*Wifl[i*8+j] + wk[i]*Wifl[(512+i)*8+j];
    } else {
        const float* wv = Wv + ((size_t)l*512 + (c-512))*512;
        #pragma unroll 4
        for (int i=0;i<512;i++)
            acc += wv[i]*Wifl[(1024+i)*8+j];
    }
    Wg[(size_t)l*8192 + c*8 + j] = acc;
}

// ---------------- embed ----------------
__global__ void embed_kernel(const float* __restrict__ x, const float* __restrict__ tf,
                             const float* __restrict__ Wp, const float* __restrict__ bp,
                             float* __restrict__ h){
    int idx = blockIdx.x*blockDim.x + threadIdx.x;
    int j = idx & 255; int tok = idx >> 8;
    float acc = bp[j] + x[tok]*Wp[j];
    #pragma unroll
    for (int f=0; f<4; f++) acc += tf[tok*4+f]*Wp[(1+f)*256+j];
    h[idx] = acc;
}

// ---------------- layernorm, bf16 out ----------------
__global__ void ln_kernel(const float* __restrict__ x, const float* __restrict__ g,
                          const float* __restrict__ b, __nv_bfloat16* __restrict__ y){
    int row = blockIdx.x*8 + (threadIdx.x>>5);
    int lane = threadIdx.x & 31;
    const float* xr = x + (size_t)row*256;
    float4 v0 = *(const float4*)(xr + lane*4);
    float4 v1 = *(const float4*)(xr + 128 + lane*4);
    float s = v0.x+v0.y+v0.z+v0.w + v1.x+v1.y+v1.z+v1.w;
    s = warp_sum(s);
    float mu = s * (1.f/256.f);
    float d0x=v0.x-mu, d0y=v0.y-mu, d0z=v0.z-mu, d0w=v0.w-mu;
    float d1x=v1.x-mu, d1y=v1.y-mu, d1z=v1.z-mu, d1w=v1.w-mu;
    float sq = d0x*d0x+d0y*d0y+d0z*d0z+d0w*d0w + d1x*d1x+d1y*d1y+d1z*d1z+d1w*d1w;
    sq = warp_sum(sq);
    float is = rsqrtf(sq*(1.f/256.f) + 1e-5f);
    float4 g0 = *(const float4*)(g + lane*4);
    float4 g1 = *(const float4*)(g + 128 + lane*4);
    float4 b0 = *(const float4*)(b + lane*4);
    float4 b1 = *(const float4*)(b + 128 + lane*4);
    __nv_bfloat16* yr = y + (size_t)row*256;
    *(__nv_bfloat162*)&yr[lane*4]       = __floats2bfloat162_rn(d0x*is*g0.x + b0.x, d0y*is*g0.y + b0.y);
    *(__nv_bfloat162*)&yr[lane*4+2]     = __floats2bfloat162_rn(d0z*is*g0.z + b0.z, d0w*is*g0.w + b0.w);
    *(__nv_bfloat162*)&yr[128+lane*4]   = __floats2bfloat162_rn(d1x*is*g1.x + b1.x, d1y*is*g1.y + b1.y);
    *(__nv_bfloat162*)&yr[128+lane*4+2] = __floats2bfloat162_rn(d1z*is*g1.z + b1.z, d1w*is*g1.w + b1.w);
}

// ---------------- bf16 tensor-core GEMM, cp.async double-buffered ----------------
// z=0: (A,B,Cbf); z=1: (A,B2,Cbf2); z=2: (A2,B3,Cbf3). C fp32 optional (nullptr skips).
__global__ __launch_bounds__(256) void gemm_bf16(
    const __nv_bfloat16* __restrict__ A, int lda,
    const __nv_bfloat16* __restrict__ B, int ldb,
    float* __restrict__ C, int ldc,
    const float* __restrict__ bias,
    const float* __restrict__ resid,
    int K,
    __nv_bfloat16* __restrict__ Cbf, int bfcap,
    const __nv_bfloat16* __restrict__ A2,
    const __nv_bfloat16* __restrict__ B2,
    __nv_bfloat16* __restrict__ Cbf2,
    const __nv_bfloat16* __restrict__ B3,
    __nv_bfloat16* __restrict__ Cbf3)
{
    __shared__ __nv_bfloat16 As[2][128*64];
    __shared__ __nv_bfloat16 Bs[2][64*64];
    if (blockIdx.z == 1){ B = B2; Cbf = Cbf2; }
    else if (blockIdx.z == 2){ A = A2; B = B3; Cbf = Cbf3; }
    int tid = threadIdx.x, lane = tid&31, wid = tid>>5;
    int wm = wid>>1, wn = wid&1;
    int m0 = blockIdx.y*128, n0 = blockIdx.x*64;

    int ar = tid >> 1;
    int ac0 = (tid & 1) << 2;
    int br = tid >> 2;
    int bc0 = (tid & 3) << 1;
    const __nv_bfloat16* Ag = A + (size_t)(m0+ar)*lda;
    const __nv_bfloat16* Bg = B + (size_t)br*ldb + n0;

    int KC = K >> 6;
    {
        #pragma unroll
        for (int c=0;c<4;c++){
            int ch = ac0+c;
            CPA16(smaddr(&As[0][ar*64 + ((ch ^ (ar&7))<<3)]), Ag + (ch<<3));
        }
        #pragma unroll
        for (int c=0;c<2;c++){
            int ch = bc0+c;
            CPA16(smaddr(&Bs[0][br*64 + ((ch ^ (br&7))<<3)]), Bg + (ch<<3));
        }
        CPCOMMIT();
    }

    float acc[2][4][4] = {};
    int g = lane>>3, lr = lane&7;

    for (int kc=0; kc<KC; kc++){
        int cur = kc & 1;
        if (kc+1 < KC){
            int nb = (kc+1)&1, k0 = (kc+1)<<6;
            #pragma unroll
            for (int c=0;c<4;c++){
                int ch = ac0+c;
                CPA16(smaddr(&As[nb][ar*64 + ((ch ^ (ar&7))<<3)]), Ag + k0 + (ch<<3));
            }
            #pragma unroll
            for (int c=0;c<2;c++){
                int ch = bc0+c;
                CPA16(smaddr(&Bs[nb][br*64 + ((ch ^ (br&7))<<3)]), Bg + (size_t)k0*ldb + (ch<<3));
            }
            CPCOMMIT();
            CPWAIT(1);
        } else {
            CPWAIT(0);
        }
        __syncthreads();

        #pragma unroll
        for (int ks=0; ks<4; ks++){
            uint32_t af[2][4];
            #pragma unroll
            for (int mt=0; mt<2; mt++){
                int arow = wm*32 + mt*16 + lr + ((g&1)<<3);
                int ch = (ks<<1) + (g>>1);
                uint32_t addr = smaddr(&As[cur][arow*64 + ((ch ^ (arow&7))<<3)]);
                asm volatile("ldmatrix.sync.aligned.m8n8.x4.shared.b16 {%0,%1,%2,%3}, [%4];\n"
                    : "=r"(af[mt][0]),"=r"(af[mt][1]),"=r"(af[mt][2]),"=r"(af[mt][3]) : "r"(addr));
            }
            uint32_t bf[4][2];
            int krow = (ks<<4) + lr + ((g&1)<<3);
            #pragma unroll
            for (int nt=0; nt<4; nt++){
                int ch = wn*4 + nt;
                uint32_t addr = smaddr(&Bs[cur][krow*64 + ((ch ^ (krow&7))<<3)]);
                asm volatile("ldmatrix.sync.aligned.m8n8.x2.trans.shared.b16 {%0,%1}, [%2];\n"
                    : "=r"(bf[nt][0]),"=r"(bf[nt][1]) : "r"(addr));
            }
            #pragma unroll
            for (int mt=0;mt<2;mt++)
              #pragma unroll
              for (int nt=0;nt<4;nt++)
                mma_bf16(acc[mt][nt], af[mt], bf[nt][0], bf[nt][1]);
        }
        __syncthreads();
    }

    #pragma unroll
    for (int mt=0;mt<2;mt++){
        #pragma unroll
        for (int nt=0;nt<4;nt++){
            int row0 = m0 + wm*32 + mt*16 + (lane>>2);
            int col  = n0 + wn*32 + nt*8 + ((lane&3)<<1);
            float bx=0.f, by=0.f;
            if (bias){ bx = bias[col]; by = bias[col+1]; }
            float2 r0v = make_float2(0.f,0.f), r1v = make_float2(0.f,0.f);
            if (resid){
                r0v = *(const float2*)&resid[(size_t)row0*ldc + col];
                r1v = *(const float2*)&resid[(size_t)(row0+8)*ldc + col];
            }
            float v00 = acc[mt][nt][0]+bx+r0v.x, v01 = acc[mt][nt][1]+by+r0v.y;
            float v10 = acc[mt][nt][2]+bx+r1v.x, v11 = acc[mt][nt][3]+by+r1v.y;
            if (C){
                *(float2*)&C[(size_t)row0*ldc + col]     = make_float2(v00, v01);
                *(float2*)&C[(size_t)(row0+8)*ldc + col] = make_float2(v10, v11);
            }
            if (Cbf && col < bfcap){
                *(__nv_bfloat162*)&Cbf[(size_t)row0*bfcap + col]     = __floats2bfloat162_rn(v00, v01);
                *(__nv_bfloat162*)&Cbf[(size_t)(row0+8)*bfcap + col] = __floats2bfloat162_rn(v10, v11);
            }
        }
    }
}

// ---------------- causal depthwise conv (K=4) + silu ----------------
__global__ void conv_silu_kernel(const float* __restrict__ up, const float* __restrict__ w,
                                 const float* __restrict__ cb, float* __restrict__ xc,
                                 __nv_bfloat16* __restrict__ xcbf){
    int idx = blockIdx.x*blockDim.x + threadIdx.x;
    int c = idx & 511; int tok = idx >> 9; int t = tok & 1023;
    float acc = cb[c];
    #pragma unroll
    for (int j=0;j<4;j++){
        int ts = t - 3 + j;
        if (ts >= 0) acc += w[j*512+c] * up[(size_t)(tok-3+j)*1024 + c];
    }
    float sv = acc / (1.f + expf(-acc));
    xc[(size_t)tok*512 + c] = sv;
    xcbf[(size_t)tok*512 + c] = __float2bfloat16(sv);
}

// ---------------- gates from composite weights: gates = [xc|xm] @ Wg + bif ----------------
__global__ void gates2_kernel(const float* __restrict__ xc, const float* __restrict__ up,
                              const float* __restrict__ Wg, const float* __restrict__ bif,
                              float* __restrict__ giT, float* __restrict__ gfT){
    __shared__ float xrow[1024];
    int tok = blockIdx.x, tid = threadIdx.x;
    for (int i=tid;i<512;i+=256){
        xrow[i]     = xc[(size_t)tok*512+i];
        xrow[512+i] = up[(size_t)tok*1024+i];
    }
    __syncthreads();
    int w = tid>>5, lane = tid&31;
    float acc = 0.f;
    for (int i=lane;i<1024;i+=32) acc += xrow[i]*Wg[i*8+w];
    acc = warp_sum(acc);
    if (!lane){
        float r = acc + bif[w];
        int b = tok >> 10, s = tok & 1023;
        if (w < 4) giT[(size_t)(b*4+w)*1024 + s] = r;
        else       gfT[(size_t)(b*4+w-4)*1024 + s] = r;
    }
}

// ---------------- gate scan ----------------
__global__ void scan_kernel3(const float* __restrict__ giT, const float* __restrict__ gfT,
                             float* __restrict__ Fc, float* __restrict__ a, float* __restrict__ m){
    int bh = blockIdx.x, lane = threadIdx.x;
    const float* gih = giT + (size_t)bh*1024;
    const float* gfh = gfT + (size_t)bh*1024;
    float cfc = 0.f, cmax = -1e30f;
    float ipc = gih[lane], fpc = gfh[lane];
    for (int c=0;c<32;c++){
        float ip = ipc, fp = fpc;
        if (c+1 < 32){ ipc = gih[(c+1)*32+lane]; fpc = gfh[(c+1)*32+lane]; }
        float lf = fminf(fp, 0.f) - log1pf(expf(-fabsf(fp)));
        float x = lf;
        #pragma unroll
        for (int o=1;o<32;o<<=1){ float y = __shfl_up_sync(0xffffffffu, x, o); if (lane>=o) x += y; }
        float fc = cfc + x;
        float av = ip - fc;
        float mx = av;
        #pragma unroll
        for (int o=1;o<32;o<<=1){ float y = __shfl_up_sync(0xffffffffu, mx, o); if (lane>=o) mx = fmaxf(mx, y); }
        float cm = fmaxf(cmax, mx);
        int off = bh*SEQ + c*32 + lane;
        Fc[off] = fc; a[off] = av; m[off] = fc + cm;
        cfc += __shfl_sync(0xffffffffu, x, 31);
        cmax = fmaxf(cmax, __shfl_sync(0xffffffffu, mx, 31));
    }
}

// ---------------- mLSTM attention + fused GN/skip/silu-gate epilogue ----------------
#define QKW 68
#define VW  64
#define PW  36
__global__ __launch_bounds__(256) void attn_bf16(
    const __nv_bfloat16* __restrict__ q, const __nv_bfloat16* __restrict__ k,
    const __nv_bfloat16* __restrict__ v,
    const float* __restrict__ Fcv, const float* __restrict__ av, const float* __restrict__ mv,
    const float* __restrict__ xc, const float* __restrict__ up,
    const float* __restrict__ gng, const float* __restrict__ gnb,
    const float* __restrict__ skip,
    __nv_bfloat16* __restrict__ out)
{
    extern __shared__ uint32_t smu[];
    uint32_t* Qs = smu;                  // 64*68 words; reused as P (64*36)
    uint32_t* Ks = Qs + 64*QKW;
    uint32_t* Vs = Ks + 64*QKW;          // 64*64 words
    float* fct  = (float*)(Vs + 64*VW);  // 64
    float* mt   = fct + 64;              // 64
    float* as_  = mt + 64;               // 64
    float* den2 = as_ + 64;              // 128

    int bh = blockIdx.x; int b = bh>>2, hh = bh&3;
    int it = (int)(gridDim.y - 1) - (int)blockIdx.y;
    int t0 = it<<6;
    int tid = threadIdx.x, lane = tid&31, wid = tid>>5;
    int wm = wid>>1, wn = wid&1;
    int ls = lane>>2, lk = lane&3;
    int g8 = lane>>3, lr = lane&7;
    const float scale = 0.08838834764831845f;

    const __nv_bfloat16* qg = q + ((size_t)(b*SEQ + t0))*512 + hh*128;
    #pragma unroll
    for (int r=0;r<4;r++){
        int idx = tid + (r<<8);
        int row = idx>>4, c16 = idx&15;
        uint4 val = *(const uint4*)(qg + (size_t)row*512 + (c16<<3));
        *(uint4*)&Qs[row*QKW + (c16<<2)] = val;
    }
    if (tid < 64){ int tg = bh*SEQ + t0 + tid; fct[tid] = Fcv[tg]; mt[tid] = mv[tg]; }
    __syncthreads();

    uint32_t qf[8][4];
    int r0 = wm*16 + ls, r1 = r0 + 8;
    #pragma unroll
    for (int ks=0; ks<8; ks++){
        qf[ks][0] = Qs[r0*QKW + ks*8 + lk];
        qf[ks][1] = Qs[r1*QKW + ks*8 + lk];
        qf[ks][2] = Qs[r0*QKW + ks*8 + lk + 4];
        qf[ks][3] = Qs[r1*QKW + ks*8 + lk + 4];
    }

    float oacc[8][4];
    #pragma unroll
    for (int i=0;i<8;i++){ oacc[i][0]=0.f; oacc[i][1]=0.f; oacc[i][2]=0.f; oacc[i][3]=0.f; }
    float den0 = 0.f, den1 = 0.f;

    for (int js=0; js<=it; js++){
        int s0 = js<<6;
        __syncthreads();
        const __nv_bfloat16* kg = k + ((size_t)(b*SEQ + s0))*512 + hh*128;
        const __nv_bfloat16* vg = v + ((size_t)(b*SEQ + s0))*512 + hh*128;
        #pragma unroll
        for (int r=0;r<4;r++){
            int idx = tid + (r<<8);
            int row = idx>>4, c16 = idx&15;
            uint4 kv = *(const uint4*)(kg + (size_t)row*512 + (c16<<3));
            uint4 vv = *(const uint4*)(vg + (size_t)row*512 + (c16<<3));
            *(uint4*)&Ks[row*QKW + (c16<<2)] = kv;
            *(uint4*)&Vs[row*VW + ((c16 ^ (row&7))<<2)] = vv;
        }
        if (tid < 64) as_[tid] = av[bh*SEQ + s0 + tid];
        __syncthreads();

        float sacc[4][4] = {};
        #pragma unroll
        for (int ks=0; ks<8; ks++){
            #pragma unroll
            for (int nt=0; nt<4; nt++){
                int sc = wn*32 + nt*8 + ls;
                uint32_t b0 = Ks[sc*QKW + ks*8 + lk];
                uint32_t b1 = Ks[sc*QKW + ks*8 + lk + 4];
                mma_bf16(sacc[nt], qf[ks], b0, b1);
            }
        }

        float f0 = fct[r0], mm0 = mt[r0], f1 = fct[r1], mm1 = mt[r1];
        bool diag = (js == it);
        #pragma unroll
        for (int nt=0; nt<4; nt++){
            int c0 = wn*32 + nt*8 + (lk<<1);
            int c1 = c0 + 1;
            float a0v = as_[c0], a1v = as_[c1];
            float v00 = sacc[nt][0]*scale*__expf(f0 + a0v - mm0);
            float v01 = sacc[nt][1]*scale*__expf(f0 + a1v - mm0);
            float v10 = sacc[nt][2]*scale*__expf(f1 + a0v - mm1);
            float v11 = sacc[nt][3]*scale*__expf(f1 + a1v - mm1);
            if (diag){
                if (c0 > r0) v00 = 0.f;
                if (c1 > r0) v01 = 0.f;
                if (c0 > r1) v10 = 0.f;
                if (c1 > r1) v11 = 0.f;
            }
            den0 += v00 + v01;
            den1 += v10 + v11;
            int wcol = wn*16 + nt*4 + lk;
            Qs[r0*PW + wcol] = bf2pack(v00, v01);
            Qs[r1*PW + wcol] = bf2pack(v10, v11);
        }
        __syncthreads();

        #pragma unroll
        for (int ks2=0; ks2<4; ks2++){
            uint32_t af[4];
            af[0] = Qs[r0*PW + ks2*8 + lk];
            af[1] = Qs[r1*PW + ks2*8 + lk];
            af[2] = Qs[r0*PW + ks2*8 + lk + 4];
            af[3] = Qs[r1*PW + ks2*8 + lk + 4];
            int krow = (ks2<<4) + lr + ((g8&1)<<3);
            #pragma unroll
            for (int nt=0; nt<8; nt++){
                int cd = wn*8 + nt;
                uint32_t addr = smaddr(&Vs[krow*VW + ((cd ^ (krow&7))<<2)]);
                uint32_t b0, b1;
                asm volatile("ldmatrix.sync.aligned.m8n8.x2.trans.shared.b16 {%0,%1}, [%2];\n"
                    : "=r"(b0),"=r"(b1) : "r"(addr));
                mma_bf16(oacc[nt], af, b0, b1);
            }
        }
    }

    // ---- denominator ----
    den0 += __shfl_xor_sync(0xffffffffu, den0, 1);
    den0 += __shfl_xor_sync(0xffffffffu, den0, 2);
    den1 += __shfl_xor_sync(0xffffffffu, den1, 1);
    den1 += __shfl_xor_sync(0xffffffffu, den1, 2);
    if (lk == 0){ den2[wn*64 + r0] = den0; den2[wn*64 + r1] = den1; }
    __syncthreads();
    float dt0 = den2[r0] + den2[64 + r0];
    float dt1 = den2[r1] + den2[64 + r1];
    float inv0 = 1.f / (fmaxf(fabsf(dt0), __expf(-mt[r0])) + 1e-6f);
    float inv1 = 1.f / (fmaxf(fabsf(dt1), __expf(-mt[r1])) + 1e-6f);

    // ---- normalized head outputs ----
    float hv0[16], hv1[16];
    #pragma unroll
    for (int nt=0; nt<8; nt++){
        hv0[nt*2]   = oacc[nt][0]*inv0;
        hv0[nt*2+1] = oacc[nt][1]*inv0;
        hv1[nt*2]   = oacc[nt][2]*inv1;
        hv1[nt*2+1] = oacc[nt][3]*inv1;
    }

    // ---- fused GroupNorm over 128 head dims ----
    float s0 = 0.f, s1 = 0.f;
    #pragma unroll
    for (int i=0;i<16;i++){ s0 += hv0[i]; s1 += hv1[i]; }
    s0 += __shfl_xor_sync(0xffffffffu, s0, 1);
    s0 += __shfl_xor_sync(0xffffffffu, s0, 2);
    s1 += __shfl_xor_sync(0xffffffffu, s1, 1);
    s1 += __shfl_xor_sync(0xffffffffu, s1, 2);
    __syncthreads();
    if (lk == 0){ den2[wn*64 + r0] = s0; den2[wn*64 + r1] = s1; }
    __syncthreads();
    float mu0 = (den2[r0] + den2[64 + r0]) * (1.f/128.f);
    float mu1 = (den2[r1] + den2[64 + r1]) * (1.f/128.f);
    float q0 = 0.f, q1 = 0.f;
    #pragma unroll
    for (int i=0;i<16;i++){
        float d0 = hv0[i]-mu0; q0 += d0*d0;
        float d1 = hv1[i]-mu1; q1 += d1*d1;
    }
    q0 += __shfl_xor_sync(0xffffffffu, q0, 1);
    q0 += __shfl_xor_sync(0xffffffffu, q0, 2);
    q1 += __shfl_xor_sync(0xffffffffu, q1, 1);
    q1 += __shfl_xor_sync(0xffffffffu, q1, 2);
    __syncthreads();
    if (lk == 0){ den2[wn*64 + r0] = q0; den2[wn*64 + r1] = q1; }
    __syncthreads();
    float is0 = rsqrtf((den2[r0] + den2[64 + r0])*(1.f/128.f) + 1e-5f);
    float is1 = rsqrtf((den2[r1] + den2[64 + r1])*(1.f/128.f) + 1e-5f);

    // ---- gamma/beta + skip*xc + silu(z), bf16 store ----
    size_t tok0 = (size_t)(b*SEQ + t0 + r0), tok1 = (size_t)(b*SEQ + t0 + r1);
    #pragma unroll
    for (int nt=0; nt<8; nt++){
        int dc = wn*64 + nt*8 + (lk<<1);
        int c = hh*128 + dc;
        float2 gg = *(const float2*)&gng[c];
        float2 gb = *(const float2*)&gnb[c];
        float2 sk = *(const float2*)&skip[c];
        float2 x0 = *(const float2*)&xc[tok0*512 + c];
        float2 x1 = *(const float2*)&xc[tok1*512 + c];
        float2 z0 = *(const float2*)&up[tok0*1024 + 512 + c];
        float2 z1 = *(const float2*)&up[tok1*1024 + 512 + c];
        float y00 = (hv0[nt*2]  -mu0)*is0*gg.x + gb.x + sk.x*x0.x;
        float y01 = (hv0[nt*2+1]-mu0)*is0*gg.y + gb.y + sk.y*x0.y;
        float y10 = (hv1[nt*2]  -mu1)*is1*gg.x + gb.x + sk.x*x1.x;
        float y11 = (hv1[nt*2+1]-mu1)*is1*gg.y + gb.y + sk.y*x1.y;
        y00 *= z0.x / (1.f + expf(-z0.x));
        y01 *= z0.y / (1.f + expf(-z0.y));
        y10 *= z1.x / (1.f + expf(-z1.x));
        y11 *= z1.y / (1.f + expf(-z1.y));
        *(__nv_bfloat162*)&out[tok0*512 + c] = __floats2bfloat162_rn(y00, y01);
        *(__nv_bfloat162*)&out[tok1*512 + c] = __floats2bfloat162_rn(y10, y11);
    }
}

// ---------------- final ----------------
__global__ void final_kernel(const float* __restrict__ h, const float* __restrict__ g,
                             const float* __restrict__ b, const float* __restrict__ Wf,
                             const float* __restrict__ bf, float* __restrict__ out){
    __shared__ float sh[8];
    __shared__ float sv;
    int bb = blockIdx.x, tid = threadIdx.x;
    float vv = h[((size_t)(bb*SEQ + SEQ-1))*256 + tid];
    float s = warp_sum(vv);
    if (!(tid&31)) sh[tid>>5] = s;
    __syncthreads();
    if (tid==0){ float t=0; for(int i=0;i<8;i++) t+=sh[i]; sv = t*(1.f/256.f); }
    __syncthreads();
    float mu = sv;
    float d = vv - mu;
    float s2 = warp_sum(d*d);
    if (!(tid&31)) sh[tid>>5] = s2;
    __syncthreads();
    if (tid==0){ float t=0; for(int i=0;i<8;i++) t+=sh[i]; sv = t*(1.f/256.f); }
    __syncthreads();
    float yn = d*rsqrtf(sv + 1e-5f)*g[tid] + b[tid];
    float p = yn * Wf[tid];
    float s3 = warp_sum(p);
    __syncthreads();
    if (!(tid&31)) sh[tid>>5] = s3;
    __syncthreads();
    if (tid==0){ float t=0; for(int i=0;i<8;i++) t+=sh[i]; out[bb] = t + bf[0]; }
}

// ---------------- launch ----------------
extern "C" void kernel_launch(void* const* d_in, const int* in_sizes, int n_in,
                              void* d_out, int out_size){
    const float* x    = (const float*)d_in[0];
    const float* tf   = (const float*)d_in[1];
    const float* Wp   = (const float*)d_in[2];
    const float* bp   = (const float*)d_in[3];
    const float* ln_g = (const float*)d_in[4];
    const float* ln_b = (const float*)d_in[5];
    const float* Wup  = (const float*)d_in[6];
    const float* bup  = (const float*)d_in[7];
    const float* cw   = (const float*)d_in[8];
    const float* cb   = (const float*)d_in[9];
    const float* Wq   = (const float*)d_in[10];
    const float* Wk   = (const float*)d_in[11];
    const float* Wv   = (const float*)d_in[12];
    const float* Wif  = (const float*)d_in[13];
    const float* bif  = (const float*)d_in[14];
    const float* gng  = (const float*)d_in[15];
    const float* gnb  = (const float*)d_in[16];
    const float* skip = (const float*)d_in[17];
    const float* Wdn  = (const float*)d_in[18];
    const float* bdn  = (const float*)d_in[19];
    const float* lnfg = (const float*)d_in[20];
    const float* lnfb = (const float*)d_in[21];
    const float* Wf   = (const float*)d_in[22];
    const float* bf   = (const float*)d_in[23];

    float *h,*up,*xc,*giT,*gfT,*Fc,*a,*m,*Wg;
    __nv_bfloat16 *hnbf,*xcbf,*upbf,*qbf,*kbf,*vbf,*att2bf,*wupbf,*wqbf,*wkbf,*wvbf,*wdnbf;
    cudaGetSymbolAddress((void**)&h,    g_h);
    cudaGetSymbolAddress((void**)&up,   g_up);
    cudaGetSymbolAddress((void**)&xc,   g_xc);
    cudaGetSymbolAddress((void**)&giT,  g_giT);
    cudaGetSymbolAddress((void**)&gfT,  g_gfT);
    cudaGetSymbolAddress((void**)&Fc,   g_Fc);
    cudaGetSymbolAddress((void**)&a,    g_a);
    cudaGetSymbolAddress((void**)&m,    g_m);
    cudaGetSymbolAddress((void**)&Wg,   g_Wg);
    cudaGetSymbolAddress((void**)&hnbf, g_hn_bf);
    cudaGetSymbolAddress((void**)&xcbf, g_xc_bf);
    cudaGetSymbolAddress((void**)&upbf, g_up_bf);
    cudaGetSymbolAddress((void**)&qbf,  g_q_bf);
    cudaGetSymbolAddress((void**)&kbf,  g_k_bf);
    cudaGetSymbolAddress((void**)&vbf,  g_v_bf);
    cudaGetSymbolAddress((void**)&att2bf, g_att2_bf);
    cudaGetSymbolAddress((void**)&wupbf, g_wup_bf);
    cudaGetSymbolAddress((void**)&wqbf,  g_wq_bf);
    cudaGetSymbolAddress((void**)&wkbf,  g_wk_bf);
    cudaGetSymbolAddress((void**)&wvbf,  g_wv_bf);
    cudaGetSymbolAddress((void**)&wdnbf, g_wdn_bf);

    int attn_smem = (64*QKW + 64*QKW + 64*VW + 64 + 64 + 64 + 128) * 4;
    static int attr_set = 0;
    if (!attr_set){
        cudaFuncSetAttribute(attn_bf16, cudaFuncAttributeMaxDynamicSharedMemorySize, attn_smem);
        attr_set = 1;
    }

    f2bf_kernel<<<(NL*DMODEL*1024/2+255)/256, 256>>>(Wup, wupbf, NL*DMODEL*1024);
    f2bf_kernel<<<(NL*DI*DI/2+255)/256, 256>>>(Wq, wqbf, NL*DI*DI);
    f2bf_kernel<<<(NL*DI*DI/2+255)/256, 256>>>(Wk, wkbf, NL*DI*DI);
    f2bf_kernel<<<(NL*DI*DI/2+255)/256, 256>>>(Wv, wvbf, NL*DI*DI);
    f2bf_kernel<<<(NL*DI*DMODEL/2+255)/256, 256>>>(Wdn, wdnbf, NL*DI*DMODEL);
    gatew_kernel<<<NL*1024*8/256, 256>>>(Wq, Wk, Wv, Wif, Wg);

    embed_kernel<<<TOK*256/256, 256>>>(x, tf, Wp, bp, h);

    for (int l=0; l<NL; l++){
        ln_kernel<<<TOK/8, 256>>>(h, ln_g + l*256, ln_b + l*256, hnbf);
        gemm_bf16<<<dim3(1024/64, TOK/128, 1), 256>>>(hnbf, 256, wupbf + (size_t)l*256*1024, 1024,
                                                   up, 1024, bup + l*1024, nullptr, 256,
                                                   upbf, 512, nullptr, nullptr, nullptr, nullptr, nullptr);
        conv_silu_kernel<<<TOK*512/256, 256>>>(up, cw + l*4*512, cb + l*512, xc, xcbf);
        // merged Q (z=0), K (z=1), V (z=2) projections; bf16 outputs only
        gemm_bf16<<<dim3(512/64, TOK/128, 3), 256>>>(xcbf, 512, wqbf + (size_t)l*512*512, 512,
                                                  nullptr, 512, nullptr, nullptr, 512, qbf, 512,
                                                  upbf,
                                                  wkbf + (size_t)l*512*512, kbf,
                                                  wvbf + (size_t)l*512*512, vbf);
        gates2_kernel<<<TOK, 256>>>(xc, up, Wg + (size_t)l*8192, bif + l*8, giT, gfT);
        scan_kernel3<<<32, 32>>>(giT, gfT, Fc, a, m);
        attn_bf16<<<dim3(BATCH*NH, SEQ/64), 256, attn_smem>>>(qbf, kbf, vbf, Fc, a, m,
                                                  xc, up, gng + l*512, gnb + l*512, skip + l*512,
                                                  att2bf);
        gemm_bf16<<<dim3(256/64, TOK/128, 1), 256>>>(att2bf, 512, wdnbf + (size_t)l*512*256, 256,
                                                  h, 256, bdn + l*256, h, 512,
                                                  nullptr, 0, nullptr, nullptr, nullptr, nullptr, nullptr);
    }
    final_kernel<<<BATCH, 256>>>(h, lnfg, lnfb, Wf, bf, (float*)d_out);
}

// round 9
// speedup vs baseline: 5.4092x; 1.0099x over previous
#include <cuda_runtime.h>
#include <cuda_bf16.h>
#include <cstdint>
#include <cstddef>

#define SEQ 1024
#define BATCH 8
#define TOK (BATCH*SEQ)
#define DMODEL 256
#define DI 512
#define NH 4
#define DHH 128
#define NL 4

// ---------------- scratch (device globals; no allocation allowed) ----------------
__device__ float g_h[TOK*DMODEL];
__device__ float g_up[TOK*1024];
__device__ float g_xc[TOK*DI];
__device__ float g_giT[BATCH*NH*SEQ];
__device__ float g_gfT[BATCH*NH*SEQ];
__device__ float g_Fc[BATCH*NH*SEQ];
__device__ float g_a[BATCH*NH*SEQ];
__device__ float g_m[BATCH*NH*SEQ];
__device__ float g_wcol[BATCH*NH*SEQ];
__device__ float g_amaxT[BATCH*NH*16];
__device__ float g_Wg[NL*1024*8];

__device__ __nv_bfloat16 g_hn_bf[TOK*DMODEL];
__device__ __nv_bfloat16 g_xc_bf[TOK*DI];
__device__ __nv_bfloat16 g_up_bf[TOK*DI];
__device__ __nv_bfloat16 g_q_bf[TOK*DI];
__device__ __nv_bfloat16 g_k_bf[TOK*DI];
__device__ __nv_bfloat16 g_v_bf[TOK*DI];
__device__ __nv_bfloat16 g_att2_bf[TOK*DI];
__device__ __nv_bfloat16 g_wup_bf[NL*DMODEL*1024];
__device__ __nv_bfloat16 g_wq_bf[NL*DI*DI];
__device__ __nv_bfloat16 g_wk_bf[NL*DI*DI];
__device__ __nv_bfloat16 g_wv_bf[NL*DI*DI];
__device__ __nv_bfloat16 g_wdn_bf[NL*DI*DMODEL];

__device__ __forceinline__ float warp_sum(float v){
    #pragma unroll
    for (int o=16;o;o>>=1) v += __shfl_xor_sync(0xffffffffu, v, o);
    return v;
}

__device__ __forceinline__ uint32_t bf2pack(float x, float y){
    __nv_bfloat162 t = __floats2bfloat162_rn(x, y);
    return *(uint32_t*)&t;
}

__device__ __forceinline__ void mma_bf16(float* c, const uint32_t* a, uint32_t b0, uint32_t b1){
    asm volatile(
      "mma.sync.aligned.m16n8k16.row.col.f32.bf16.bf16.f32 "
      "{%0,%1,%2,%3}, {%4,%5,%6,%7}, {%8,%9}, {%0,%1,%2,%3};\n"
      : "+f"(c[0]), "+f"(c[1]), "+f"(c[2]), "+f"(c[3])
      : "r"(a[0]), "r"(a[1]), "r"(a[2]), "r"(a[3]), "r"(b0), "r"(b1));
}

__device__ __forceinline__ uint32_t smaddr(const void* p){
    return (uint32_t)__cvta_generic_to_shared(p);
}
#define CPA16(dst,src) asm volatile("cp.async.cg.shared.global [%0], [%1], 16;\n"::"r"(dst),"l"(src))
#define CPCOMMIT() asm volatile("cp.async.commit_group;\n")
#define CPWAIT(n) asm volatile("cp.async.wait_group %0;\n"::"n"(n))

// ---------------- merged f32 -> bf16 convert for all 5 weight tensors ----------------
__global__ void f2bf5_kernel(const float* __restrict__ i0, __nv_bfloat16* __restrict__ o0, int n0,
                             const float* __restrict__ i1, __nv_bfloat16* __restrict__ o1, int n1,
                             const float* __restrict__ i2, __nv_bfloat16* __restrict__ o2, int n2,
                             const float* __restrict__ i3, __nv_bfloat16* __restrict__ o3, int n3,
                             const float* __restrict__ i4, __nv_bfloat16* __restrict__ o4, int n4){
    int i = (blockIdx.x*blockDim.x + threadIdx.x)*2;
    const float* in; __nv_bfloat16* out;
    if (i < n0){ in=i0; out=o0; }
    else if ((i-=n0) < n1){ in=i1; out=o1; }
    else if ((i-=n1) < n2){ in=i2; out=o2; }
    else if ((i-=n2) < n3){ in=i3; out=o3; }
    else if ((i-=n3) < n4){ in=i4; out=o4; }
    else return;
    float2 v = *(const float2*)(in+i);
    *(__nv_bfloat162*)(out+i) = __floats2bfloat162_rn(v.x, v.y);
}

// ---------------- composite gate weights: Wg = [Wq@Wif_i + Wk@Wif_k ; Wv@Wif_v] ----------------
__global__ void gatew_kernel(const float* __restrict__ Wq, const float* __restrict__ Wk,
                             const float* __restrict__ Wv, const float* __restrict__ Wif,
                             float* __restrict__ Wg){
    int idx = blockIdx.x*blockDim.x + threadIdx.x;   // NL*1024*8
    int l = idx >> 13; int r = idx & 8191;
    int c = r >> 3; int j = r & 7;
    const float* Wifl = Wif + (size_t)l*1536*8;
    float acc = 0.f;
    if (c < 512){
        const float* wq = Wq + ((size_t)l*512 + c)*512;
        const float* wk = Wk + ((size_t)l*512 + c)*512;
        #pragma unroll 4
        for (int i=0;i<512;i++)
            acc += wq[i]*Wifl[i*8+j] + wk[i]*Wifl[(512+i)*8+j];
    } else {
        const float* wv = Wv + ((size_t)l*512 + (c-512))*512;
        #pragma unroll 4
        for (int i=0;i<512;i++)
            acc += wv[i]*Wifl[(1024+i)*8+j];
    }
    Wg[(size_t)l*8192 + c*8 + j] = acc;
}

// ---------------- embed ----------------
__global__ void embed_kernel(const float* __restrict__ x, const float* __restrict__ tf,
                             const float* __restrict__ Wp, const float* __restrict__ bp,
                             float* __restrict__ h){
    int idx = blockIdx.x*blockDim.x + threadIdx.x;
    int j = idx & 255; int tok = idx >> 8;
    float acc = bp[j] + x[tok]*Wp[j];
    #pragma unroll
    for (int f=0; f<4; f++) acc += tf[tok*4+f]*Wp[(1+f)*256+j];
    h[idx] = acc;
}

// ---------------- layernorm, bf16 out ----------------
__global__ void ln_kernel(const float* __restrict__ x, const float* __restrict__ g,
                          const float* __restrict__ b, __nv_bfloat16* __restrict__ y){
    int row = blockIdx.x*8 + (threadIdx.x>>5);
    int lane = threadIdx.x & 31;
    const float* xr = x + (size_t)row*256;
    float4 v0 = *(const float4*)(xr + lane*4);
    float4 v1 = *(const float4*)(xr + 128 + lane*4);
    float s = v0.x+v0.y+v0.z+v0.w + v1.x+v1.y+v1.z+v1.w;
    s = warp_sum(s);
    float mu = s * (1.f/256.f);
    float d0x=v0.x-mu, d0y=v0.y-mu, d0z=v0.z-mu, d0w=v0.w-mu;
    float d1x=v1.x-mu, d1y=v1.y-mu, d1z=v1.z-mu, d1w=v1.w-mu;
    float sq = d0x*d0x+d0y*d0y+d0z*d0z+d0w*d0w + d1x*d1x+d1y*d1y+d1z*d1z+d1w*d1w;
    sq = warp_sum(sq);
    float is = rsqrtf(sq*(1.f/256.f) + 1e-5f);
    float4 g0 = *(const float4*)(g + lane*4);
    float4 g1 = *(const float4*)(g + 128 + lane*4);
    float4 b0 = *(const float4*)(b + lane*4);
    float4 b1 = *(const float4*)(b + 128 + lane*4);
    __nv_bfloat16* yr = y + (size_t)row*256;
    *(__nv_bfloat162*)&yr[lane*4]       = __floats2bfloat162_rn(d0x*is*g0.x + b0.x, d0y*is*g0.y + b0.y);
    *(__nv_bfloat162*)&yr[lane*4+2]     = __floats2bfloat162_rn(d0z*is*g0.z + b0.z, d0w*is*g0.w + b0.w);
    *(__nv_bfloat162*)&yr[128+lane*4]   = __floats2bfloat162_rn(d1x*is*g1.x + b1.x, d1y*is*g1.y + b1.y);
    *(__nv_bfloat162*)&yr[128+lane*4+2] = __floats2bfloat162_rn(d1z*is*g1.z + b1.z, d1w*is*g1.w + b1.w);
}

// ---------------- bf16 tensor-core GEMM, cp.async double-buffered ----------------
// z=0: (A,B,Cbf); z=1: (A,B2,Cbf2); z=2: (A2,B3,Cbf3). C fp32 optional (nullptr skips).
__global__ __launch_bounds__(256) void gemm_bf16(
    const __nv_bfloat16* __restrict__ A, int lda,
    const __nv_bfloat16* __restrict__ B, int ldb,
    float* __restrict__ C, int ldc,
    const float* __restrict__ bias,
    const float* __restrict__ resid,
    int K,
    __nv_bfloat16* __restrict__ Cbf, int bfcap,
    const __nv_bfloat16* __restrict__ A2,
    const __nv_bfloat16* __restrict__ B2,
    __nv_bfloat16* __restrict__ Cbf2,
    const __nv_bfloat16* __restrict__ B3,
    __nv_bfloat16* __restrict__ Cbf3)
{
    __shared__ __nv_bfloat16 As[2][128*64];
    __shared__ __nv_bfloat16 Bs[2][64*64];
    if (blockIdx.z == 1){ B = B2; Cbf = Cbf2; }
    else if (blockIdx.z == 2){ A = A2; B = B3; Cbf = Cbf3; }
    int tid = threadIdx.x, lane = tid&31, wid = tid>>5;
    int wm = wid>>1, wn = wid&1;
    int m0 = blockIdx.y*128, n0 = blockIdx.x*64;

    int ar = tid >> 1;
    int ac0 = (tid & 1) << 2;
    int br = tid >> 2;
    int bc0 = (tid & 3) << 1;
    const __nv_bfloat16* Ag = A + (size_t)(m0+ar)*lda;
    const __nv_bfloat16* Bg = B + (size_t)br*ldb + n0;

    int KC = K >> 6;
    {
        #pragma unroll
        for (int c=0;c<4;c++){
            int ch = ac0+c;
            CPA16(smaddr(&As[0][ar*64 + ((ch ^ (ar&7))<<3)]), Ag + (ch<<3));
        }
        #pragma unroll
        for (int c=0;c<2;c++){
            int ch = bc0+c;
            CPA16(smaddr(&Bs[0][br*64 + ((ch ^ (br&7))<<3)]), Bg + (ch<<3));
        }
        CPCOMMIT();
    }

    float acc[2][4][4] = {};
    int g = lane>>3, lr = lane&7;

    for (int kc=0; kc<KC; kc++){
        int cur = kc & 1;
        if (kc+1 < KC){
            int nb = (kc+1)&1, k0 = (kc+1)<<6;
            #pragma unroll
            for (int c=0;c<4;c++){
                int ch = ac0+c;
                CPA16(smaddr(&As[nb][ar*64 + ((ch ^ (ar&7))<<3)]), Ag + k0 + (ch<<3));
            }
            #pragma unroll
            for (int c=0;c<2;c++){
                int ch = bc0+c;
                CPA16(smaddr(&Bs[nb][br*64 + ((ch ^ (br&7))<<3)]), Bg + (size_t)k0*ldb + (ch<<3));
            }
            CPCOMMIT();
            CPWAIT(1);
        } else {
            CPWAIT(0);
        }
        __syncthreads();

        #pragma unroll
        for (int ks=0; ks<4; ks++){
            uint32_t af[2][4];
            #pragma unroll
            for (int mt=0; mt<2; mt++){
                int arow = wm*32 + mt*16 + lr + ((g&1)<<3);
                int ch = (ks<<1) + (g>>1);
                uint32_t addr = smaddr(&As[cur][arow*64 + ((ch ^ (arow&7))<<3)]);
                asm volatile("ldmatrix.sync.aligned.m8n8.x4.shared.b16 {%0,%1,%2,%3}, [%4];\n"
                    : "=r"(af[mt][0]),"=r"(af[mt][1]),"=r"(af[mt][2]),"=r"(af[mt][3]) : "r"(addr));
            }
            uint32_t bf[4][2];
            int krow = (ks<<4) + lr + ((g&1)<<3);
            #pragma unroll
            for (int nt=0; nt<4; nt++){
                int ch = wn*4 + nt;
                uint32_t addr = smaddr(&Bs[cur][krow*64 + ((ch ^ (krow&7))<<3)]);
                asm volatile("ldmatrix.sync.aligned.m8n8.x2.trans.shared.b16 {%0,%1}, [%2];\n"
                    : "=r"(bf[nt][0]),"=r"(bf[nt][1]) : "r"(addr));
            }
            #pragma unroll
            for (int mt=0;mt<2;mt++)
              #pragma unroll
              for (int nt=0;nt<4;nt++)
                mma_bf16(acc[mt][nt], af[mt], bf[nt][0], bf[nt][1]);
        }
        __syncthreads();
    }

    #pragma unroll
    for (int mt=0;mt<2;mt++){
        #pragma unroll
        for (int nt=0;nt<4;nt++){
            int row0 = m0 + wm*32 + mt*16 + (lane>>2);
            int col  = n0 + wn*32 + nt*8 + ((lane&3)<<1);
            float bx=0.f, by=0.f;
            if (bias){ bx = bias[col]; by = bias[col+1]; }
            float2 r0v = make_float2(0.f,0.f), r1v = make_float2(0.f,0.f);
            if (resid){
                r0v = *(const float2*)&resid[(size_t)row0*ldc + col];
                r1v = *(const float2*)&resid[(size_t)(row0+8)*ldc + col];
            }
            float v00 = acc[mt][nt][0]+bx+r0v.x, v01 = acc[mt][nt][1]+by+r0v.y;
            float v10 = acc[mt][nt][2]+bx+r1v.x, v11 = acc[mt][nt][3]+by+r1v.y;
            if (C){
                *(float2*)&C[(size_t)row0*ldc + col]     = make_float2(v00, v01);
                *(float2*)&C[(size_t)(row0+8)*ldc + col] = make_float2(v10, v11);
            }
            if (Cbf && col < bfcap){
                *(__nv_bfloat162*)&Cbf[(size_t)row0*bfcap + col]     = __floats2bfloat162_rn(v00, v01);
                *(__nv_bfloat162*)&Cbf[(size_t)(row0+8)*bfcap + col] = __floats2bfloat162_rn(v10, v11);
            }
        }
    }
}

// ---------------- fused causal conv + silu + composite gates ----------------
// one block per token: conv for 512 channels (xc kept in smem), then 8 gate dots.
__global__ __launch_bounds__(256) void conv_gates_kernel(
    const float* __restrict__ up, const float* __restrict__ cw, const float* __restrict__ cb,
    const float* __restrict__ Wg, const float* __restrict__ bif,
    float* __restrict__ xc, __nv_bfloat16* __restrict__ xcbf,
    float* __restrict__ giT, float* __restrict__ gfT)
{
    __shared__ float xcs[512], xms[512];
    int tok = blockIdx.x, tid = threadIdx.x;
    int t = tok & 1023;
    #pragma unroll
    for (int r=0;r<2;r++){
        int c = tid + (r<<8);
        float xm = up[(size_t)tok*1024 + c];
        float acc = cb[c] + cw[3*512+c]*xm;
        #pragma unroll
        for (int j=0;j<3;j++){
            int ts = t - 3 + j;
            if (ts >= 0) acc += cw[j*512+c]*up[(size_t)(tok-3+j)*1024 + c];
        }
        float sv = acc/(1.f+expf(-acc));
        xcs[c] = sv; xms[c] = xm;
        xc[(size_t)tok*512 + c] = sv;
        xcbf[(size_t)tok*512 + c] = __float2bfloat16(sv);
    }
    __syncthreads();
    int w = tid>>5, lane = tid&31;
    float acc = 0.f;
    for (int i=lane;i<512;i+=32) acc += xcs[i]*Wg[i*8+w] + xms[i]*Wg[(512+i)*8+w];
    acc = warp_sum(acc);
    if (!lane){
        float r = acc + bif[w];
        int b = tok >> 10, s = tok & 1023;
        if (w < 4) giT[(size_t)(b*4+w)*1024 + s] = r;
        else       gfT[(size_t)(b*4+w-4)*1024 + s] = r;
    }
}

// ---------------- gate scan + per-tile col weights ----------------
// wcol[s] = scale*exp(a_s - amaxT[tile(s)]), amaxT = per-64-chunk max of a.
__global__ void scan_kernel4(const float* __restrict__ giT, const float* __restrict__ gfT,
                             float* __restrict__ Fc, float* __restrict__ a, float* __restrict__ m,
                             float* __restrict__ wcol, float* __restrict__ amaxT){
    __shared__ float ash[1024];
    int bh = blockIdx.x, lane = threadIdx.x;
    const float* gih = giT + (size_t)bh*1024;
    const float* gfh = gfT + (size_t)bh*1024;
    const float scale = 0.08838834764831845f;
    float cfc = 0.f, cmax = -1e30f;
    float ipc = gih[lane], fpc = gfh[lane];
    for (int c=0;c<32;c++){
        float ip = ipc, fp = fpc;
        if (c+1 < 32){ ipc = gih[(c+1)*32+lane]; fpc = gfh[(c+1)*32+lane]; }
        float lf = fminf(fp, 0.f) - log1pf(expf(-fabsf(fp)));
        float x = lf;
        #pragma unroll
        for (int o=1;o<32;o<<=1){ float y = __shfl_up_sync(0xffffffffu, x, o); if (lane>=o) x += y; }
        float fc = cfc + x;
        float av = ip - fc;
        float mx = av;
        #pragma unroll
        for (int o=1;o<32;o<<=1){ float y = __shfl_up_sync(0xffffffffu, mx, o); if (lane>=o) mx = fmaxf(mx, y); }
        float cm = fmaxf(cmax, mx);
        int off = bh*SEQ + c*32 + lane;
        Fc[off] = fc; a[off] = av; m[off] = fc + cm;
        ash[c*32 + lane] = av;
        cfc += __shfl_sync(0xffffffffu, x, 31);
        cmax = fmaxf(cmax, __shfl_sync(0xffffffffu, mx, 31));
    }
    __syncwarp();
    for (int tile=0;tile<16;tile++){
        float v0 = ash[tile*64 + lane];
        float v1 = ash[tile*64 + 32 + lane];
        float mx = fmaxf(v0, v1);
        #pragma unroll
        for (int o=16;o;o>>=1) mx = fmaxf(mx, __shfl_xor_sync(0xffffffffu, mx, o));
        if (lane == 0) amaxT[bh*16 + tile] = mx;
        wcol[bh*SEQ + tile*64 + lane]      = scale*__expf(v0 - mx);
        wcol[bh*SEQ + tile*64 + 32 + lane] = scale*__expf(v1 - mx);
    }
}

// ---------------- mLSTM attention + fused GN/skip/silu-gate epilogue ----------------
// Off-diagonal tiles: factorized decay weights (2 exps/thread/tile).
// Diagonal tile: per-element exp + causal mask.
#define QKW 68
#define VW  64
#define PW  36
__global__ __launch_bounds__(256) void attn_bf16(
    const __nv_bfloat16* __restrict__ q, const __nv_bfloat16* __restrict__ k,
    const __nv_bfloat16* __restrict__ v,
    const float* __restrict__ Fcv, const float* __restrict__ av, const float* __restrict__ mv,
    const float* __restrict__ wcol, const float* __restrict__ amaxT,
    const float* __restrict__ xc, const float* __restrict__ up,
    const float* __restrict__ gng, const float* __restrict__ gnb,
    const float* __restrict__ skip,
    __nv_bfloat16* __restrict__ out)
{
    extern __shared__ uint32_t smu[];
    uint32_t* Qs = smu;                  // 64*68 words; reused as P (64*36)
    uint32_t* Ks = Qs + 64*QKW;
    uint32_t* Vs = Ks + 64*QKW;          // 64*64 words
    float* fct  = (float*)(Vs + 64*VW);  // 64
    float* mt   = fct + 64;              // 64
    float* as_  = mt + 64;               // 64 (wcol off-diag / raw a on diag)
    float* den2 = as_ + 64;              // 128

    int bh = blockIdx.x; int b = bh>>2, hh = bh&3;
    int it = (int)(gridDim.y - 1) - (int)blockIdx.y;
    int t0 = it<<6;
    int tid = threadIdx.x, lane = tid&31, wid = tid>>5;
    int wm = wid>>1, wn = wid&1;
    int ls = lane>>2, lk = lane&3;
    int g8 = lane>>3, lr = lane&7;
    const float scale = 0.08838834764831845f;

    const __nv_bfloat16* qg = q + ((size_t)(b*SEQ + t0))*512 + hh*128;
    #pragma unroll
    for (int r=0;r<4;r++){
        int idx = tid + (r<<8);
        int row = idx>>4, c16 = idx&15;
        uint4 val = *(const uint4*)(qg + (size_t)row*512 + (c16<<3));
        *(uint4*)&Qs[row*QKW + (c16<<2)] = val;
    }
    if (tid < 64){ int tg = bh*SEQ + t0 + tid; fct[tid] = Fcv[tg]; mt[tid] = mv[tg]; }
    __syncthreads();

    uint32_t qf[8][4];
    int r0 = wm*16 + ls, r1 = r0 + 8;
    #pragma unroll
    for (int ks=0; ks<8; ks++){
        qf[ks][0] = Qs[r0*QKW + ks*8 + lk];
        qf[ks][1] = Qs[r1*QKW + ks*8 + lk];
        qf[ks][2] = Qs[r0*QKW + ks*8 + lk + 4];
        qf[ks][3] = Qs[r1*QKW + ks*8 + lk + 4];
    }

    float oacc[8][4];
    #pragma unroll
    for (int i=0;i<8;i++){ oacc[i][0]=0.f; oacc[i][1]=0.f; oacc[i][2]=0.f; oacc[i][3]=0.f; }
    float den0 = 0.f, den1 = 0.f;

    for (int js=0; js<=it; js++){
        int s0 = js<<6;
        bool diag = (js == it);
        __syncthreads();
        const __nv_bfloat16* kg = k + ((size_t)(b*SEQ + s0))*512 + hh*128;
        const __nv_bfloat16* vg = v + ((size_t)(b*SEQ + s0))*512 + hh*128;
        #pragma unroll
        for (int r=0;r<4;r++){
            int idx = tid + (r<<8);
            int row = idx>>4, c16 = idx&15;
            uint4 kv = *(const uint4*)(kg + (size_t)row*512 + (c16<<3));
            uint4 vv = *(const uint4*)(vg + (size_t)row*512 + (c16<<3));
            *(uint4*)&Ks[row*QKW + (c16<<2)] = kv;
            *(uint4*)&Vs[row*VW + ((c16 ^ (row&7))<<2)] = vv;
        }
        if (tid < 64)
            as_[tid] = diag ? av[bh*SEQ + s0 + tid] : wcol[bh*SEQ + s0 + tid];
        __syncthreads();

        float sacc[4][4] = {};
        #pragma unroll
        for (int ks=0; ks<8; ks++){
            #pragma unroll
            for (int nt=0; nt<4; nt++){
                int sc = wn*32 + nt*8 + ls;
                uint32_t b0 = Ks[sc*QKW + ks*8 + lk];
                uint32_t b1 = Ks[sc*QKW + ks*8 + lk + 4];
                mma_bf16(sacc[nt], qf[ks], b0, b1);
            }
        }

        float f0 = fct[r0], mm0 = mt[r0], f1 = fct[r1], mm1 = mt[r1];
        if (!diag){
            // factorized: w_row = exp(fct - m + amaxT) <= 1, wcol already has scale folded
            float amx = amaxT[bh*16 + js];
            float w0 = __expf(f0 - mm0 + amx);
            float w1 = __expf(f1 - mm1 + amx);
            #pragma unroll
            for (int nt=0; nt<4; nt++){
                int c0 = wn*32 + nt*8 + (lk<<1);
                float wc0 = as_[c0], wc1 = as_[c0+1];
                float v00 = sacc[nt][0]*w0*wc0;
                float v01 = sacc[nt][1]*w0*wc1;
                float v10 = sacc[nt][2]*w1*wc0;
                float v11 = sacc[nt][3]*w1*wc1;
                den0 += v00 + v01;
                den1 += v10 + v11;
                int wcl = wn*16 + nt*4 + lk;
                Qs[r0*PW + wcl] = bf2pack(v00, v01);
                Qs[r1*PW + wcl] = bf2pack(v10, v11);
            }
        } else {
            #pragma unroll
            for (int nt=0; nt<4; nt++){
                int c0 = wn*32 + nt*8 + (lk<<1);
                int c1 = c0 + 1;
                float a0v = as_[c0], a1v = as_[c1];
                float v00 = sacc[nt][0]*scale*__expf(f0 + a0v - mm0);
                float v01 = sacc[nt][1]*scale*__expf(f0 + a1v - mm0);
                float v10 = sacc[nt][2]*scale*__expf(f1 + a0v - mm1);
                float v11 = sacc[nt][3]*scale*__expf(f1 + a1v - mm1);
                if (c0 > r0) v00 = 0.f;
                if (c1 > r0) v01 = 0.f;
                if (c0 > r1) v10 = 0.f;
                if (c1 > r1) v11 = 0.f;
                den0 += v00 + v01;
                den1 += v10 + v11;
                int wcl = wn*16 + nt*4 + lk;
                Qs[r0*PW + wcl] = bf2pack(v00, v01);
                Qs[r1*PW + wcl] = bf2pack(v10, v11);
            }
        }
        __syncthreads();

        #pragma unroll
        for (int ks2=0; ks2<4; ks2++){
            uint32_t af[4];
            af[0] = Qs[r0*PW + ks2*8 + lk];
            af[1] = Qs[r1*PW + ks2*8 + lk];
            af[2] = Qs[r0*PW + ks2*8 + lk + 4];
            af[3] = Qs[r1*PW + ks2*8 + lk + 4];
            int krow = (ks2<<4) + lr + ((g8&1)<<3);
            #pragma unroll
            for (int nt=0; nt<8; nt++){
                int cd = wn*8 + nt;
                uint32_t addr = smaddr(&Vs[krow*VW + ((cd ^ (krow&7))<<2)]);
                uint32_t b0, b1;
                asm volatile("ldmatrix.sync.aligned.m8n8.x2.trans.shared.b16 {%0,%1}, [%2];\n"
                    : "=r"(b0),"=r"(b1) : "r"(addr));
                mma_bf16(oacc[nt], af, b0, b1);
            }
        }
    }

    // ---- denominator ----
    den0 += __shfl_xor_sync(0xffffffffu, den0, 1);
    den0 += __shfl_xor_sync(0xffffffffu, den0, 2);
    den1 += __shfl_xor_sync(0xffffffffu, den1, 1);
    den1 += __shfl_xor_sync(0xffffffffu, den1, 2);
    if (lk == 0){ den2[wn*64 + r0] = den0; den2[wn*64 + r1] = den1; }
    __syncthreads();
    float dt0 = den2[r0] + den2[64 + r0];
    float dt1 = den2[r1] + den2[64 + r1];
    float inv0 = 1.f / (fmaxf(fabsf(dt0), __expf(-mt[r0])) + 1e-6f);
    float inv1 = 1.f / (fmaxf(fabsf(dt1), __expf(-mt[r1])) + 1e-6f);

    // ---- normalized head outputs ----
    float hv0[16], hv1[16];
    #pragma unroll
    for (int nt=0; nt<8; nt++){
        hv0[nt*2]   = oacc[nt][0]*inv0;
        hv0[nt*2+1] = oacc[nt][1]*inv0;
        hv1[nt*2]   = oacc[nt][2]*inv1;
        hv1[nt*2+1] = oacc[nt][3]*inv1;
    }

    // ---- fused GroupNorm over 128 head dims ----
    float s0 = 0.f, s1 = 0.f;
    #pragma unroll
    for (int i=0;i<16;i++){ s0 += hv0[i]; s1 += hv1[i]; }
    s0 += __shfl_xor_sync(0xffffffffu, s0, 1);
    s0 += __shfl_xor_sync(0xffffffffu, s0, 2);
    s1 += __shfl_xor_sync(0xffffffffu, s1, 1);
    s1 += __shfl_xor_sync(0xffffffffu, s1, 2);
    __syncthreads();
    if (lk == 0){ den2[wn*64 + r0] = s0; den2[wn*64 + r1] = s1; }
    __syncthreads();
    float mu0 = (den2[r0] + den2[64 + r0]) * (1.f/128.f);
    float mu1 = (den2[r1] + den2[64 + r1]) * (1.f/128.f);
    float q0 = 0.f, q1 = 0.f;
    #pragma unroll
    for (int i=0;i<16;i++){
        float d0 = hv0[i]-mu0; q0 += d0*d0;
        float d1 = hv1[i]-mu1; q1 += d1*d1;
    }
    q0 += __shfl_xor_sync(0xffffffffu, q0, 1);
    q0 += __shfl_xor_sync(0xffffffffu, q0, 2);
    q1 += __shfl_xor_sync(0xffffffffu, q1, 1);
    q1 += __shfl_xor_sync(0xffffffffu, q1, 2);
    __syncthreads();
    if (lk == 0){ den2[wn*64 + r0] = q0; den2[wn*64 + r1] = q1; }
    __syncthreads();
    float is0 = rsqrtf((den2[r0] + den2[64 + r0])*(1.f/128.f) + 1e-5f);
    float is1 = rsqrtf((den2[r1] + den2[64 + r1])*(1.f/128.f) + 1e-5f);

    // ---- gamma/beta + skip*xc + silu(z), bf16 store ----
    size_t tok0 = (size_t)(b*SEQ + t0 + r0), tok1 = (size_t)(b*SEQ + t0 + r1);
    #pragma unroll
    for (int nt=0; nt<8; nt++){
        int dc = wn*64 + nt*8 + (lk<<1);
        int c = hh*128 + dc;
        float2 gg = *(const float2*)&gng[c];
        float2 gb = *(const float2*)&gnb[c];
        float2 sk = *(const float2*)&skip[c];
        float2 x0 = *(const float2*)&xc[tok0*512 + c];
        float2 x1 = *(const float2*)&xc[tok1*512 + c];
        float2 z0 = *(const float2*)&up[tok0*1024 + 512 + c];
        float2 z1 = *(const float2*)&up[tok1*1024 + 512 + c];
        float y00 = (hv0[nt*2]  -mu0)*is0*gg.x + gb.x + sk.x*x0.x;
        float y01 = (hv0[nt*2+1]-mu0)*is0*gg.y + gb.y + sk.y*x0.y;
        float y10 = (hv1[nt*2]  -mu1)*is1*gg.x + gb.x + sk.x*x1.x;
        float y11 = (hv1[nt*2+1]-mu1)*is1*gg.y + gb.y + sk.y*x1.y;
        y00 *= z0.x / (1.f + expf(-z0.x));
        y01 *= z0.y / (1.f + expf(-z0.y));
        y10 *= z1.x / (1.f + expf(-z1.x));
        y11 *= z1.y / (1.f + expf(-z1.y));
        *(__nv_bfloat162*)&out[tok0*512 + c] = __floats2bfloat162_rn(y00, y01);
        *(__nv_bfloat162*)&out[tok1*512 + c] = __floats2bfloat162_rn(y10, y11);
    }
}

// ---------------- final ----------------
__global__ void final_kernel(const float* __restrict__ h, const float* __restrict__ g,
                             const float* __restrict__ b, const float* __restrict__ Wf,
                             const float* __restrict__ bf, float* __restrict__ out){
    __shared__ float sh[8];
    __shared__ float sv;
    int bb = blockIdx.x, tid = threadIdx.x;
    float vv = h[((size_t)(bb*SEQ + SEQ-1))*256 + tid];
    float s = warp_sum(vv);
    if (!(tid&31)) sh[tid>>5] = s;
    __syncthreads();
    if (tid==0){ float t=0; for(int i=0;i<8;i++) t+=sh[i]; sv = t*(1.f/256.f); }
    __syncthreads();
    float mu = sv;
    float d = vv - mu;
    float s2 = warp_sum(d*d);
    if (!(tid&31)) sh[tid>>5] = s2;
    __syncthreads();
    if (tid==0){ float t=0; for(int i=0;i<8;i++) t+=sh[i]; sv = t*(1.f/256.f); }
    __syncthreads();
    float yn = d*rsqrtf(sv + 1e-5f)*g[tid] + b[tid];
    float p = yn * Wf[tid];
    float s3 = warp_sum(p);
    __syncthreads();
    if (!(tid&31)) sh[tid>>5] = s3;
    __syncthreads();
    if (tid==0){ float t=0; for(int i=0;i<8;i++) t+=sh[i]; out[bb] = t + bf[0]; }
}

// ---------------- launch ----------------
extern "C" void kernel_launch(void* const* d_in, const int* in_sizes, int n_in,
                              void* d_out, int out_size){
    const float* x    = (const float*)d_in[0];
    const float* tf   = (const float*)d_in[1];
    const float* Wp   = (const float*)d_in[2];
    const float* bp   = (const float*)d_in[3];
    const float* ln_g = (const float*)d_in[4];
    const float* ln_b = (const float*)d_in[5];
    const float* Wup  = (const float*)d_in[6];
    const float* bup  = (const float*)d_in[7];
    const float* cw   = (const float*)d_in[8];
    const float* cb   = (const float*)d_in[9];
    const float* Wq   = (const float*)d_in[10];
    const float* Wk   = (const float*)d_in[11];
    const float* Wv   = (const float*)d_in[12];
    const float* Wif  = (const float*)d_in[13];
    const float* bif  = (const float*)d_in[14];
    const float* gng  = (const float*)d_in[15];
    const float* gnb  = (const float*)d_in[16];
    const float* skip = (const float*)d_in[17];
    const float* Wdn  = (const float*)d_in[18];
    const float* bdn  = (const float*)d_in[19];
    const float* lnfg = (const float*)d_in[20];
    const float* lnfb = (const float*)d_in[21];
    const float* Wf   = (const float*)d_in[22];
    const float* bf   = (const float*)d_in[23];

    float *h,*up,*xc,*giT,*gfT,*Fc,*a,*m,*wcol,*amaxT,*Wg;
    __nv_bfloat16 *hnbf,*xcbf,*upbf,*qbf,*kbf,*vbf,*att2bf,*wupbf,*wqbf,*wkbf,*wvbf,*wdnbf;
    cudaGetSymbolAddress((void**)&h,    g_h);
    cudaGetSymbolAddress((void**)&up,   g_up);
    cudaGetSymbolAddress((void**)&xc,   g_xc);
    cudaGetSymbolAddress((void**)&giT,  g_giT);
    cudaGetSymbolAddress((void**)&gfT,  g_gfT);
    cudaGetSymbolAddress((void**)&Fc,   g_Fc);
    cudaGetSymbolAddress((void**)&a,    g_a);
    cudaGetSymbolAddress((void**)&m,    g_m);
    cudaGetSymbolAddress((void**)&wcol, g_wcol);
    cudaGetSymbolAddress((void**)&amaxT,g_amaxT);
    cudaGetSymbolAddress((void**)&Wg,   g_Wg);
    cudaGetSymbolAddress((void**)&hnbf, g_hn_bf);
    cudaGetSymbolAddress((void**)&xcbf, g_xc_bf);
    cudaGetSymbolAddress((void**)&upbf, g_up_bf);
    cudaGetSymbolAddress((void**)&qbf,  g_q_bf);
    cudaGetSymbolAddress((void**)&kbf,  g_k_bf);
    cudaGetSymbolAddress((void**)&vbf,  g_v_bf);
    cudaGetSymbolAddress((void**)&att2bf, g_att2_bf);
    cudaGetSymbolAddress((void**)&wupbf, g_wup_bf);
    cudaGetSymbolAddress((void**)&wqbf,  g_wq_bf);
    cudaGetSymbolAddress((void**)&wkbf,  g_wk_bf);
    cudaGetSymbolAddress((void**)&wvbf,  g_wv_bf);
    cudaGetSymbolAddress((void**)&wdnbf, g_wdn_bf);

    int attn_smem = (64*QKW + 64*QKW + 64*VW + 64 + 64 + 64 + 128) * 4;
    static int attr_set = 0;
    if (!attr_set){
        cudaFuncSetAttribute(attn_bf16, cudaFuncAttributeMaxDynamicSharedMemorySize, attn_smem);
        attr_set = 1;
    }

    int n0 = NL*DMODEL*1024, n1 = NL*DI*DI, n4 = NL*DI*DMODEL;
    int ntot = n0 + 3*n1 + n4;
    f2bf5_kernel<<<(ntot/2 + 255)/256, 256>>>(Wup, wupbf, n0,
                                              Wq, wqbf, n1,
                                              Wk, wkbf, n1,
                                              Wv, wvbf, n1,
                                              Wdn, wdnbf, n4);
    gatew_kernel<<<NL*1024*8/256, 256>>>(Wq, Wk, Wv, Wif, Wg);

    embed_kernel<<<TOK*256/256, 256>>>(x, tf, Wp, bp, h);

    for (int l=0; l<NL; l++){
        ln_kernel<<<TOK/8, 256>>>(h, ln_g + l*256, ln_b + l*256, hnbf);
        gemm_bf16<<<dim3(1024/64, TOK/128, 1), 256>>>(hnbf, 256, wupbf + (size_t)l*256*1024, 1024,
                                                   up, 1024, bup + l*1024, nullptr, 256,
                                                   upbf, 512, nullptr, nullptr, nullptr, nullptr, nullptr);
        conv_gates_kernel<<<TOK, 256>>>(up, cw + l*4*512, cb + l*512,
                                        Wg + (size_t)l*8192, bif + l*8,
                                        xc, xcbf, giT, gfT);
        // merged Q (z=0), K (z=1), V (z=2) projections; bf16 outputs only
        gemm_bf16<<<dim3(512/64, TOK/128, 3), 256>>>(xcbf, 512, wqbf + (size_t)l*512*512, 512,
                                                  nullptr, 512, nullptr, nullptr, 512, qbf, 512,
                                                  upbf,
                                                  wkbf + (size_t)l*512*512, kbf,
                                                  wvbf + (size_t)l*512*512, vbf);
        scan_kernel4<<<32, 32>>>(giT, gfT, Fc, a, m, wcol, amaxT);
        attn_bf16<<<dim3(BATCH*NH, SEQ/64), 256, attn_smem>>>(qbf, kbf, vbf, Fc, a, m,
                                                  wcol, amaxT,
                                                  xc, up, gng + l*512, gnb + l*512, skip + l*512,
                                                  att2bf);
        gemm_bf16<<<dim3(256/64, TOK/128, 1), 256>>>(att2bf, 512, wdnbf + (size_t)l*512*256, 256,
                                                  h, 256, bdn + l*256, h, 512,
                                                  nullptr, 0, nullptr, nullptr, nullptr, nullptr, nullptr);
    }
    final_kernel<<<BATCH, 256>>>(h, lnfg, lnfb, Wf, bf, (float*)d_out);
}